// round 2
// baseline (speedup 1.0000x reference)
#include <cuda_runtime.h>
#include <cstdint>

// Problem constants
#define BB 4
#define SS 1024
#define DD 768
#define HH 12
#define DH 64
#define RR 129          // 2K+1, K=64
#define KWIN 64

#define NTHR 256
#define QT 32           // q rows per attention block

// ---------------- scratch (no allocation allowed) ----------------
__device__ float g_Qp[BB * SS * DD];
__device__ float g_Kp[BB * SS * DD];
__device__ float g_Vp[BB * SS * DD];
__device__ float g_Ctx[BB * SS * DD];

// ---------------- SGEMM: C[M,N] = A[M,K] @ W[N,K]^T + bias[N] ----------------
#define BM 64
#define BN 64
#define BKK 16

__global__ __launch_bounds__(256) void sgemm_nt_bias(
    const float* __restrict__ A, const float* __restrict__ W,
    const float* __restrict__ bias, float* __restrict__ C,
    int M, int N, int Kd)
{
    __shared__ float As[BKK][BM + 4];
    __shared__ float Ws[BKK][BN + 4];

    const int tid = threadIdx.x;
    const int bm = blockIdx.y * BM;
    const int bn = blockIdx.x * BN;
    const int tx = tid & 15;        // n micro
    const int ty = tid >> 4;        // m micro
    const int lr = tid >> 2;        // loader row 0..63
    const int lc = (tid & 3) * 4;   // loader k 0,4,8,12

    float acc[4][4] = {};

    for (int k0 = 0; k0 < Kd; k0 += BKK) {
        float4 a4 = *(const float4*)&A[(size_t)(bm + lr) * Kd + k0 + lc];
        float4 w4 = *(const float4*)&W[(size_t)(bn + lr) * Kd + k0 + lc];
        As[lc + 0][lr] = a4.x; As[lc + 1][lr] = a4.y;
        As[lc + 2][lr] = a4.z; As[lc + 3][lr] = a4.w;
        Ws[lc + 0][lr] = w4.x; Ws[lc + 1][lr] = w4.y;
        Ws[lc + 2][lr] = w4.z; Ws[lc + 3][lr] = w4.w;
        __syncthreads();

        #pragma unroll
        for (int k = 0; k < BKK; k++) {
            float ar[4], wr[4];
            #pragma unroll
            for (int i = 0; i < 4; i++) ar[i] = As[k][ty * 4 + i];
            #pragma unroll
            for (int j = 0; j < 4; j++) wr[j] = Ws[k][tx * 4 + j];
            #pragma unroll
            for (int i = 0; i < 4; i++)
                #pragma unroll
                for (int j = 0; j < 4; j++)
                    acc[i][j] += ar[i] * wr[j];
        }
        __syncthreads();
    }

    #pragma unroll
    for (int i = 0; i < 4; i++) {
        int m = bm + ty * 4 + i;
        #pragma unroll
        for (int j = 0; j < 4; j++) {
            int n = bn + tx * 4 + j;
            C[(size_t)m * N + n] = acc[i][j] + bias[n];
        }
    }
}

// ---------------- fused relative attention ----------------
// smem layout (floats):
//   sQ     : QT  x 65      (2080)
//   sK     : 64  x 65      (4160)   -- K tiles, then V tiles
//   sE     : 129 x 65      (8385)   -- embK slice, then embV slice
//   sW     : QT  x 132     (4224)   -- rel scores, then w buckets
//   sScore : QT  x 1032    (33024)
#define SM_FLOATS (QT*65 + 64*65 + RR*65 + QT*132 + QT*1032)
#define SM_BYTES  (SM_FLOATS * 4)

__global__ __launch_bounds__(NTHR) void attn_kernel(
    const float* __restrict__ Qp, const float* __restrict__ Kp,
    const float* __restrict__ Vp, const float* __restrict__ embK,
    const float* __restrict__ embV, float* __restrict__ attn_out,
    float* __restrict__ ctx)
{
    extern __shared__ float sm[];
    float* sQ     = sm;
    float* sK     = sQ + QT * 65;
    float* sE     = sK + 64 * 65;
    float* sW     = sE + RR * 65;
    float* sScore = sW + QT * 132;

    const int tid = threadIdx.x;
    const int nq = SS / QT;                 // 32
    const int bidx = blockIdx.x;
    const int qt = bidx % nq;
    const int h  = (bidx / nq) % HH;
    const int b  = bidx / (nq * HH);
    const int q0 = qt * QT;

    // --- load Q tile and embK head-slice ---
    for (int i = tid; i < QT * DH; i += NTHR) {
        int q = i >> 6, d = i & 63;
        sQ[q * 65 + d] = Qp[((size_t)(b * SS) + q0 + q) * DD + h * DH + d];
    }
    for (int i = tid; i < RR * DH; i += NTHR) {
        int r = i >> 6, d = i & 63;
        sE[r * 65 + d] = embK[(size_t)r * DD + h * DH + d];
    }
    __syncthreads();

    // --- rel scores: sW[q][r] = dot(Q[q], embK_h[r]) ---
    for (int i = tid; i < QT * RR; i += NTHR) {
        int q = i / RR, r = i - q * RR;
        float acc = 0.f;
        #pragma unroll 8
        for (int d = 0; d < DH; d++) acc += sQ[q * 65 + d] * sE[r * 65 + d];
        sW[q * 132 + r] = acc;
    }

    // --- scores: qk + rel, scaled ---
    const float scale = 0.125f;          // 1/sqrt(64)
    {
        const int ty = tid >> 5;         // q group (4 rows each)
        const int tx = tid & 31;         // k pair
        for (int kt = 0; kt < SS / 64; kt++) {
            int k0 = kt * 64;
            __syncthreads();
            for (int i = tid; i < 64 * DH; i += NTHR) {
                int k = i >> 6, d = i & 63;
                sK[k * 65 + d] = Kp[((size_t)(b * SS) + k0 + k) * DD + h * DH + d];
            }
            __syncthreads();

            float acc[4][2] = {};
            #pragma unroll 4
            for (int d = 0; d < DH; d++) {
                float kv0 = sK[(tx * 2)     * 65 + d];
                float kv1 = sK[(tx * 2 + 1) * 65 + d];
                #pragma unroll
                for (int j = 0; j < 4; j++) {
                    float qv = sQ[(ty * 4 + j) * 65 + d];
                    acc[j][0] += qv * kv0;
                    acc[j][1] += qv * kv1;
                }
            }
            #pragma unroll
            for (int j = 0; j < 4; j++) {
                int q = ty * 4 + j;
                #pragma unroll
                for (int jj = 0; jj < 2; jj++) {
                    int gk = k0 + tx * 2 + jj;
                    int rel = gk - (q0 + q);
                    rel = min(max(rel, -KWIN), KWIN) + KWIN;
                    sScore[q * 1032 + gk] = (acc[j][jj] + sW[q * 132 + rel]) * scale;
                }
            }
        }
    }
    __syncthreads();

    // --- softmax: 8 threads per q-row ---
    const int qrow = tid >> 3;
    const int s8   = tid & 7;
    {
        float* row = sScore + qrow * 1032;
        float m = -1e30f;
        for (int k = s8; k < SS; k += 8) m = fmaxf(m, row[k]);
        #pragma unroll
        for (int off = 1; off < 8; off <<= 1)
            m = fmaxf(m, __shfl_xor_sync(0xffffffffu, m, off));
        float sum = 0.f;
        for (int k = s8; k < SS; k += 8) {
            float e = __expf(row[k] - m);
            row[k] = e;
            sum += e;
        }
        #pragma unroll
        for (int off = 1; off < 8; off <<= 1)
            sum += __shfl_xor_sync(0xffffffffu, sum, off);
        float inv = 1.f / sum;
        for (int k = s8; k < SS; k += 8) row[k] *= inv;
    }
    __syncthreads();

    // --- write attn (coalesced) ---
    {
        float* aout = attn_out + ((size_t)(b * HH + h) * SS + q0) * SS;
        for (int i = tid; i < QT * SS; i += NTHR) {
            int qq = i >> 10, kk = i & 1023;
            aout[(size_t)qq * SS + kk] = sScore[qq * 1032 + kk];
        }
    }

    // --- w buckets: sW[q][r] ---
    {
        const int qg = q0 + qrow;
        for (int r = 1 + s8; r <= 127; r += 8) {
            int k = qg - KWIN + r;
            sW[qrow * 132 + r] = (k >= 0 && k < SS) ? sScore[qrow * 1032 + k] : 0.f;
        }
        float s0 = 0.f, s1 = 0.f;
        for (int k = s8; k < SS; k += 8) {
            float v = sScore[qrow * 1032 + k];
            if (k <= qg - KWIN) s0 += v;
            else if (k >= qg + KWIN) s1 += v;
        }
        #pragma unroll
        for (int off = 1; off < 8; off <<= 1) {
            s0 += __shfl_xor_sync(0xffffffffu, s0, off);
            s1 += __shfl_xor_sync(0xffffffffu, s1, off);
        }
        if (s8 == 0) {
            sW[qrow * 132 + 0]   = s0;
            sW[qrow * 132 + 128] = s1;
        }
    }
    // --- load embV head-slice (reuse sE) ---
    for (int i = tid; i < RR * DH; i += NTHR) {
        int r = i >> 6, d = i & 63;
        sE[r * 65 + d] = embV[(size_t)r * DD + h * DH + d];
    }
    __syncthreads();

    // --- out = attn @ V + w @ embV_h ---
    {
        const int ty = tid >> 5;         // q group
        const int tx = tid & 31;         // d pair
        float oacc[4][2] = {};
        for (int kt = 0; kt < SS / 64; kt++) {
            int k0 = kt * 64;
            __syncthreads();
            for (int i = tid; i < 64 * DH; i += NTHR) {
                int k = i >> 6, d = i & 63;
                sK[k * 65 + d] = Vp[((size_t)(b * SS) + k0 + k) * DD + h * DH + d];
            }
            __syncthreads();
            #pragma unroll 4
            for (int kk = 0; kk < 64; kk++) {
                float v0 = sK[kk * 65 + tx * 2];
                float v1 = sK[kk * 65 + tx * 2 + 1];
                #pragma unroll
                for (int j = 0; j < 4; j++) {
                    float a = sScore[(ty * 4 + j) * 1032 + k0 + kk];
                    oacc[j][0] += a * v0;
                    oacc[j][1] += a * v1;
                }
            }
        }
        #pragma unroll 4
        for (int r = 0; r < RR; r++) {
            float e0 = sE[r * 65 + tx * 2];
            float e1 = sE[r * 65 + tx * 2 + 1];
            #pragma unroll
            for (int j = 0; j < 4; j++) {
                float w = sW[(ty * 4 + j) * 132 + r];
                oacc[j][0] += w * e0;
                oacc[j][1] += w * e1;
            }
        }
        #pragma unroll
        for (int j = 0; j < 4; j++) {
            int qq = ty * 4 + j;
            float* dst = ctx + ((size_t)(b * SS) + q0 + qq) * DD + h * DH;
            dst[tx * 2]     = oacc[j][0];
            dst[tx * 2 + 1] = oacc[j][1];
        }
    }
}

// ---------------- launch ----------------
extern "C" void kernel_launch(void* const* d_in, const int* in_sizes, int n_in,
                              void* d_out, int out_size)
{
    const float* query = (const float*)d_in[0];
    const float* key   = (const float*)d_in[1];
    const float* value = (const float*)d_in[2];
    const float* WQ_w  = (const float*)d_in[3];
    const float* WQ_b  = (const float*)d_in[4];
    const float* WK_w  = (const float*)d_in[5];
    const float* WK_b  = (const float*)d_in[6];
    const float* WV_w  = (const float*)d_in[7];
    const float* WV_b  = (const float*)d_in[8];
    const float* WO_w  = (const float*)d_in[9];
    const float* WO_b  = (const float*)d_in[10];
    const float* embK  = (const float*)d_in[11];
    const float* embV  = (const float*)d_in[12];

    float* out = (float*)d_out;                       // [B,S,D]
    float* attn = out + (size_t)BB * SS * DD;         // [B,H,S,S]

    static float *Qp = nullptr, *Kp = nullptr, *Vp = nullptr, *Ctx = nullptr;
    if (!Qp) {
        cudaGetSymbolAddress((void**)&Qp, g_Qp);
        cudaGetSymbolAddress((void**)&Kp, g_Kp);
        cudaGetSymbolAddress((void**)&Vp, g_Vp);
        cudaGetSymbolAddress((void**)&Ctx, g_Ctx);
        cudaFuncSetAttribute(attn_kernel,
                             cudaFuncAttributeMaxDynamicSharedMemorySize, SM_BYTES);
    }

    const int M = BB * SS;   // 4096
    dim3 gproj(DD / BN, M / BM);   // (12, 64)

    sgemm_nt_bias<<<gproj, 256>>>(query, WQ_w, WQ_b, Qp, M, DD, DD);
    sgemm_nt_bias<<<gproj, 256>>>(key,   WK_w, WK_b, Kp, M, DD, DD);
    sgemm_nt_bias<<<gproj, 256>>>(value, WV_w, WV_b, Vp, M, DD, DD);

    attn_kernel<<<BB * HH * (SS / QT), NTHR, SM_BYTES>>>(
        Qp, Kp, Vp, embK, embV, attn, Ctx);

    sgemm_nt_bias<<<gproj, 256>>>(Ctx, WO_w, WO_b, out, M, DD, DD);
}

// round 3
// speedup vs baseline: 1.3181x; 1.3181x over previous
#include <cuda_runtime.h>
#include <cstdint>

// Problem constants
#define BB 4
#define SS 1024
#define DD 768
#define HH 12
#define DH 64
#define RR 129          // 2K+1, K=64
#define KWIN 64

#define NTHR 512
#define QT 32           // q rows per attention block
#define KT 256          // k rows per score/PV tile

// ---------------- scratch (no allocation allowed) ----------------
__device__ float g_Qp[BB * SS * DD];
__device__ float g_Kp[BB * SS * DD];
__device__ float g_Vp[BB * SS * DD];
__device__ float g_Ctx[BB * SS * DD];

// ---------------- SGEMM: C[M,N] = A[M,K] @ W[N,K]^T + bias[N] ----------------
#define BM 64
#define BN 64
#define BKK 16

__global__ __launch_bounds__(256) void sgemm_nt_bias(
    const float* __restrict__ A, const float* __restrict__ W,
    const float* __restrict__ bias, float* __restrict__ C,
    int M, int N, int Kd)
{
    __shared__ float As[BKK][BM + 4];
    __shared__ float Ws[BKK][BN + 4];

    const int tid = threadIdx.x;
    const int bm = blockIdx.y * BM;
    const int bn = blockIdx.x * BN;
    const int tx = tid & 15;        // n micro
    const int ty = tid >> 4;        // m micro
    const int lr = tid >> 2;        // loader row 0..63
    const int lc = (tid & 3) * 4;   // loader k 0,4,8,12

    float acc[4][4] = {};

    for (int k0 = 0; k0 < Kd; k0 += BKK) {
        float4 a4 = *(const float4*)&A[(size_t)(bm + lr) * Kd + k0 + lc];
        float4 w4 = *(const float4*)&W[(size_t)(bn + lr) * Kd + k0 + lc];
        As[lc + 0][lr] = a4.x; As[lc + 1][lr] = a4.y;
        As[lc + 2][lr] = a4.z; As[lc + 3][lr] = a4.w;
        Ws[lc + 0][lr] = w4.x; Ws[lc + 1][lr] = w4.y;
        Ws[lc + 2][lr] = w4.z; Ws[lc + 3][lr] = w4.w;
        __syncthreads();

        #pragma unroll
        for (int k = 0; k < BKK; k++) {
            float ar[4], wr[4];
            #pragma unroll
            for (int i = 0; i < 4; i++) ar[i] = As[k][ty * 4 + i];
            #pragma unroll
            for (int j = 0; j < 4; j++) wr[j] = Ws[k][tx * 4 + j];
            #pragma unroll
            for (int i = 0; i < 4; i++)
                #pragma unroll
                for (int j = 0; j < 4; j++)
                    acc[i][j] += ar[i] * wr[j];
        }
        __syncthreads();
    }

    #pragma unroll
    for (int i = 0; i < 4; i++) {
        int m = bm + ty * 4 + i;
        #pragma unroll
        for (int j = 0; j < 4; j++) {
            int n = bn + tx * 4 + j;
            C[(size_t)m * N + n] = acc[i][j] + bias[n];
        }
    }
}

// ---------------- fused relative attention (512 threads) ----------------
// smem layout (floats):
//   sQ     : 32  x 65      [0      .. 2080)
//   sK     : 256 x 65      [2080   .. 18720)   -- K tiles / V tiles
//   sW     : 32  x 132     [18720  .. 22944)   -- rel table, then w buckets
//   sScore : 32  x 1040    [22944  .. 56224)
// aliases:
//   sE  (embK, 129x65=8385)  = sScore   (used before sScore is written)
//   sEv (embV, 8385)         = sK+6656  (used after V tiles consumed)
//   staging (6144)           = sK[0..6144)
#define SM_FLOATS 56224
#define SM_BYTES  (SM_FLOATS * 4)
#define SSTR 1040

__global__ __launch_bounds__(NTHR) void attn_kernel(
    const float* __restrict__ Qp, const float* __restrict__ Kp,
    const float* __restrict__ Vp, const float* __restrict__ embK,
    const float* __restrict__ embV, float* __restrict__ attn_out,
    float* __restrict__ ctx)
{
    extern __shared__ float sm[];
    float* sQ     = sm;
    float* sK     = sm + 2080;
    float* sW     = sm + 18720;
    float* sScore = sm + 22944;
    float* sE     = sScore;         // embK alias
    float* sEv    = sK + 6656;      // embV alias

    const int tid = threadIdx.x;
    const int nq = SS / QT;                 // 32
    const int bidx = blockIdx.x;
    const int qt = bidx % nq;
    const int h  = (bidx / nq) % HH;
    const int b  = bidx / (nq * HH);
    const int q0 = qt * QT;

    // --- load Q tile and embK head-slice ---
    for (int i = tid; i < QT * DH; i += NTHR) {
        int q = i >> 6, d = i & 63;
        sQ[q * 65 + d] = Qp[((size_t)(b * SS) + q0 + q) * DD + h * DH + d];
    }
    for (int i = tid; i < RR * DH; i += NTHR) {
        int r = i >> 6, d = i & 63;
        sE[r * 65 + d] = embK[(size_t)r * DD + h * DH + d];
    }
    __syncthreads();

    // --- rel table: sW[q][r] = dot(Q[q], embK_h[r]) ---
    for (int i = tid; i < QT * RR; i += NTHR) {
        int q = i / RR, r = i - q * RR;
        float acc = 0.f;
        #pragma unroll 8
        for (int d = 0; d < DH; d++) acc += sQ[q * 65 + d] * sE[r * 65 + d];
        sW[q * 132 + r] = acc;
    }
    __syncthreads();   // sW done; sE region may now be overwritten (sScore)

    // --- scores: qk + rel, scaled ---
    const float scale = 0.125f;          // 1/sqrt(64)
    {
        const int ty = tid >> 6;         // q group: 0..7 (4 q each)
        const int tx = tid & 63;         // k lane: k = k0 + tx + 64*j
        for (int kt = 0; kt < SS / KT; kt++) {
            int k0 = kt * KT;
            for (int i = tid; i < KT * DH; i += NTHR) {
                int k = i >> 6, d = i & 63;
                sK[k * 65 + d] = Kp[((size_t)(b * SS) + k0 + k) * DD + h * DH + d];
            }
            __syncthreads();

            float acc[4][4] = {};
            #pragma unroll 4
            for (int d = 0; d < DH; d++) {
                float qv[4], kv[4];
                #pragma unroll
                for (int i = 0; i < 4; i++) qv[i] = sQ[(ty * 4 + i) * 65 + d];
                #pragma unroll
                for (int j = 0; j < 4; j++) kv[j] = sK[(tx + 64 * j) * 65 + d];
                #pragma unroll
                for (int i = 0; i < 4; i++)
                    #pragma unroll
                    for (int j = 0; j < 4; j++)
                        acc[i][j] += qv[i] * kv[j];
            }
            #pragma unroll
            for (int i = 0; i < 4; i++) {
                int q = ty * 4 + i;
                int qg = q0 + q;
                #pragma unroll
                for (int j = 0; j < 4; j++) {
                    int gk = k0 + tx + 64 * j;
                    int rel = min(max(gk - qg, -KWIN), KWIN) + KWIN;
                    sScore[q * SSTR + gk] = (acc[i][j] + sW[q * 132 + rel]) * scale;
                }
            }
            __syncthreads();
        }
    }

    // --- softmax: 16 threads per q-row ---
    const int qrow = tid >> 4;
    const int s16  = tid & 15;
    {
        float* row = sScore + qrow * SSTR;
        float m = -1e30f;
        for (int k = s16; k < SS; k += 16) m = fmaxf(m, row[k]);
        #pragma unroll
        for (int off = 1; off < 16; off <<= 1)
            m = fmaxf(m, __shfl_xor_sync(0xffffffffu, m, off, 16));
        float sum = 0.f;
        for (int k = s16; k < SS; k += 16) {
            float e = __expf(row[k] - m);
            row[k] = e;
            sum += e;
        }
        #pragma unroll
        for (int off = 1; off < 16; off <<= 1)
            sum += __shfl_xor_sync(0xffffffffu, sum, off, 16);
        float inv = 1.f / sum;
        for (int k = s16; k < SS; k += 16) row[k] *= inv;
    }
    __syncthreads();

    // --- write attn (coalesced) ---
    {
        float* aout = attn_out + ((size_t)(b * HH + h) * SS + q0) * SS;
        for (int i = tid; i < QT * SS; i += NTHR) {
            int qq = i >> 10, kk = i & 1023;
            aout[(size_t)qq * SS + kk] = sScore[qq * SSTR + kk];
        }
    }

    // --- w buckets: sW[q][r] ---
    {
        const int qg = q0 + qrow;
        for (int r = 1 + s16; r <= 127; r += 16) {
            int k = qg - KWIN + r;
            sW[qrow * 132 + r] = (k >= 0 && k < SS) ? sScore[qrow * SSTR + k] : 0.f;
        }
        float s0 = 0.f, s1 = 0.f;
        for (int k = s16; k < SS; k += 16) {
            float v = sScore[qrow * SSTR + k];
            if (k <= qg - KWIN) s0 += v;
            else if (k >= qg + KWIN) s1 += v;
        }
        #pragma unroll
        for (int off = 1; off < 16; off <<= 1) {
            s0 += __shfl_xor_sync(0xffffffffu, s0, off, 16);
            s1 += __shfl_xor_sync(0xffffffffu, s1, off, 16);
        }
        if (s16 == 0) {
            sW[qrow * 132 + 0]   = s0;
            sW[qrow * 132 + 128] = s1;
        }
    }
    __syncthreads();

    // --- out = attn @ V + w @ embV_h ---
    {
        const int t127 = tid & 127;
        const int kq   = tid >> 7;       // k-quarter 0..3
        const int pty  = t127 >> 4;      // q group 0..7 (4 q each)
        const int ptx  = t127 & 15;      // d lane: d = ptx + 16*j

        float oacc[4][4] = {};
        for (int vt = 0; vt < SS / KT; vt++) {
            int k0 = vt * KT;
            for (int i = tid; i < KT * DH; i += NTHR) {
                int k = i >> 6, d = i & 63;
                sK[k * 65 + d] = Vp[((size_t)(b * SS) + k0 + k) * DD + h * DH + d];
            }
            __syncthreads();
            const int kb = kq * 64;
            #pragma unroll 2
            for (int kk = kb; kk < kb + 64; kk++) {
                float vv[4];
                #pragma unroll
                for (int j = 0; j < 4; j++) vv[j] = sK[kk * 65 + ptx + 16 * j];
                #pragma unroll
                for (int i = 0; i < 4; i++) {
                    float a = sScore[(pty * 4 + i) * SSTR + k0 + kk];
                    #pragma unroll
                    for (int j = 0; j < 4; j++) oacc[i][j] += a * vv[j];
                }
            }
            __syncthreads();
        }

        // load embV (into sK+6656, V tiles no longer needed)
        for (int i = tid; i < RR * DH; i += NTHR) {
            int r = i >> 6, d = i & 63;
            sEv[r * 65 + d] = embV[(size_t)r * DD + h * DH + d];
        }
        __syncthreads();

        // rel-V term: group kq handles its r-slice (folded into same reduction)
        {
            int r0 = kq * 32;
            int r1 = (kq == 3) ? RR : (r0 + 32);
            for (int r = r0; r < r1; r++) {
                float ev[4];
                #pragma unroll
                for (int j = 0; j < 4; j++) ev[j] = sEv[r * 65 + ptx + 16 * j];
                #pragma unroll
                for (int i = 0; i < 4; i++) {
                    float w = sW[(pty * 4 + i) * 132 + r];
                    #pragma unroll
                    for (int j = 0; j < 4; j++) oacc[i][j] += w * ev[j];
                }
            }
        }

        // stage partials from groups 1..3 into sK[0..6144), group 0 reduces
        if (kq > 0) {
            #pragma unroll
            for (int i = 0; i < 4; i++)
                #pragma unroll
                for (int j = 0; j < 4; j++)
                    sK[(i * 4 + j) * 384 + (kq - 1) * 128 + t127] = oacc[i][j];
        }
        __syncthreads();
        if (kq == 0) {
            #pragma unroll
            for (int i = 0; i < 4; i++) {
                int qq = pty * 4 + i;
                float* dst = ctx + ((size_t)(b * SS) + q0 + qq) * DD + h * DH;
                #pragma unroll
                for (int j = 0; j < 4; j++) {
                    int e = i * 4 + j;
                    float v = oacc[i][j]
                            + sK[e * 384 + 0 * 128 + t127]
                            + sK[e * 384 + 1 * 128 + t127]
                            + sK[e * 384 + 2 * 128 + t127];
                    dst[ptx + 16 * j] = v;
                }
            }
        }
    }
}

// ---------------- launch ----------------
extern "C" void kernel_launch(void* const* d_in, const int* in_sizes, int n_in,
                              void* d_out, int out_size)
{
    const float* query = (const float*)d_in[0];
    const float* key   = (const float*)d_in[1];
    const float* value = (const float*)d_in[2];
    const float* WQ_w  = (const float*)d_in[3];
    const float* WQ_b  = (const float*)d_in[4];
    const float* WK_w  = (const float*)d_in[5];
    const float* WK_b  = (const float*)d_in[6];
    const float* WV_w  = (const float*)d_in[7];
    const float* WV_b  = (const float*)d_in[8];
    const float* WO_w  = (const float*)d_in[9];
    const float* WO_b  = (const float*)d_in[10];
    const float* embK  = (const float*)d_in[11];
    const float* embV  = (const float*)d_in[12];

    float* out = (float*)d_out;                       // [B,S,D]
    float* attn = out + (size_t)BB * SS * DD;         // [B,H,S,S]

    static float *Qp = nullptr, *Kp = nullptr, *Vp = nullptr, *Ctx = nullptr;
    if (!Qp) {
        cudaGetSymbolAddress((void**)&Qp, g_Qp);
        cudaGetSymbolAddress((void**)&Kp, g_Kp);
        cudaGetSymbolAddress((void**)&Vp, g_Vp);
        cudaGetSymbolAddress((void**)&Ctx, g_Ctx);
        cudaFuncSetAttribute(attn_kernel,
                             cudaFuncAttributeMaxDynamicSharedMemorySize, SM_BYTES);
    }

    const int M = BB * SS;   // 4096
    dim3 gproj(DD / BN, M / BM);   // (12, 64)

    sgemm_nt_bias<<<gproj, 256>>>(query, WQ_w, WQ_b, Qp, M, DD, DD);
    sgemm_nt_bias<<<gproj, 256>>>(key,   WK_w, WK_b, Kp, M, DD, DD);
    sgemm_nt_bias<<<gproj, 256>>>(value, WV_w, WV_b, Vp, M, DD, DD);

    attn_kernel<<<BB * HH * (SS / QT), NTHR, SM_BYTES>>>(
        Qp, Kp, Vp, embK, embV, attn, Ctx);

    sgemm_nt_bias<<<gproj, 256>>>(Ctx, WO_w, WO_b, out, M, DD, DD);
}

// round 5
// speedup vs baseline: 1.6444x; 1.2476x over previous
#include <cuda_runtime.h>
#include <cuda_bf16.h>
#include <cstdint>

// Problem constants
#define BB 4
#define SS 1024
#define DD 768
#define HH 12
#define DH 64
#define RR 129          // 2K+1, K=64
#define KWIN 64

#define NTHR 512
#define QT 32           // q rows per attention block
#define KT 256          // k rows per score/PV tile

#define MTOT (BB * SS)  // 4096

// ---------------- scratch (no allocation allowed) ----------------
__device__ float g_Qp[MTOT * DD];
__device__ float g_Kp[MTOT * DD];
__device__ float g_Vp[MTOT * DD];
__device__ float g_Ctx[MTOT * DD];

// bf16 hi/lo split scratch
__device__ __nv_bfloat16 g_qh[MTOT * DD],  g_ql[MTOT * DD];
__device__ __nv_bfloat16 g_kh[MTOT * DD],  g_kl[MTOT * DD];
__device__ __nv_bfloat16 g_vh[MTOT * DD],  g_vl[MTOT * DD];
__device__ __nv_bfloat16 g_ch[MTOT * DD],  g_cl[MTOT * DD];
__device__ __nv_bfloat16 g_wqh[DD * DD], g_wql[DD * DD];
__device__ __nv_bfloat16 g_wkh[DD * DD], g_wkl[DD * DD];
__device__ __nv_bfloat16 g_wvh[DD * DD], g_wvl[DD * DD];
__device__ __nv_bfloat16 g_woh[DD * DD], g_wol[DD * DD];

// ---------------- fp32 -> bf16 hi/lo split ----------------
__global__ __launch_bounds__(256) void split_kernel(
    const float* __restrict__ x, __nv_bfloat16* __restrict__ hi,
    __nv_bfloat16* __restrict__ lo, int n)
{
    int i = (blockIdx.x * 256 + threadIdx.x) * 4;
    if (i >= n) return;
    float4 v = *(const float4*)&x[i];
    float vv[4] = {v.x, v.y, v.z, v.w};
    uint16_t h[4], l[4];
    #pragma unroll
    for (int p = 0; p < 4; p++) {
        __nv_bfloat16 hb = __float2bfloat16(vv[p]);
        __nv_bfloat16 lb = __float2bfloat16(vv[p] - __bfloat162float(hb));
        h[p] = __bfloat16_as_ushort(hb);
        l[p] = __bfloat16_as_ushort(lb);
    }
    uint2 hp = make_uint2(((uint32_t)h[1] << 16) | h[0], ((uint32_t)h[3] << 16) | h[2]);
    uint2 lp = make_uint2(((uint32_t)l[1] << 16) | l[0], ((uint32_t)l[3] << 16) | l[2]);
    *(uint2*)&hi[i] = hp;
    *(uint2*)&lo[i] = lp;
}

// ---------------- mma.sync bf16-split GEMM ----------------
// C[M,N] = A @ W^T + bias.  A,W pre-split into bf16 hi/lo, k-contiguous.
__device__ __forceinline__ void mma16816(float* d, const uint32_t* a, const uint32_t* b) {
    asm volatile("mma.sync.aligned.m16n8k16.row.col.f32.bf16.bf16.f32 "
        "{%0,%1,%2,%3}, {%4,%5,%6,%7}, {%8,%9}, {%0,%1,%2,%3};"
        : "+f"(d[0]), "+f"(d[1]), "+f"(d[2]), "+f"(d[3])
        : "r"(a[0]), "r"(a[1]), "r"(a[2]), "r"(a[3]), "r"(b[0]), "r"(b[1]));
}

#define SP 40   // smem row pitch (bf16 elems): conflict-free for frag loads

__global__ __launch_bounds__(256) void gemm_mma_bias(
    const __nv_bfloat16* __restrict__ Ah, const __nv_bfloat16* __restrict__ Al,
    const __nv_bfloat16* __restrict__ Wh, const __nv_bfloat16* __restrict__ Wl,
    const float* __restrict__ bias, float* __restrict__ C,
    int M, int N, int Kd)
{
    __shared__ __nv_bfloat16 sAh[128 * SP], sAl[128 * SP];
    __shared__ __nv_bfloat16 sWh[128 * SP], sWl[128 * SP];

    const int tid = threadIdx.x;
    const int bm = blockIdx.y * 128, bn = blockIdx.x * 128;
    const int warp = tid >> 5, lane = tid & 31;
    const int wm = warp & 1, wn = warp >> 1;      // 2 x 4 warp grid
    const int g = lane >> 2, t = lane & 3;

    float d[4][4][4] = {};

    const int nch = Kd / 32;
    for (int c = 0; c < nch; c++) {
        const int k0 = c * 32;
        __syncthreads();
        #pragma unroll
        for (int it = 0; it < 2; it++) {
            int i = tid + it * 256;
            int row = i >> 2, cc = (i & 3) * 8;
            size_t ga = (size_t)(bm + row) * Kd + k0 + cc;
            size_t gw = (size_t)(bn + row) * Kd + k0 + cc;
            *(uint4*)&sAh[row * SP + cc] = *(const uint4*)&Ah[ga];
            *(uint4*)&sAl[row * SP + cc] = *(const uint4*)&Al[ga];
            *(uint4*)&sWh[row * SP + cc] = *(const uint4*)&Wh[gw];
            *(uint4*)&sWl[row * SP + cc] = *(const uint4*)&Wl[gw];
        }
        __syncthreads();

        #pragma unroll
        for (int ks = 0; ks < 2; ks++) {
            const int kk = ks * 16 + 2 * t;
            uint32_t bh[4][2], bl[4][2];
            #pragma unroll
            for (int ni = 0; ni < 4; ni++) {
                int rb = (wn * 32 + ni * 8 + g) * SP;
                bh[ni][0] = *(const uint32_t*)&sWh[rb + kk];
                bh[ni][1] = *(const uint32_t*)&sWh[rb + kk + 8];
                bl[ni][0] = *(const uint32_t*)&sWl[rb + kk];
                bl[ni][1] = *(const uint32_t*)&sWl[rb + kk + 8];
            }
            #pragma unroll
            for (int mi = 0; mi < 4; mi++) {
                int r0 = (wm * 64 + mi * 16 + g) * SP;
                int r1 = (wm * 64 + mi * 16 + 8 + g) * SP;
                uint32_t ah[4], al[4];
                ah[0] = *(const uint32_t*)&sAh[r0 + kk];
                ah[1] = *(const uint32_t*)&sAh[r1 + kk];
                ah[2] = *(const uint32_t*)&sAh[r0 + kk + 8];
                ah[3] = *(const uint32_t*)&sAh[r1 + kk + 8];
                al[0] = *(const uint32_t*)&sAl[r0 + kk];
                al[1] = *(const uint32_t*)&sAl[r1 + kk];
                al[2] = *(const uint32_t*)&sAl[r0 + kk + 8];
                al[3] = *(const uint32_t*)&sAl[r1 + kk + 8];
                #pragma unroll
                for (int ni = 0; ni < 4; ni++) {
                    mma16816(d[mi][ni], ah, bh[ni]);
                    mma16816(d[mi][ni], ah, bl[ni]);
                    mma16816(d[mi][ni], al, bh[ni]);
                }
            }
        }
    }

    #pragma unroll
    for (int mi = 0; mi < 4; mi++) {
        int r0 = bm + wm * 64 + mi * 16 + g;
        #pragma unroll
        for (int ni = 0; ni < 4; ni++) {
            int c0 = bn + wn * 32 + ni * 8 + 2 * t;
            float b0 = bias[c0], b1 = bias[c0 + 1];
            C[(size_t)r0 * N + c0]           = d[mi][ni][0] + b0;
            C[(size_t)r0 * N + c0 + 1]       = d[mi][ni][1] + b1;
            C[(size_t)(r0 + 8) * N + c0]     = d[mi][ni][2] + b0;
            C[(size_t)(r0 + 8) * N + c0 + 1] = d[mi][ni][3] + b1;
        }
    }
}

// ---------------- fused relative attention (512 threads) ----------------
#define SM_FLOATS 56224
#define SM_BYTES  (SM_FLOATS * 4)
#define SSTR 1040

__global__ __launch_bounds__(NTHR) void attn_kernel(
    const float* __restrict__ Qp, const float* __restrict__ Kp,
    const float* __restrict__ Vp, const float* __restrict__ embK,
    const float* __restrict__ embV, float* __restrict__ attn_out,
    float* __restrict__ ctx)
{
    extern __shared__ float sm[];
    float* sQ     = sm;
    float* sK     = sm + 2080;
    float* sW     = sm + 18720;
    float* sScore = sm + 22944;
    float* sE     = sScore;         // embK alias
    float* sEv    = sK + 6656;      // embV alias

    const int tid = threadIdx.x;
    const int nq = SS / QT;
    const int bidx = blockIdx.x;
    const int qt = bidx % nq;
    const int h  = (bidx / nq) % HH;
    const int b  = bidx / (nq * HH);
    const int q0 = qt * QT;

    for (int i = tid; i < QT * DH; i += NTHR) {
        int q = i >> 6, d = i & 63;
        sQ[q * 65 + d] = Qp[((size_t)(b * SS) + q0 + q) * DD + h * DH + d];
    }
    for (int i = tid; i < RR * DH; i += NTHR) {
        int r = i >> 6, d = i & 63;
        sE[r * 65 + d] = embK[(size_t)r * DD + h * DH + d];
    }
    __syncthreads();

    for (int i = tid; i < QT * RR; i += NTHR) {
        int q = i / RR, r = i - q * RR;
        float acc = 0.f;
        #pragma unroll 8
        for (int d = 0; d < DH; d++) acc += sQ[q * 65 + d] * sE[r * 65 + d];
        sW[q * 132 + r] = acc;
    }
    __syncthreads();

    const float scale = 0.125f;
    {
        const int ty = tid >> 6;
        const int tx = tid & 63;
        for (int kt = 0; kt < SS / KT; kt++) {
            int k0 = kt * KT;
            for (int i = tid; i < KT * DH; i += NTHR) {
                int k = i >> 6, d = i & 63;
                sK[k * 65 + d] = Kp[((size_t)(b * SS) + k0 + k) * DD + h * DH + d];
            }
            __syncthreads();

            float acc[4][4] = {};
            #pragma unroll 4
            for (int d = 0; d < DH; d++) {
                float qv[4], kv[4];
                #pragma unroll
                for (int i = 0; i < 4; i++) qv[i] = sQ[(ty * 4 + i) * 65 + d];
                #pragma unroll
                for (int j = 0; j < 4; j++) kv[j] = sK[(tx + 64 * j) * 65 + d];
                #pragma unroll
                for (int i = 0; i < 4; i++)
                    #pragma unroll
                    for (int j = 0; j < 4; j++)
                        acc[i][j] += qv[i] * kv[j];
            }
            #pragma unroll
            for (int i = 0; i < 4; i++) {
                int q = ty * 4 + i;
                int qg = q0 + q;
                #pragma unroll
                for (int j = 0; j < 4; j++) {
                    int gk = k0 + tx + 64 * j;
                    int rel = min(max(gk - qg, -KWIN), KWIN) + KWIN;
                    sScore[q * SSTR + gk] = (acc[i][j] + sW[q * 132 + rel]) * scale;
                }
            }
            __syncthreads();
        }
    }

    const int qrow = tid >> 4;
    const int s16  = tid & 15;
    {
        float* row = sScore + qrow * SSTR;
        float m = -1e30f;
        for (int k = s16; k < SS; k += 16) m = fmaxf(m, row[k]);
        #pragma unroll
        for (int off = 1; off < 16; off <<= 1)
            m = fmaxf(m, __shfl_xor_sync(0xffffffffu, m, off, 16));
        float sum = 0.f;
        for (int k = s16; k < SS; k += 16) {
            float e = __expf(row[k] - m);
            row[k] = e;
            sum += e;
        }
        #pragma unroll
        for (int off = 1; off < 16; off <<= 1)
            sum += __shfl_xor_sync(0xffffffffu, sum, off, 16);
        float inv = 1.f / sum;
        for (int k = s16; k < SS; k += 16) row[k] *= inv;
    }
    __syncthreads();

    {
        float* aout = attn_out + ((size_t)(b * HH + h) * SS + q0) * SS;
        for (int i = tid; i < QT * SS; i += NTHR) {
            int qq = i >> 10, kk = i & 1023;
            aout[(size_t)qq * SS + kk] = sScore[qq * SSTR + kk];
        }
    }

    {
        const int qg = q0 + qrow;
        for (int r = 1 + s16; r <= 127; r += 16) {
            int k = qg - KWIN + r;
            sW[qrow * 132 + r] = (k >= 0 && k < SS) ? sScore[qrow * SSTR + k] : 0.f;
        }
        float s0 = 0.f, s1 = 0.f;
        for (int k = s16; k < SS; k += 16) {
            float v = sScore[qrow * SSTR + k];
            if (k <= qg - KWIN) s0 += v;
            else if (k >= qg + KWIN) s1 += v;
        }
        #pragma unroll
        for (int off = 1; off < 16; off <<= 1) {
            s0 += __shfl_xor_sync(0xffffffffu, s0, off, 16);
            s1 += __shfl_xor_sync(0xffffffffu, s1, off, 16);
        }
        if (s16 == 0) {
            sW[qrow * 132 + 0]   = s0;
            sW[qrow * 132 + 128] = s1;
        }
    }
    __syncthreads();

    {
        const int t127 = tid & 127;
        const int kq   = tid >> 7;
        const int pty  = t127 >> 4;
        const int ptx  = t127 & 15;

        float oacc[4][4] = {};
        for (int vt = 0; vt < SS / KT; vt++) {
            int k0 = vt * KT;
            for (int i = tid; i < KT * DH; i += NTHR) {
                int k = i >> 6, d = i & 63;
                sK[k * 65 + d] = Vp[((size_t)(b * SS) + k0 + k) * DD + h * DH + d];
            }
            __syncthreads();
            const int kb = kq * 64;
            #pragma unroll 2
            for (int kk = kb; kk < kb + 64; kk++) {
                float vv[4];
                #pragma unroll
                for (int j = 0; j < 4; j++) vv[j] = sK[kk * 65 + ptx + 16 * j];
                #pragma unroll
                for (int i = 0; i < 4; i++) {
                    float a = sScore[(pty * 4 + i) * SSTR + k0 + kk];
                    #pragma unroll
                    for (int j = 0; j < 4; j++) oacc[i][j] += a * vv[j];
                }
            }
            __syncthreads();
        }

        for (int i = tid; i < RR * DH; i += NTHR) {
            int r = i >> 6, d = i & 63;
            sEv[r * 65 + d] = embV[(size_t)r * DD + h * DH + d];
        }
        __syncthreads();

        {
            int r0 = kq * 32;
            int r1 = (kq == 3) ? RR : (r0 + 32);
            for (int r = r0; r < r1; r++) {
                float ev[4];
                #pragma unroll
                for (int j = 0; j < 4; j++) ev[j] = sEv[r * 65 + ptx + 16 * j];
                #pragma unroll
                for (int i = 0; i < 4; i++) {
                    float w = sW[(pty * 4 + i) * 132 + r];
                    #pragma unroll
                    for (int j = 0; j < 4; j++) oacc[i][j] += w * ev[j];
                }
            }
        }

        if (kq > 0) {
            #pragma unroll
            for (int i = 0; i < 4; i++)
                #pragma unroll
                for (int j = 0; j < 4; j++)
                    sK[(i * 4 + j) * 384 + (kq - 1) * 128 + t127] = oacc[i][j];
        }
        __syncthreads();
        if (kq == 0) {
            #pragma unroll
            for (int i = 0; i < 4; i++) {
                int qq = pty * 4 + i;
                float* dst = ctx + ((size_t)(b * SS) + q0 + qq) * DD + h * DH;
                #pragma unroll
                for (int j = 0; j < 4; j++) {
                    int e = i * 4 + j;
                    float v = oacc[i][j]
                            + sK[e * 384 + 0 * 128 + t127]
                            + sK[e * 384 + 1 * 128 + t127]
                            + sK[e * 384 + 2 * 128 + t127];
                    dst[ptx + 16 * j] = v;
                }
            }
        }
    }
}

// ---------------- launch ----------------
extern "C" void kernel_launch(void* const* d_in, const int* in_sizes, int n_in,
                              void* d_out, int out_size)
{
    const float* query = (const float*)d_in[0];
    const float* key   = (const float*)d_in[1];
    const float* value = (const float*)d_in[2];
    const float* WQ_w  = (const float*)d_in[3];
    const float* WQ_b  = (const float*)d_in[4];
    const float* WK_w  = (const float*)d_in[5];
    const float* WK_b  = (const float*)d_in[6];
    const float* WV_w  = (const float*)d_in[7];
    const float* WV_b  = (const float*)d_in[8];
    const float* WO_w  = (const float*)d_in[9];
    const float* WO_b  = (const float*)d_in[10];
    const float* embK  = (const float*)d_in[11];
    const float* embV  = (const float*)d_in[12];

    float* out = (float*)d_out;                       // [B,S,D]
    float* attn = out + (size_t)BB * SS * DD;         // [B,H,S,S]

    static float *Qp = nullptr, *Kp, *Vp, *Ctx;
    static __nv_bfloat16 *qh, *ql, *kh, *kl, *vh, *vl, *ch, *cl;
    static __nv_bfloat16 *wqh, *wql, *wkh, *wkl, *wvh, *wvl, *woh, *wol;
    if (!Qp) {
        cudaGetSymbolAddress((void**)&Qp, g_Qp);
        cudaGetSymbolAddress((void**)&Kp, g_Kp);
        cudaGetSymbolAddress((void**)&Vp, g_Vp);
        cudaGetSymbolAddress((void**)&Ctx, g_Ctx);
        cudaGetSymbolAddress((void**)&qh, g_qh);   cudaGetSymbolAddress((void**)&ql, g_ql);
        cudaGetSymbolAddress((void**)&kh, g_kh);   cudaGetSymbolAddress((void**)&kl, g_kl);
        cudaGetSymbolAddress((void**)&vh, g_vh);   cudaGetSymbolAddress((void**)&vl, g_vl);
        cudaGetSymbolAddress((void**)&ch, g_ch);   cudaGetSymbolAddress((void**)&cl, g_cl);
        cudaGetSymbolAddress((void**)&wqh, g_wqh); cudaGetSymbolAddress((void**)&wql, g_wql);
        cudaGetSymbolAddress((void**)&wkh, g_wkh); cudaGetSymbolAddress((void**)&wkl, g_wkl);
        cudaGetSymbolAddress((void**)&wvh, g_wvh); cudaGetSymbolAddress((void**)&wvl, g_wvl);
        cudaGetSymbolAddress((void**)&woh, g_woh); cudaGetSymbolAddress((void**)&wol, g_wol);
        cudaFuncSetAttribute(attn_kernel,
                             cudaFuncAttributeMaxDynamicSharedMemorySize, SM_BYTES);
    }

    const int NIN = MTOT * DD;     // 3,145,728
    const int NW  = DD * DD;       // 589,824

    split_kernel<<<NIN / 4 / 256, 256>>>(query, qh, ql, NIN);
    split_kernel<<<NIN / 4 / 256, 256>>>(key,   kh, kl, NIN);
    split_kernel<<<NIN / 4 / 256, 256>>>(value, vh, vl, NIN);
    split_kernel<<<NW / 4 / 256, 256>>>(WQ_w, wqh, wql, NW);
    split_kernel<<<NW / 4 / 256, 256>>>(WK_w, wkh, wkl, NW);
    split_kernel<<<NW / 4 / 256, 256>>>(WV_w, wvh, wvl, NW);
    split_kernel<<<NW / 4 / 256, 256>>>(WO_w, woh, wol, NW);

    dim3 gproj(DD / 128, MTOT / 128);   // (6, 32)
    gemm_mma_bias<<<gproj, 256>>>(qh, ql, wqh, wql, WQ_b, Qp, MTOT, DD, DD);
    gemm_mma_bias<<<gproj, 256>>>(kh, kl, wkh, wkl, WK_b, Kp, MTOT, DD, DD);
    gemm_mma_bias<<<gproj, 256>>>(vh, vl, wvh, wvl, WV_b, Vp, MTOT, DD, DD);

    attn_kernel<<<BB * HH * (SS / QT), NTHR, SM_BYTES>>>(
        Qp, Kp, Vp, embK, embV, attn, Ctx);

    split_kernel<<<NIN / 4 / 256, 256>>>(Ctx, ch, cl, NIN);
    gemm_mma_bias<<<gproj, 256>>>(ch, cl, woh, wol, WO_b, out, MTOT, DD, DD);
}

// round 6
// speedup vs baseline: 2.2417x; 1.3632x over previous
#include <cuda_runtime.h>
#include <cuda_bf16.h>
#include <cstdint>
#include <cstring>

// Problem constants
#define BB 4
#define SS 1024
#define DD 768
#define HH 12
#define DH 64
#define RR 129          // 2K+1, K=64
#define KWIN 64

#define MTOT (BB * SS)  // 4096

// ---------------- scratch (no allocation allowed) ----------------
// g_Qp/g_Kp/g_Vp reinterpreted as bf16 hi/lo split storage (proj outputs)
__device__ float g_Qp[MTOT * DD];
__device__ float g_Kp[MTOT * DD];
__device__ float g_Vp[MTOT * DD];
__device__ float g_Ctx[MTOT * DD];

// bf16 hi/lo split scratch (inputs + weights + ctx)
__device__ __nv_bfloat16 g_qh[MTOT * DD],  g_ql[MTOT * DD];
__device__ __nv_bfloat16 g_kh[MTOT * DD],  g_kl[MTOT * DD];
__device__ __nv_bfloat16 g_vh[MTOT * DD],  g_vl[MTOT * DD];
__device__ __nv_bfloat16 g_ch[MTOT * DD],  g_cl[MTOT * DD];
__device__ __nv_bfloat16 g_wqh[DD * DD], g_wql[DD * DD];
__device__ __nv_bfloat16 g_wkh[DD * DD], g_wkl[DD * DD];
__device__ __nv_bfloat16 g_wvh[DD * DD], g_wvl[DD * DD];
__device__ __nv_bfloat16 g_woh[DD * DD], g_wol[DD * DD];

// ---------------- fp32 -> bf16 hi/lo split ----------------
__global__ __launch_bounds__(256) void split_kernel(
    const float* __restrict__ x, __nv_bfloat16* __restrict__ hi,
    __nv_bfloat16* __restrict__ lo, int n)
{
    int i = (blockIdx.x * 256 + threadIdx.x) * 4;
    if (i >= n) return;
    float4 v = *(const float4*)&x[i];
    float vv[4] = {v.x, v.y, v.z, v.w};
    uint16_t h[4], l[4];
    #pragma unroll
    for (int p = 0; p < 4; p++) {
        __nv_bfloat16 hb = __float2bfloat16(vv[p]);
        __nv_bfloat16 lb = __float2bfloat16(vv[p] - __bfloat162float(hb));
        h[p] = __bfloat16_as_ushort(hb);
        l[p] = __bfloat16_as_ushort(lb);
    }
    uint2 hp = make_uint2(((uint32_t)h[1] << 16) | h[0], ((uint32_t)h[3] << 16) | h[2]);
    uint2 lp = make_uint2(((uint32_t)l[1] << 16) | l[0], ((uint32_t)l[3] << 16) | l[2]);
    *(uint2*)&hi[i] = hp;
    *(uint2*)&lo[i] = lp;
}

// ---------------- mma.sync helper ----------------
__device__ __forceinline__ void mma16816(float* d, const uint32_t* a, const uint32_t* b) {
    asm volatile("mma.sync.aligned.m16n8k16.row.col.f32.bf16.bf16.f32 "
        "{%0,%1,%2,%3}, {%4,%5,%6,%7}, {%8,%9}, {%0,%1,%2,%3};"
        : "+f"(d[0]), "+f"(d[1]), "+f"(d[2]), "+f"(d[3])
        : "r"(a[0]), "r"(a[1]), "r"(a[2]), "r"(a[3]), "r"(b[0]), "r"(b[1]));
}

// ---------------- bf16-split GEMM: C = A @ W^T + bias ----------------
#define SP 40   // smem row pitch (bf16 elems): conflict-free for frag loads

__global__ __launch_bounds__(256) void gemm_mma_bias(
    const __nv_bfloat16* __restrict__ Ah, const __nv_bfloat16* __restrict__ Al,
    const __nv_bfloat16* __restrict__ Wh, const __nv_bfloat16* __restrict__ Wl,
    const float* __restrict__ bias, float* __restrict__ C,
    __nv_bfloat16* __restrict__ Ch, __nv_bfloat16* __restrict__ Cl,
    int M, int N, int Kd)
{
    __shared__ __nv_bfloat16 sAh[128 * SP], sAl[128 * SP];
    __shared__ __nv_bfloat16 sWh[128 * SP], sWl[128 * SP];

    const int tid = threadIdx.x;
    const int bm = blockIdx.y * 128, bn = blockIdx.x * 128;
    const int warp = tid >> 5, lane = tid & 31;
    const int wm = warp & 1, wn = warp >> 1;      // 2 x 4 warp grid
    const int g = lane >> 2, t = lane & 3;

    float d[4][4][4] = {};

    const int nch = Kd / 32;
    for (int c = 0; c < nch; c++) {
        const int k0 = c * 32;
        __syncthreads();
        #pragma unroll
        for (int it = 0; it < 2; it++) {
            int i = tid + it * 256;
            int row = i >> 2, cc = (i & 3) * 8;
            size_t ga = (size_t)(bm + row) * Kd + k0 + cc;
            size_t gw = (size_t)(bn + row) * Kd + k0 + cc;
            *(uint4*)&sAh[row * SP + cc] = *(const uint4*)&Ah[ga];
            *(uint4*)&sAl[row * SP + cc] = *(const uint4*)&Al[ga];
            *(uint4*)&sWh[row * SP + cc] = *(const uint4*)&Wh[gw];
            *(uint4*)&sWl[row * SP + cc] = *(const uint4*)&Wl[gw];
        }
        __syncthreads();

        #pragma unroll
        for (int ks = 0; ks < 2; ks++) {
            const int kk = ks * 16 + 2 * t;
            uint32_t bh[4][2], bl[4][2];
            #pragma unroll
            for (int ni = 0; ni < 4; ni++) {
                int rb = (wn * 32 + ni * 8 + g) * SP;
                bh[ni][0] = *(const uint32_t*)&sWh[rb + kk];
                bh[ni][1] = *(const uint32_t*)&sWh[rb + kk + 8];
                bl[ni][0] = *(const uint32_t*)&sWl[rb + kk];
                bl[ni][1] = *(const uint32_t*)&sWl[rb + kk + 8];
            }
            #pragma unroll
            for (int mi = 0; mi < 4; mi++) {
                int r0 = (wm * 64 + mi * 16 + g) * SP;
                int r1 = (wm * 64 + mi * 16 + 8 + g) * SP;
                uint32_t ah[4], al[4];
                ah[0] = *(const uint32_t*)&sAh[r0 + kk];
                ah[1] = *(const uint32_t*)&sAh[r1 + kk];
                ah[2] = *(const uint32_t*)&sAh[r0 + kk + 8];
                ah[3] = *(const uint32_t*)&sAh[r1 + kk + 8];
                al[0] = *(const uint32_t*)&sAl[r0 + kk];
                al[1] = *(const uint32_t*)&sAl[r1 + kk];
                al[2] = *(const uint32_t*)&sAl[r0 + kk + 8];
                al[3] = *(const uint32_t*)&sAl[r1 + kk + 8];
                #pragma unroll
                for (int ni = 0; ni < 4; ni++) {
                    mma16816(d[mi][ni], ah, bh[ni]);
                    mma16816(d[mi][ni], ah, bl[ni]);
                    mma16816(d[mi][ni], al, bh[ni]);
                }
            }
        }
    }

    #pragma unroll
    for (int mi = 0; mi < 4; mi++) {
        int r0 = bm + wm * 64 + mi * 16 + g;
        #pragma unroll
        for (int ni = 0; ni < 4; ni++) {
            int c0 = bn + wn * 32 + ni * 8 + 2 * t;
            float b0 = bias[c0], b1 = bias[c0 + 1];
            float v00 = d[mi][ni][0] + b0, v01 = d[mi][ni][1] + b1;
            float v10 = d[mi][ni][2] + b0, v11 = d[mi][ni][3] + b1;
            if (Ch) {
                // write bf16 hi/lo split pairs directly
                __nv_bfloat16 h00 = __float2bfloat16(v00), h01 = __float2bfloat16(v01);
                __nv_bfloat16 h10 = __float2bfloat16(v10), h11 = __float2bfloat16(v11);
                __nv_bfloat16 l00 = __float2bfloat16(v00 - __bfloat162float(h00));
                __nv_bfloat16 l01 = __float2bfloat16(v01 - __bfloat162float(h01));
                __nv_bfloat16 l10 = __float2bfloat16(v10 - __bfloat162float(h10));
                __nv_bfloat16 l11 = __float2bfloat16(v11 - __bfloat162float(h11));
                *(uint32_t*)&Ch[(size_t)r0 * N + c0] =
                    ((uint32_t)__bfloat16_as_ushort(h01) << 16) | __bfloat16_as_ushort(h00);
                *(uint32_t*)&Cl[(size_t)r0 * N + c0] =
                    ((uint32_t)__bfloat16_as_ushort(l01) << 16) | __bfloat16_as_ushort(l00);
                *(uint32_t*)&Ch[(size_t)(r0 + 8) * N + c0] =
                    ((uint32_t)__bfloat16_as_ushort(h11) << 16) | __bfloat16_as_ushort(h10);
                *(uint32_t*)&Cl[(size_t)(r0 + 8) * N + c0] =
                    ((uint32_t)__bfloat16_as_ushort(l11) << 16) | __bfloat16_as_ushort(l10);
            } else {
                C[(size_t)r0 * N + c0]           = v00;
                C[(size_t)r0 * N + c0 + 1]       = v01;
                C[(size_t)(r0 + 8) * N + c0]     = v10;
                C[(size_t)(r0 + 8) * N + c0 + 1] = v11;
            }
        }
    }
}

// ---------------- fused relative attention with mma.sync ----------------
// smem byte layout:
//   regionA : [0, 41472)        2 x 20736 -- embK^T / K chunks (bf16 pitch 72) or V^T pairs (u32 [64][81])
//   regionQ : [41472, 50688)    qH, qL  (bf16 32x72)
//   regionP : [50688, 72192)    pH, pL  (bf16 32x168)  / fp32 staging [2][32][64]
//   sW      : [72192, 92672)    fp32 [32][160]
//   sScore  : [92672, 225792)   fp32 [32][1040]
#define KP 72
#define PP 168
#define VP 81
#define WP 160
#define SSTR 1040
#define OFF_A  0
#define ASTRIDE 20736
#define OFF_Q  41472
#define QSTRIDE 4608
#define OFF_P  50688
#define PSTRIDE 10752
#define OFF_W  72192
#define OFF_S  92672
#define ASM_BYTES 225792

__global__ __launch_bounds__(512) void attn_mma(
    const __nv_bfloat16* __restrict__ QsH, const __nv_bfloat16* __restrict__ QsL,
    const __nv_bfloat16* __restrict__ KsH, const __nv_bfloat16* __restrict__ KsL,
    const __nv_bfloat16* __restrict__ VsH, const __nv_bfloat16* __restrict__ VsL,
    const float* __restrict__ embK, const float* __restrict__ embV,
    float* __restrict__ attn_out, float* __restrict__ ctx)
{
    extern __shared__ char smc[];
    __nv_bfloat16* aH = (__nv_bfloat16*)(smc + OFF_A);
    __nv_bfloat16* aL = (__nv_bfloat16*)(smc + OFF_A + ASTRIDE);
    uint32_t* vH = (uint32_t*)(smc + OFF_A);
    uint32_t* vL = (uint32_t*)(smc + OFF_A + ASTRIDE);
    __nv_bfloat16* qH = (__nv_bfloat16*)(smc + OFF_Q);
    __nv_bfloat16* qL = (__nv_bfloat16*)(smc + OFF_Q + QSTRIDE);
    __nv_bfloat16* pH = (__nv_bfloat16*)(smc + OFF_P);
    __nv_bfloat16* pL = (__nv_bfloat16*)(smc + OFF_P + PSTRIDE);
    float* stg = (float*)(smc + OFF_P);
    float* sW  = (float*)(smc + OFF_W);
    float* sS  = (float*)(smc + OFF_S);

    const int tid = threadIdx.x;
    const int warp = tid >> 5, lane = tid & 31;
    const int g = lane >> 2, t = lane & 3;
    const int nq = SS / 32;
    const int qt = blockIdx.x % nq;
    const int h  = (blockIdx.x / nq) % HH;
    const int b  = blockIdx.x / (nq * HH);
    const int q0 = qt * 32;

    // ---- load Q tile (pre-split bf16) ----
    for (int i = tid; i < 512; i += 512) {
        int s = i >> 8, idx = i & 255;
        int row = idx >> 3, c = (idx & 7) * 8;
        const __nv_bfloat16* src = s ? QsL : QsH;
        __nv_bfloat16* dst = s ? qL : qH;
        *(uint4*)&dst[row * KP + c] =
            *(const uint4*)&src[((size_t)(b * SS) + q0 + row) * DD + h * DH + c];
    }
    // ---- load embK^T (136 rows x 64, split on the fly, pad >=129 zero) ----
    for (int i = tid; i < 1088; i += 512) {
        int r = i >> 3, c = (i & 7) * 8;
        float v[8] = {};
        if (r < RR) {
            float4 x = *(const float4*)&embK[(size_t)r * DD + h * DH + c];
            float4 y = *(const float4*)&embK[(size_t)r * DD + h * DH + c + 4];
            v[0]=x.x; v[1]=x.y; v[2]=x.z; v[3]=x.w; v[4]=y.x; v[5]=y.y; v[6]=y.z; v[7]=y.w;
        }
        #pragma unroll
        for (int j = 0; j < 8; j++) {
            __nv_bfloat16 hb = __float2bfloat16(v[j]);
            aH[r * KP + c + j] = hb;
            aL[r * KP + c + j] = __float2bfloat16(v[j] - __bfloat162float(hb));
        }
    }
    __syncthreads();

    // ---- rel table via mma: sW[q][r] = Q . embK_r ----
    for (int nt = warp; nt < 17; nt += 16) {
        float dr[2][4] = {};
        #pragma unroll
        for (int ks = 0; ks < 4; ks++) {
            int kk = ks * 16 + 2 * t;
            int rb = (nt * 8 + g) * KP;
            uint32_t bh2[2] = {*(uint32_t*)&aH[rb + kk], *(uint32_t*)&aH[rb + kk + 8]};
            uint32_t bl2[2] = {*(uint32_t*)&aL[rb + kk], *(uint32_t*)&aL[rb + kk + 8]};
            #pragma unroll
            for (int mi = 0; mi < 2; mi++) {
                int r0 = (mi * 16 + g) * KP, r1 = r0 + 8 * KP;
                uint32_t ah4[4] = {*(uint32_t*)&qH[r0 + kk], *(uint32_t*)&qH[r1 + kk],
                                   *(uint32_t*)&qH[r0 + kk + 8], *(uint32_t*)&qH[r1 + kk + 8]};
                uint32_t al4[4] = {*(uint32_t*)&qL[r0 + kk], *(uint32_t*)&qL[r1 + kk],
                                   *(uint32_t*)&qL[r0 + kk + 8], *(uint32_t*)&qL[r1 + kk + 8]};
                mma16816(dr[mi], ah4, bh2);
                mma16816(dr[mi], ah4, bl2);
                mma16816(dr[mi], al4, bh2);
            }
        }
        #pragma unroll
        for (int mi = 0; mi < 2; mi++) {
            int q = mi * 16 + g;
            int r = nt * 8 + 2 * t;
            if (r < RR)     sW[q * WP + r]           = dr[mi][0];
            if (r + 1 < RR) sW[q * WP + r + 1]       = dr[mi][1];
            if (r < RR)     sW[(q + 8) * WP + r]     = dr[mi][2];
            if (r + 1 < RR) sW[(q + 8) * WP + r + 1] = dr[mi][3];
        }
    }
    __syncthreads();

    // ---- scores: 8 chunks of 128 k-cols ----
    const float scale = 0.125f;
    for (int kt = 0; kt < 8; kt++) {
        for (int i = tid; i < 2048; i += 512) {
            int s = i >> 10, idx = i & 1023;
            int row = idx >> 3, c = (idx & 7) * 8;
            const __nv_bfloat16* src = s ? KsL : KsH;
            __nv_bfloat16* dst = s ? aL : aH;
            *(uint4*)&dst[row * KP + c] =
                *(const uint4*)&src[((size_t)(b * SS) + kt * 128 + row) * DD + h * DH + c];
        }
        __syncthreads();

        float dacc[2][4] = {};
        #pragma unroll
        for (int ks = 0; ks < 4; ks++) {
            int kk = ks * 16 + 2 * t;
            int rb = (warp * 8 + g) * KP;
            uint32_t bh2[2] = {*(uint32_t*)&aH[rb + kk], *(uint32_t*)&aH[rb + kk + 8]};
            uint32_t bl2[2] = {*(uint32_t*)&aL[rb + kk], *(uint32_t*)&aL[rb + kk + 8]};
            #pragma unroll
            for (int mi = 0; mi < 2; mi++) {
                int r0 = (mi * 16 + g) * KP, r1 = r0 + 8 * KP;
                uint32_t ah4[4] = {*(uint32_t*)&qH[r0 + kk], *(uint32_t*)&qH[r1 + kk],
                                   *(uint32_t*)&qH[r0 + kk + 8], *(uint32_t*)&qH[r1 + kk + 8]};
                uint32_t al4[4] = {*(uint32_t*)&qL[r0 + kk], *(uint32_t*)&qL[r1 + kk],
                                   *(uint32_t*)&qL[r0 + kk + 8], *(uint32_t*)&qL[r1 + kk + 8]};
                mma16816(dacc[mi], ah4, bh2);
                mma16816(dacc[mi], ah4, bl2);
                mma16816(dacc[mi], al4, bh2);
            }
        }
        #pragma unroll
        for (int mi = 0; mi < 2; mi++) {
            int q = mi * 16 + g;
            int gk = kt * 128 + warp * 8 + 2 * t;
            #pragma unroll
            for (int rr = 0; rr < 2; rr++) {
                int qq = q + rr * 8;
                int qg = q0 + qq;
                int rel0 = min(max(gk - qg,     -KWIN), KWIN) + KWIN;
                int rel1 = min(max(gk + 1 - qg, -KWIN), KWIN) + KWIN;
                sS[qq * SSTR + gk]     = (dacc[mi][rr * 2]     + sW[qq * WP + rel0]) * scale;
                sS[qq * SSTR + gk + 1] = (dacc[mi][rr * 2 + 1] + sW[qq * WP + rel1]) * scale;
            }
        }
        __syncthreads();
    }

    // ---- softmax: 16 threads per q-row ----
    const int qrow = tid >> 4;
    const int s16  = tid & 15;
    {
        float* row = sS + qrow * SSTR;
        float m = -1e30f;
        for (int k = s16; k < SS; k += 16) m = fmaxf(m, row[k]);
        #pragma unroll
        for (int off = 1; off < 16; off <<= 1)
            m = fmaxf(m, __shfl_xor_sync(0xffffffffu, m, off, 16));
        float sum = 0.f;
        for (int k = s16; k < SS; k += 16) {
            float e = __expf(row[k] - m);
            row[k] = e;
            sum += e;
        }
        #pragma unroll
        for (int off = 1; off < 16; off <<= 1)
            sum += __shfl_xor_sync(0xffffffffu, sum, off, 16);
        float inv = 1.f / sum;
        for (int k = s16; k < SS; k += 16) row[k] *= inv;
    }
    __syncthreads();

    // ---- write attn ----
    {
        float* aout = attn_out + ((size_t)(b * HH + h) * SS + q0) * SS;
        for (int i = tid; i < 32 * SS; i += 512) {
            int qq = i >> 10, kk = i & 1023;
            aout[(size_t)qq * SS + kk] = sS[qq * SSTR + kk];
        }
    }

    // ---- w buckets into sW (zero-pad cols 129..159) ----
    {
        const int qg = q0 + qrow;
        for (int r = 1 + s16; r <= 127; r += 16) {
            int k = qg - KWIN + r;
            sW[qrow * WP + r] = (k >= 0 && k < SS) ? sS[qrow * SSTR + k] : 0.f;
        }
        float s0 = 0.f, s1 = 0.f;
        for (int k = s16; k < SS; k += 16) {
            float v = sS[qrow * SSTR + k];
            if (k <= qg - KWIN) s0 += v;
            else if (k >= qg + KWIN) s1 += v;
        }
        #pragma unroll
        for (int off = 1; off < 16; off <<= 1) {
            s0 += __shfl_xor_sync(0xffffffffu, s0, off, 16);
            s1 += __shfl_xor_sync(0xffffffffu, s1, off, 16);
        }
        if (s16 == 0) {
            sW[qrow * WP + 0]   = s0;
            sW[qrow * WP + 128] = s1;
        }
        for (int i = tid; i < 32 * 31; i += 512) {
            int q = i / 31, r = 129 + (i % 31);
            sW[q * WP + r] = 0.f;
        }
    }
    __syncthreads();

    // ---- PV: 8 chunks of 128 positions; warp = (d-tile wn, k-half hf) ----
    const int wn = warp >> 1, hf = warp & 1;
    float oacc[2][4] = {};
    for (int vt = 0; vt < 8; vt++) {
        // V chunk transposed into pairs: vH/vL [d][pair] pitch VP
        for (int i = tid; i < 1024; i += 512) {
            int s = i >> 9, r = i & 511;
            int p = r >> 3, dg = r & 7;
            const __nv_bfloat16* src = s ? VsL : VsH;
            size_t base = ((size_t)(b * SS) + vt * 128 + 2 * p) * DD + h * DH + dg * 8;
            uint4 w0 = *(const uint4*)&src[base];
            uint4 w1 = *(const uint4*)&src[base + DD];
            uint16_t a0[8], a1[8];
            memcpy(a0, &w0, 16);
            memcpy(a1, &w1, 16);
            uint32_t* dst = s ? vL : vH;
            #pragma unroll
            for (int j = 0; j < 8; j++)
                dst[(dg * 8 + j) * VP + p] = (uint32_t)a0[j] | ((uint32_t)a1[j] << 16);
        }
        // P chunk fp32 -> bf16 hi/lo
        for (int i = tid; i < 4096; i += 512) {
            int q = i >> 7, c = i & 127;
            float v = sS[q * SSTR + vt * 128 + c];
            __nv_bfloat16 hb = __float2bfloat16(v);
            pH[q * PP + c] = hb;
            pL[q * PP + c] = __float2bfloat16(v - __bfloat162float(hb));
        }
        __syncthreads();

        #pragma unroll
        for (int ks = 0; ks < 4; ks++) {
            int kb = hf * 64 + ks * 16 + 2 * t;
            int widx = hf * 32 + ks * 8 + t;
            int vrow = (wn * 8 + g) * VP;
            uint32_t bh2[2] = {vH[vrow + widx], vH[vrow + widx + 4]};
            uint32_t bl2[2] = {vL[vrow + widx], vL[vrow + widx + 4]};
            #pragma unroll
            for (int mi = 0; mi < 2; mi++) {
                int r0 = (mi * 16 + g) * PP, r1 = r0 + 8 * PP;
                uint32_t ah4[4] = {*(uint32_t*)&pH[r0 + kb], *(uint32_t*)&pH[r1 + kb],
                                   *(uint32_t*)&pH[r0 + kb + 8], *(uint32_t*)&pH[r1 + kb + 8]};
                uint32_t al4[4] = {*(uint32_t*)&pL[r0 + kb], *(uint32_t*)&pL[r1 + kb],
                                   *(uint32_t*)&pL[r0 + kb + 8], *(uint32_t*)&pL[r1 + kb + 8]};
                mma16816(oacc[mi], ah4, bh2);
                mma16816(oacc[mi], ah4, bl2);
                mma16816(oacc[mi], al4, bh2);
            }
        }
        __syncthreads();
    }

    // ---- extra chunk: w @ embV_h (160 padded cols) ----
    {
        for (int i = tid; i < 640; i += 512) {
            int p = i >> 3, dg = i & 7;
            int r0 = 2 * p, r1 = 2 * p + 1;
            float v0[8] = {}, v1[8] = {};
            if (r0 < RR) {
                float4 x = *(const float4*)&embV[(size_t)r0 * DD + h * DH + dg * 8];
                float4 y = *(const float4*)&embV[(size_t)r0 * DD + h * DH + dg * 8 + 4];
                v0[0]=x.x; v0[1]=x.y; v0[2]=x.z; v0[3]=x.w; v0[4]=y.x; v0[5]=y.y; v0[6]=y.z; v0[7]=y.w;
            }
            if (r1 < RR) {
                float4 x = *(const float4*)&embV[(size_t)r1 * DD + h * DH + dg * 8];
                float4 y = *(const float4*)&embV[(size_t)r1 * DD + h * DH + dg * 8 + 4];
                v1[0]=x.x; v1[1]=x.y; v1[2]=x.z; v1[3]=x.w; v1[4]=y.x; v1[5]=y.y; v1[6]=y.z; v1[7]=y.w;
            }
            #pragma unroll
            for (int j = 0; j < 8; j++) {
                __nv_bfloat16 h0 = __float2bfloat16(v0[j]);
                __nv_bfloat16 h1 = __float2bfloat16(v1[j]);
                __nv_bfloat16 l0 = __float2bfloat16(v0[j] - __bfloat162float(h0));
                __nv_bfloat16 l1 = __float2bfloat16(v1[j] - __bfloat162float(h1));
                vH[(dg * 8 + j) * VP + p] =
                    (uint32_t)__bfloat16_as_ushort(h0) | ((uint32_t)__bfloat16_as_ushort(h1) << 16);
                vL[(dg * 8 + j) * VP + p] =
                    (uint32_t)__bfloat16_as_ushort(l0) | ((uint32_t)__bfloat16_as_ushort(l1) << 16);
            }
        }
        for (int i = tid; i < 32 * 160; i += 512) {
            int q = i / 160, c = i - q * 160;
            float v = sW[q * WP + c];
            __nv_bfloat16 hb = __float2bfloat16(v);
            pH[q * PP + c] = hb;
            pL[q * PP + c] = __float2bfloat16(v - __bfloat162float(hb));
        }
        __syncthreads();

        #pragma unroll
        for (int ks = 0; ks < 5; ks++) {
            int kb = hf * 80 + ks * 16 + 2 * t;
            int widx = hf * 40 + ks * 8 + t;
            int vrow = (wn * 8 + g) * VP;
            uint32_t bh2[2] = {vH[vrow + widx], vH[vrow + widx + 4]};
            uint32_t bl2[2] = {vL[vrow + widx], vL[vrow + widx + 4]};
            #pragma unroll
            for (int mi = 0; mi < 2; mi++) {
                int r0 = (mi * 16 + g) * PP, r1 = r0 + 8 * PP;
                uint32_t ah4[4] = {*(uint32_t*)&pH[r0 + kb], *(uint32_t*)&pH[r1 + kb],
                                   *(uint32_t*)&pH[r0 + kb + 8], *(uint32_t*)&pH[r1 + kb + 8]};
                uint32_t al4[4] = {*(uint32_t*)&pL[r0 + kb], *(uint32_t*)&pL[r1 + kb],
                                   *(uint32_t*)&pL[r0 + kb + 8], *(uint32_t*)&pL[r1 + kb + 8]};
                mma16816(oacc[mi], ah4, bh2);
                mma16816(oacc[mi], ah4, bl2);
                mma16816(oacc[mi], al4, bh2);
            }
        }
        __syncthreads();
    }

    // ---- reduce two k-halves and write ctx ----
    #pragma unroll
    for (int mi = 0; mi < 2; mi++) {
        int q = mi * 16 + g;
        int dc = wn * 8 + 2 * t;
        stg[hf * 2048 + q * 64 + dc]           = oacc[mi][0];
        stg[hf * 2048 + q * 64 + dc + 1]       = oacc[mi][1];
        stg[hf * 2048 + (q + 8) * 64 + dc]     = oacc[mi][2];
        stg[hf * 2048 + (q + 8) * 64 + dc + 1] = oacc[mi][3];
    }
    __syncthreads();
    for (int i = tid; i < 2048; i += 512) {
        int q = i >> 6, dc = i & 63;
        ctx[((size_t)(b * SS) + q0 + q) * DD + h * DH + dc] = stg[i] + stg[2048 + i];
    }
}

// ---------------- launch ----------------
extern "C" void kernel_launch(void* const* d_in, const int* in_sizes, int n_in,
                              void* d_out, int out_size)
{
    const float* query = (const float*)d_in[0];
    const float* key   = (const float*)d_in[1];
    const float* value = (const float*)d_in[2];
    const float* WQ_w  = (const float*)d_in[3];
    const float* WQ_b  = (const float*)d_in[4];
    const float* WK_w  = (const float*)d_in[5];
    const float* WK_b  = (const float*)d_in[6];
    const float* WV_w  = (const float*)d_in[7];
    const float* WV_b  = (const float*)d_in[8];
    const float* WO_w  = (const float*)d_in[9];
    const float* WO_b  = (const float*)d_in[10];
    const float* embK  = (const float*)d_in[11];
    const float* embV  = (const float*)d_in[12];

    float* out = (float*)d_out;                       // [B,S,D]
    float* attn = out + (size_t)BB * SS * DD;         // [B,H,S,S]

    static float *Qp = nullptr, *Kp, *Vp, *Ctx;
    static __nv_bfloat16 *qh, *ql, *kh, *kl, *vh, *vl, *ch, *cl;
    static __nv_bfloat16 *wqh, *wql, *wkh, *wkl, *wvh, *wvl, *woh, *wol;
    if (!Qp) {
        cudaGetSymbolAddress((void**)&Qp, g_Qp);
        cudaGetSymbolAddress((void**)&Kp, g_Kp);
        cudaGetSymbolAddress((void**)&Vp, g_Vp);
        cudaGetSymbolAddress((void**)&Ctx, g_Ctx);
        cudaGetSymbolAddress((void**)&qh, g_qh);   cudaGetSymbolAddress((void**)&ql, g_ql);
        cudaGetSymbolAddress((void**)&kh, g_kh);   cudaGetSymbolAddress((void**)&kl, g_kl);
        cudaGetSymbolAddress((void**)&vh, g_vh);   cudaGetSymbolAddress((void**)&vl, g_vl);
        cudaGetSymbolAddress((void**)&ch, g_ch);   cudaGetSymbolAddress((void**)&cl, g_cl);
        cudaGetSymbolAddress((void**)&wqh, g_wqh); cudaGetSymbolAddress((void**)&wql, g_wql);
        cudaGetSymbolAddress((void**)&wkh, g_wkh); cudaGetSymbolAddress((void**)&wkl, g_wkl);
        cudaGetSymbolAddress((void**)&wvh, g_wvh); cudaGetSymbolAddress((void**)&wvl, g_wvl);
        cudaGetSymbolAddress((void**)&woh, g_woh); cudaGetSymbolAddress((void**)&wol, g_wol);
        cudaFuncSetAttribute(attn_mma,
                             cudaFuncAttributeMaxDynamicSharedMemorySize, ASM_BYTES);
    }

    // proj split outputs live in the old fp32 scratch (reinterpreted)
    __nv_bfloat16* QsH = (__nv_bfloat16*)Qp;  __nv_bfloat16* QsL = QsH + (size_t)MTOT * DD;
    __nv_bfloat16* KsH = (__nv_bfloat16*)Kp;  __nv_bfloat16* KsL = KsH + (size_t)MTOT * DD;
    __nv_bfloat16* VsH = (__nv_bfloat16*)Vp;  __nv_bfloat16* VsL = VsH + (size_t)MTOT * DD;

    const int NIN = MTOT * DD;     // 3,145,728
    const int NW  = DD * DD;       // 589,824

    split_kernel<<<NIN / 4 / 256, 256>>>(query, qh, ql, NIN);
    split_kernel<<<NIN / 4 / 256, 256>>>(key,   kh, kl, NIN);
    split_kernel<<<NIN / 4 / 256, 256>>>(value, vh, vl, NIN);
    split_kernel<<<NW / 4 / 256, 256>>>(WQ_w, wqh, wql, NW);
    split_kernel<<<NW / 4 / 256, 256>>>(WK_w, wkh, wkl, NW);
    split_kernel<<<NW / 4 / 256, 256>>>(WV_w, wvh, wvl, NW);
    split_kernel<<<NW / 4 / 256, 256>>>(WO_w, woh, wol, NW);

    dim3 gproj(DD / 128, MTOT / 128);   // (6, 32)
    gemm_mma_bias<<<gproj, 256>>>(qh, ql, wqh, wql, WQ_b, nullptr, QsH, QsL, MTOT, DD, DD);
    gemm_mma_bias<<<gproj, 256>>>(kh, kl, wkh, wkl, WK_b, nullptr, KsH, KsL, MTOT, DD, DD);
    gemm_mma_bias<<<gproj, 256>>>(vh, vl, wvh, wvl, WV_b, nullptr, VsH, VsL, MTOT, DD, DD);

    attn_mma<<<BB * HH * (SS / 32), 512, ASM_BYTES>>>(
        QsH, QsL, KsH, KsL, VsH, VsL, embK, embV, attn, Ctx);

    split_kernel<<<NIN / 4 / 256, 256>>>(Ctx, ch, cl, NIN);
    gemm_mma_bias<<<gproj, 256>>>(ch, cl, woh, wol, WO_b, out, nullptr, nullptr, MTOT, DD, DD);
}

// round 7
// speedup vs baseline: 2.3272x; 1.0381x over previous
#include <cuda_runtime.h>
#include <cuda_bf16.h>
#include <cstdint>
#include <cstring>

// Problem constants
#define BB 4
#define SS 1024
#define DD 768
#define HH 12
#define DH 64
#define RR 129          // 2K+1, K=64
#define KWIN 64

#define MTOT (BB * SS)  // 4096

// ---------------- scratch (no allocation allowed) ----------------
__device__ float g_Qp[MTOT * DD];      // reinterpreted: bf16 QsH/QsL
__device__ float g_Kp[MTOT * DD];      // reinterpreted: bf16 KsH/KsL
__device__ float g_Vp[MTOT * DD];      // reinterpreted: bf16 VsH/VsL
__device__ float g_Ctx[MTOT * DD];

__device__ __nv_bfloat16 g_qh[MTOT * DD],  g_ql[MTOT * DD];
__device__ __nv_bfloat16 g_kh[MTOT * DD],  g_kl[MTOT * DD];
__device__ __nv_bfloat16 g_vh[MTOT * DD],  g_vl[MTOT * DD];
__device__ __nv_bfloat16 g_ch[MTOT * DD],  g_cl[MTOT * DD];
__device__ __nv_bfloat16 g_wqh[DD * DD], g_wql[DD * DD];
__device__ __nv_bfloat16 g_wkh[DD * DD], g_wkl[DD * DD];
__device__ __nv_bfloat16 g_wvh[DD * DD], g_wvl[DD * DD];
__device__ __nv_bfloat16 g_woh[DD * DD], g_wol[DD * DD];

// packed V^T: [b*HH+h][d(64)][pair(512)] u32 = (vlo | vhi<<16) of positions 2p,2p+1
__device__ uint32_t g_vtH[BB * HH * DH * (SS / 2)];
__device__ uint32_t g_vtL[BB * HH * DH * (SS / 2)];

// ---------------- fp32 -> bf16 hi/lo split helpers ----------------
__device__ __forceinline__ void split4(const float* __restrict__ x,
                                       __nv_bfloat16* __restrict__ hi,
                                       __nv_bfloat16* __restrict__ lo, int i)
{
    float4 v = *(const float4*)&x[i];
    float vv[4] = {v.x, v.y, v.z, v.w};
    uint16_t h[4], l[4];
    #pragma unroll
    for (int p = 0; p < 4; p++) {
        __nv_bfloat16 hb = __float2bfloat16(vv[p]);
        __nv_bfloat16 lb = __float2bfloat16(vv[p] - __bfloat162float(hb));
        h[p] = __bfloat16_as_ushort(hb);
        l[p] = __bfloat16_as_ushort(lb);
    }
    *(uint2*)&hi[i] = make_uint2(((uint32_t)h[1] << 16) | h[0], ((uint32_t)h[3] << 16) | h[2]);
    *(uint2*)&lo[i] = make_uint2(((uint32_t)l[1] << 16) | l[0], ((uint32_t)l[3] << 16) | l[2]);
}

__global__ __launch_bounds__(256) void split_kernel(
    const float* __restrict__ x, __nv_bfloat16* __restrict__ hi,
    __nv_bfloat16* __restrict__ lo, int n)
{
    int i = (blockIdx.x * 256 + threadIdx.x) * 4;
    if (i < n) split4(x, hi, lo, i);
}

__global__ __launch_bounds__(256) void split3_kernel(
    const float* __restrict__ a, __nv_bfloat16* ah, __nv_bfloat16* al,
    const float* __restrict__ b, __nv_bfloat16* bh, __nv_bfloat16* bl,
    const float* __restrict__ c, __nv_bfloat16* ch, __nv_bfloat16* cl, int n)
{
    int i = (blockIdx.x * 256 + threadIdx.x) * 4;
    if (i >= n) return;
    const float* x; __nv_bfloat16 *hi, *lo;
    if (blockIdx.y == 0)      { x = a; hi = ah; lo = al; }
    else if (blockIdx.y == 1) { x = b; hi = bh; lo = bl; }
    else                      { x = c; hi = ch; lo = cl; }
    split4(x, hi, lo, i);
}

__global__ __launch_bounds__(256) void split4_kernel(
    const float* __restrict__ a, __nv_bfloat16* ah, __nv_bfloat16* al,
    const float* __restrict__ b, __nv_bfloat16* bh, __nv_bfloat16* bl,
    const float* __restrict__ c, __nv_bfloat16* ch, __nv_bfloat16* cl,
    const float* __restrict__ d, __nv_bfloat16* dh, __nv_bfloat16* dl, int n)
{
    int i = (blockIdx.x * 256 + threadIdx.x) * 4;
    if (i >= n) return;
    const float* x; __nv_bfloat16 *hi, *lo;
    if (blockIdx.y == 0)      { x = a; hi = ah; lo = al; }
    else if (blockIdx.y == 1) { x = b; hi = bh; lo = bl; }
    else if (blockIdx.y == 2) { x = c; hi = ch; lo = cl; }
    else                      { x = d; hi = dh; lo = dl; }
    split4(x, hi, lo, i);
}

// ---------------- mma.sync helper ----------------
__device__ __forceinline__ void mma16816(float* d, const uint32_t* a, const uint32_t* b) {
    asm volatile("mma.sync.aligned.m16n8k16.row.col.f32.bf16.bf16.f32 "
        "{%0,%1,%2,%3}, {%4,%5,%6,%7}, {%8,%9}, {%0,%1,%2,%3};"
        : "+f"(d[0]), "+f"(d[1]), "+f"(d[2]), "+f"(d[3])
        : "r"(a[0]), "r"(a[1]), "r"(a[2]), "r"(a[3]), "r"(b[0]), "r"(b[1]));
}

// ---------------- bf16-split GEMM body ----------------
#define SP 40

__device__ __forceinline__ void gemm_body(
    const __nv_bfloat16* __restrict__ Ah, const __nv_bfloat16* __restrict__ Al,
    const __nv_bfloat16* __restrict__ Wh, const __nv_bfloat16* __restrict__ Wl,
    const float* __restrict__ bias, float* __restrict__ C,
    __nv_bfloat16* __restrict__ Ch, __nv_bfloat16* __restrict__ Cl,
    int M, int N, int Kd)
{
    static __shared__ __nv_bfloat16 sAh[128 * SP], sAl[128 * SP];
    static __shared__ __nv_bfloat16 sWh[128 * SP], sWl[128 * SP];

    const int tid = threadIdx.x;
    const int bm = blockIdx.y * 128, bn = blockIdx.x * 128;
    const int warp = tid >> 5, lane = tid & 31;
    const int wm = warp & 1, wn = warp >> 1;
    const int g = lane >> 2, t = lane & 3;

    float d[4][4][4] = {};

    const int nch = Kd / 32;
    for (int c = 0; c < nch; c++) {
        const int k0 = c * 32;
        __syncthreads();
        #pragma unroll
        for (int it = 0; it < 2; it++) {
            int i = tid + it * 256;
            int row = i >> 2, cc = (i & 3) * 8;
            size_t ga = (size_t)(bm + row) * Kd + k0 + cc;
            size_t gw = (size_t)(bn + row) * Kd + k0 + cc;
            *(uint4*)&sAh[row * SP + cc] = *(const uint4*)&Ah[ga];
            *(uint4*)&sAl[row * SP + cc] = *(const uint4*)&Al[ga];
            *(uint4*)&sWh[row * SP + cc] = *(const uint4*)&Wh[gw];
            *(uint4*)&sWl[row * SP + cc] = *(const uint4*)&Wl[gw];
        }
        __syncthreads();

        #pragma unroll
        for (int ks = 0; ks < 2; ks++) {
            const int kk = ks * 16 + 2 * t;
            uint32_t bh[4][2], bl[4][2];
            #pragma unroll
            for (int ni = 0; ni < 4; ni++) {
                int rb = (wn * 32 + ni * 8 + g) * SP;
                bh[ni][0] = *(const uint32_t*)&sWh[rb + kk];
                bh[ni][1] = *(const uint32_t*)&sWh[rb + kk + 8];
                bl[ni][0] = *(const uint32_t*)&sWl[rb + kk];
                bl[ni][1] = *(const uint32_t*)&sWl[rb + kk + 8];
            }
            #pragma unroll
            for (int mi = 0; mi < 4; mi++) {
                int r0 = (wm * 64 + mi * 16 + g) * SP;
                int r1 = (wm * 64 + mi * 16 + 8 + g) * SP;
                uint32_t ah[4], al[4];
                ah[0] = *(const uint32_t*)&sAh[r0 + kk];
                ah[1] = *(const uint32_t*)&sAh[r1 + kk];
                ah[2] = *(const uint32_t*)&sAh[r0 + kk + 8];
                ah[3] = *(const uint32_t*)&sAh[r1 + kk + 8];
                al[0] = *(const uint32_t*)&sAl[r0 + kk];
                al[1] = *(const uint32_t*)&sAl[r1 + kk];
                al[2] = *(const uint32_t*)&sAl[r0 + kk + 8];
                al[3] = *(const uint32_t*)&sAl[r1 + kk + 8];
                #pragma unroll
                for (int ni = 0; ni < 4; ni++) {
                    mma16816(d[mi][ni], ah, bh[ni]);
                    mma16816(d[mi][ni], ah, bl[ni]);
                    mma16816(d[mi][ni], al, bh[ni]);
                }
            }
        }
    }

    #pragma unroll
    for (int mi = 0; mi < 4; mi++) {
        int r0 = bm + wm * 64 + mi * 16 + g;
        #pragma unroll
        for (int ni = 0; ni < 4; ni++) {
            int c0 = bn + wn * 32 + ni * 8 + 2 * t;
            float b0 = bias[c0], b1 = bias[c0 + 1];
            float v00 = d[mi][ni][0] + b0, v01 = d[mi][ni][1] + b1;
            float v10 = d[mi][ni][2] + b0, v11 = d[mi][ni][3] + b1;
            if (Ch) {
                uint32_t hp0, lp0, hp1, lp1;
                asm("cvt.rn.bf16x2.f32 %0, %1, %2;" : "=r"(hp0) : "f"(v01), "f"(v00));
                asm("cvt.rn.bf16x2.f32 %0, %1, %2;" : "=r"(hp1) : "f"(v11), "f"(v10));
                float h00 = __uint_as_float(hp0 << 16);
                float h01 = __uint_as_float(hp0 & 0xffff0000u);
                float h10 = __uint_as_float(hp1 << 16);
                float h11 = __uint_as_float(hp1 & 0xffff0000u);
                asm("cvt.rn.bf16x2.f32 %0, %1, %2;" : "=r"(lp0) : "f"(v01 - h01), "f"(v00 - h00));
                asm("cvt.rn.bf16x2.f32 %0, %1, %2;" : "=r"(lp1) : "f"(v11 - h11), "f"(v10 - h10));
                *(uint32_t*)&Ch[(size_t)r0 * N + c0]       = hp0;
                *(uint32_t*)&Cl[(size_t)r0 * N + c0]       = lp0;
                *(uint32_t*)&Ch[(size_t)(r0 + 8) * N + c0] = hp1;
                *(uint32_t*)&Cl[(size_t)(r0 + 8) * N + c0] = lp1;
            } else {
                C[(size_t)r0 * N + c0]           = v00;
                C[(size_t)r0 * N + c0 + 1]       = v01;
                C[(size_t)(r0 + 8) * N + c0]     = v10;
                C[(size_t)(r0 + 8) * N + c0 + 1] = v11;
            }
        }
    }
}

__global__ __launch_bounds__(256) void gemm_qk(
    const __nv_bfloat16* qh, const __nv_bfloat16* ql,
    const __nv_bfloat16* wqh, const __nv_bfloat16* wql, const float* WQb,
    __nv_bfloat16* QsH, __nv_bfloat16* QsL,
    const __nv_bfloat16* kh, const __nv_bfloat16* kl,
    const __nv_bfloat16* wkh, const __nv_bfloat16* wkl, const float* WKb,
    __nv_bfloat16* KsH, __nv_bfloat16* KsL)
{
    if (blockIdx.z == 0)
        gemm_body(qh, ql, wqh, wql, WQb, nullptr, QsH, QsL, MTOT, DD, DD);
    else
        gemm_body(kh, kl, wkh, wkl, WKb, nullptr, KsH, KsL, MTOT, DD, DD);
}

__global__ __launch_bounds__(256) void gemm_v(
    const __nv_bfloat16* vh, const __nv_bfloat16* vl,
    const __nv_bfloat16* wvh, const __nv_bfloat16* wvl, const float* WVb,
    __nv_bfloat16* VsH, __nv_bfloat16* VsL)
{
    gemm_body(vh, vl, wvh, wvl, WVb, nullptr, VsH, VsL, MTOT, DD, DD);
}

__global__ __launch_bounds__(256) void gemm_o(
    const __nv_bfloat16* ch, const __nv_bfloat16* cl,
    const __nv_bfloat16* woh, const __nv_bfloat16* wol, const float* WOb,
    float* out)
{
    gemm_body(ch, cl, woh, wol, WOb, out, nullptr, nullptr, MTOT, DD, DD);
}

// ---------------- V transpose+pack (once per (b,h,chunk)) ----------------
__global__ __launch_bounds__(256) void vtrans_kernel(
    const __nv_bfloat16* __restrict__ VsH, const __nv_bfloat16* __restrict__ VsL,
    uint32_t* __restrict__ vtH, uint32_t* __restrict__ vtL)
{
    const int vt = blockIdx.x & 7;
    const int h  = (blockIdx.x >> 3) % HH;
    const int b  = blockIdx.x / (8 * HH);
    const int tid = threadIdx.x;
    const size_t obase = ((size_t)(b * HH + h)) * DH * (SS / 2) + vt * 64;

    for (int i = tid; i < 1024; i += 256) {
        int s = i >> 9, r = i & 511;
        int p = r >> 3, dg = r & 7;
        const __nv_bfloat16* src = s ? VsL : VsH;
        uint32_t* dst = s ? vtL : vtH;
        size_t base = ((size_t)(b * SS) + vt * 128 + 2 * p) * DD + h * DH + dg * 8;
        uint4 w0 = *(const uint4*)&src[base];
        uint4 w1 = *(const uint4*)&src[base + DD];
        uint16_t a0[8], a1[8];
        memcpy(a0, &w0, 16);
        memcpy(a1, &w1, 16);
        #pragma unroll
        for (int j = 0; j < 8; j++)
            dst[obase + (size_t)(dg * 8 + j) * (SS / 2) + p] =
                (uint32_t)a0[j] | ((uint32_t)a1[j] << 16);
    }
}

// ---------------- fused relative attention with mma.sync ----------------
// smem byte layout:
//   regionA : [0, 43008)        2 x 21504 -- K chunks (bf16 [128][72]) / V^T (u32 [64][84]) / embK
//   regionQ : [43008, 52224)    qH, qL  (bf16 32x72)
//   regionP : [52224, 73728)    pH, pL (bf16 32x168) / fp32 staging [2][32][64]
//   sW      : [73728, 94208)    fp32 [32][160]
//   sScore  : [94208, 227328)   fp32 [32][1040]
//   sInv    : [227328, 227456)  fp32 [32]
#define KP 72
#define PP 168
#define VP 84
#define WP 160
#define SSTR 1040
#define OFF_A  0
#define ASTRIDE 21504
#define OFF_Q  43008
#define QSTRIDE 4608
#define OFF_P  52224
#define PSTRIDE 10752
#define OFF_W  73728
#define OFF_S  94208
#define OFF_I  227328
#define ASM_BYTES 227456

__global__ __launch_bounds__(512) void attn_mma(
    const __nv_bfloat16* __restrict__ QsH, const __nv_bfloat16* __restrict__ QsL,
    const __nv_bfloat16* __restrict__ KsH, const __nv_bfloat16* __restrict__ KsL,
    const uint32_t* __restrict__ vtH, const uint32_t* __restrict__ vtL,
    const float* __restrict__ embK, const float* __restrict__ embV,
    float* __restrict__ attn_out, float* __restrict__ ctx)
{
    extern __shared__ char smc[];
    __nv_bfloat16* aH = (__nv_bfloat16*)(smc + OFF_A);
    __nv_bfloat16* aL = (__nv_bfloat16*)(smc + OFF_A + ASTRIDE);
    uint32_t* vH = (uint32_t*)(smc + OFF_A);
    uint32_t* vL = (uint32_t*)(smc + OFF_A + ASTRIDE);
    __nv_bfloat16* qH = (__nv_bfloat16*)(smc + OFF_Q);
    __nv_bfloat16* qL = (__nv_bfloat16*)(smc + OFF_Q + QSTRIDE);
    __nv_bfloat16* pH = (__nv_bfloat16*)(smc + OFF_P);
    __nv_bfloat16* pL = (__nv_bfloat16*)(smc + OFF_P + PSTRIDE);
    float* stg  = (float*)(smc + OFF_P);
    float* sW   = (float*)(smc + OFF_W);
    float* sS   = (float*)(smc + OFF_S);
    float* sInv = (float*)(smc + OFF_I);

    const int tid = threadIdx.x;
    const int warp = tid >> 5, lane = tid & 31;
    const int g = lane >> 2, t = lane & 3;
    const int nq = SS / 32;
    const int qt = blockIdx.x % nq;
    const int h  = (blockIdx.x / nq) % HH;
    const int b  = blockIdx.x / (nq * HH);
    const int q0 = qt * 32;
    const int bh = b * HH + h;

    // ---- load Q tile ----
    {
        int i = tid;
        if (i < 512) {
            int s = i >> 8, idx = i & 255;
            int row = idx >> 3, c = (idx & 7) * 8;
            const __nv_bfloat16* src = s ? QsL : QsH;
            __nv_bfloat16* dst = s ? qL : qH;
            *(uint4*)&dst[row * KP + c] =
                *(const uint4*)&src[((size_t)(b * SS) + q0 + row) * DD + h * DH + c];
        }
    }
    // ---- load embK (136 rows x 64, split, pad zero) ----
    for (int i = tid; i < 1088; i += 512) {
        int r = i >> 3, c = (i & 7) * 8;
        float v[8] = {};
        if (r < RR) {
            float4 x = *(const float4*)&embK[(size_t)r * DD + h * DH + c];
            float4 y = *(const float4*)&embK[(size_t)r * DD + h * DH + c + 4];
            v[0]=x.x; v[1]=x.y; v[2]=x.z; v[3]=x.w; v[4]=y.x; v[5]=y.y; v[6]=y.z; v[7]=y.w;
        }
        #pragma unroll
        for (int j = 0; j < 8; j++) {
            __nv_bfloat16 hb = __float2bfloat16(v[j]);
            aH[r * KP + c + j] = hb;
            aL[r * KP + c + j] = __float2bfloat16(v[j] - __bfloat162float(hb));
        }
    }
    __syncthreads();

    // ---- rel table: sW[q][r] = Q . embK_r ----
    for (int nt = warp; nt < 17; nt += 16) {
        float dr[2][4] = {};
        #pragma unroll
        for (int ks = 0; ks < 4; ks++) {
            int kk = ks * 16 + 2 * t;
            int rb = (nt * 8 + g) * KP;
            uint32_t bh2[2] = {*(uint32_t*)&aH[rb + kk], *(uint32_t*)&aH[rb + kk + 8]};
            uint32_t bl2[2] = {*(uint32_t*)&aL[rb + kk], *(uint32_t*)&aL[rb + kk + 8]};
            #pragma unroll
            for (int mi = 0; mi < 2; mi++) {
                int r0 = (mi * 16 + g) * KP, r1 = r0 + 8 * KP;
                uint32_t ah4[4] = {*(uint32_t*)&qH[r0 + kk], *(uint32_t*)&qH[r1 + kk],
                                   *(uint32_t*)&qH[r0 + kk + 8], *(uint32_t*)&qH[r1 + kk + 8]};
                uint32_t al4[4] = {*(uint32_t*)&qL[r0 + kk], *(uint32_t*)&qL[r1 + kk],
                                   *(uint32_t*)&qL[r0 + kk + 8], *(uint32_t*)&qL[r1 + kk + 8]};
                mma16816(dr[mi], ah4, bh2);
                mma16816(dr[mi], ah4, bl2);
                mma16816(dr[mi], al4, bh2);
            }
        }
        #pragma unroll
        for (int mi = 0; mi < 2; mi++) {
            int q = mi * 16 + g;
            int r = nt * 8 + 2 * t;
            if (r < RR)     sW[q * WP + r]           = dr[mi][0];
            if (r + 1 < RR) sW[q * WP + r + 1]       = dr[mi][1];
            if (r < RR)     sW[(q + 8) * WP + r]     = dr[mi][2];
            if (r + 1 < RR) sW[(q + 8) * WP + r + 1] = dr[mi][3];
        }
    }
    __syncthreads();

    // ---- scores: 8 chunks of 128 k-cols ----
    const float scale = 0.125f;
    for (int kt = 0; kt < 8; kt++) {
        for (int i = tid; i < 2048; i += 512) {
            int s = i >> 10, idx = i & 1023;
            int row = idx >> 3, c = (idx & 7) * 8;
            const __nv_bfloat16* src = s ? KsL : KsH;
            __nv_bfloat16* dst = s ? aL : aH;
            *(uint4*)&dst[row * KP + c] =
                *(const uint4*)&src[((size_t)(b * SS) + kt * 128 + row) * DD + h * DH + c];
        }
        __syncthreads();

        float dacc[2][4] = {};
        #pragma unroll
        for (int ks = 0; ks < 4; ks++) {
            int kk = ks * 16 + 2 * t;
            int rb = (warp * 8 + g) * KP;
            uint32_t bh2[2] = {*(uint32_t*)&aH[rb + kk], *(uint32_t*)&aH[rb + kk + 8]};
            uint32_t bl2[2] = {*(uint32_t*)&aL[rb + kk], *(uint32_t*)&aL[rb + kk + 8]};
            #pragma unroll
            for (int mi = 0; mi < 2; mi++) {
                int r0 = (mi * 16 + g) * KP, r1 = r0 + 8 * KP;
                uint32_t ah4[4] = {*(uint32_t*)&qH[r0 + kk], *(uint32_t*)&qH[r1 + kk],
                                   *(uint32_t*)&qH[r0 + kk + 8], *(uint32_t*)&qH[r1 + kk + 8]};
                uint32_t al4[4] = {*(uint32_t*)&qL[r0 + kk], *(uint32_t*)&qL[r1 + kk],
                                   *(uint32_t*)&qL[r0 + kk + 8], *(uint32_t*)&qL[r1 + kk + 8]};
                mma16816(dacc[mi], ah4, bh2);
                mma16816(dacc[mi], ah4, bl2);
                mma16816(dacc[mi], al4, bh2);
            }
        }
        #pragma unroll
        for (int mi = 0; mi < 2; mi++) {
            int q = mi * 16 + g;
            int gk = kt * 128 + warp * 8 + 2 * t;
            #pragma unroll
            for (int rr = 0; rr < 2; rr++) {
                int qq = q + rr * 8;
                int qg = q0 + qq;
                int rel0 = min(max(gk - qg,     -KWIN), KWIN) + KWIN;
                int rel1 = min(max(gk + 1 - qg, -KWIN), KWIN) + KWIN;
                sS[qq * SSTR + gk]     = (dacc[mi][rr * 2]     + sW[qq * WP + rel0]) * scale;
                sS[qq * SSTR + gk + 1] = (dacc[mi][rr * 2 + 1] + sW[qq * WP + rel1]) * scale;
            }
        }
        __syncthreads();
    }

    // ---- softmax (no max pass; scores bounded): e + rowsum ----
    const int qrow = tid >> 4;
    const int s16  = tid & 15;
    {
        float* row = sS + qrow * SSTR;
        float sum = 0.f;
        for (int k = s16; k < SS; k += 16) {
            float e = __expf(row[k]);
            row[k] = e;
            sum += e;
        }
        #pragma unroll
        for (int off = 1; off < 16; off <<= 1)
            sum += __shfl_xor_sync(0xffffffffu, sum, off, 16);
        if (s16 == 0) sInv[qrow] = 1.f / sum;
    }
    __syncthreads();

    // ---- write attn (normalized on the fly) ----
    {
        float* aout = attn_out + ((size_t)bh * SS + q0) * SS;
        for (int i = tid; i < 32 * SS; i += 512) {
            int qq = i >> 10, kk = i & 1023;
            aout[(size_t)qq * SS + kk] = sS[qq * SSTR + kk] * sInv[qq];
        }
    }

    // ---- w buckets from unnormalized e (inv folded at the end) ----
    {
        const int qg = q0 + qrow;
        for (int r = 1 + s16; r <= 127; r += 16) {
            int k = qg - KWIN + r;
            sW[qrow * WP + r] = (k >= 0 && k < SS) ? sS[qrow * SSTR + k] : 0.f;
        }
        float s0 = 0.f, s1 = 0.f;
        for (int k = s16; k < SS; k += 16) {
            float v = sS[qrow * SSTR + k];
            if (k <= qg - KWIN) s0 += v;
            else if (k >= qg + KWIN) s1 += v;
        }
        #pragma unroll
        for (int off = 1; off < 16; off <<= 1) {
            s0 += __shfl_xor_sync(0xffffffffu, s0, off, 16);
            s1 += __shfl_xor_sync(0xffffffffu, s1, off, 16);
        }
        if (s16 == 0) {
            sW[qrow * WP + 0]   = s0;
            sW[qrow * WP + 128] = s1;
        }
        for (int i = tid; i < 32 * 31; i += 512) {
            int q = i / 31, r = 129 + (i % 31);
            sW[q * WP + r] = 0.f;
        }
    }
    __syncthreads();

    // ---- PV: 8 chunks; warp = (d-tile wn, k-half hf) ----
    const int wn = warp >> 1, hf = warp & 1;
    float oacc[2][4] = {};
    for (int vt = 0; vt < 8; vt++) {
        // load packed V^T chunk
        for (int i = tid; i < 2048; i += 512) {
            int s = i >> 10, idx = i & 1023;
            int d = idx >> 4, g4 = (idx & 15) * 4;
            const uint32_t* src = s ? vtL : vtH;
            uint32_t* dst = s ? vL : vH;
            *(uint4*)&dst[d * VP + g4] =
                *(const uint4*)&src[((size_t)bh * DH + d) * (SS / 2) + vt * 64 + g4];
        }
        // convert P chunk (pairs)
        for (int i = tid; i < 2048; i += 512) {
            int q = i >> 6, c2 = (i & 63) * 2;
            float2 v = *(float2*)&sS[q * SSTR + vt * 128 + c2];
            uint32_t hpk, lpk;
            asm("cvt.rn.bf16x2.f32 %0, %1, %2;" : "=r"(hpk) : "f"(v.y), "f"(v.x));
            float h0 = __uint_as_float(hpk << 16);
            float h1 = __uint_as_float(hpk & 0xffff0000u);
            asm("cvt.rn.bf16x2.f32 %0, %1, %2;" : "=r"(lpk) : "f"(v.y - h1), "f"(v.x - h0));
            *(uint32_t*)&pH[q * PP + c2] = hpk;
            *(uint32_t*)&pL[q * PP + c2] = lpk;
        }
        __syncthreads();

        #pragma unroll
        for (int ks = 0; ks < 4; ks++) {
            int kb = hf * 64 + ks * 16 + 2 * t;
            int widx = hf * 32 + ks * 8 + t;
            int vrow = (wn * 8 + g) * VP;
            uint32_t bh2[2] = {vH[vrow + widx], vH[vrow + widx + 4]};
            uint32_t bl2[2] = {vL[vrow + widx], vL[vrow + widx + 4]};
            #pragma unroll
            for (int mi = 0; mi < 2; mi++) {
                int r0 = (mi * 16 + g) * PP, r1 = r0 + 8 * PP;
                uint32_t ah4[4] = {*(uint32_t*)&pH[r0 + kb], *(uint32_t*)&pH[r1 + kb],
                                   *(uint32_t*)&pH[r0 + kb + 8], *(uint32_t*)&pH[r1 + kb + 8]};
                uint32_t al4[4] = {*(uint32_t*)&pL[r0 + kb], *(uint32_t*)&pL[r1 + kb],
                                   *(uint32_t*)&pL[r0 + kb + 8], *(uint32_t*)&pL[r1 + kb + 8]};
                mma16816(oacc[mi], ah4, bh2);
                mma16816(oacc[mi], ah4, bl2);
                mma16816(oacc[mi], al4, bh2);
            }
        }
        __syncthreads();
    }

    // ---- extra chunk: w @ embV_h (160 padded cols) ----
    {
        for (int i = tid; i < 640; i += 512) {
            int p = i >> 3, dg = i & 7;
            int r0 = 2 * p, r1 = 2 * p + 1;
            float v0[8] = {}, v1[8] = {};
            if (r0 < RR) {
                float4 x = *(const float4*)&embV[(size_t)r0 * DD + h * DH + dg * 8];
                float4 y = *(const float4*)&embV[(size_t)r0 * DD + h * DH + dg * 8 + 4];
                v0[0]=x.x; v0[1]=x.y; v0[2]=x.z; v0[3]=x.w; v0[4]=y.x; v0[5]=y.y; v0[6]=y.z; v0[7]=y.w;
            }
            if (r1 < RR) {
                float4 x = *(const float4*)&embV[(size_t)r1 * DD + h * DH + dg * 8];
                float4 y = *(const float4*)&embV[(size_t)r1 * DD + h * DH + dg * 8 + 4];
                v1[0]=x.x; v1[1]=x.y; v1[2]=x.z; v1[3]=x.w; v1[4]=y.x; v1[5]=y.y; v1[6]=y.z; v1[7]=y.w;
            }
            #pragma unroll
            for (int j = 0; j < 8; j++) {
                __nv_bfloat16 h0 = __float2bfloat16(v0[j]);
                __nv_bfloat16 h1 = __float2bfloat16(v1[j]);
                __nv_bfloat16 l0 = __float2bfloat16(v0[j] - __bfloat162float(h0));
                __nv_bfloat16 l1 = __float2bfloat16(v1[j] - __bfloat162float(h1));
                vH[(dg * 8 + j) * VP + p] =
                    (uint32_t)__bfloat16_as_ushort(h0) | ((uint32_t)__bfloat16_as_ushort(h1) << 16);
                vL[(dg * 8 + j) * VP + p] =
                    (uint32_t)__bfloat16_as_ushort(l0) | ((uint32_t)__bfloat16_as_ushort(l1) << 16);
            }
        }
        for (int i = tid; i < 2560; i += 512) {
            int q = i / 80, c2 = (i % 80) * 2;
            float2 v = *(float2*)&sW[q * WP + c2];
            uint32_t hpk, lpk;
            asm("cvt.rn.bf16x2.f32 %0, %1, %2;" : "=r"(hpk) : "f"(v.y), "f"(v.x));
            float h0 = __uint_as_float(hpk << 16);
            float h1 = __uint_as_float(hpk & 0xffff0000u);
            asm("cvt.rn.bf16x2.f32 %0, %1, %2;" : "=r"(lpk) : "f"(v.y - h1), "f"(v.x - h0));
            *(uint32_t*)&pH[q * PP + c2] = hpk;
            *(uint32_t*)&pL[q * PP + c2] = lpk;
        }
        __syncthreads();

        #pragma unroll
        for (int ks = 0; ks < 5; ks++) {
            int kb = hf * 80 + ks * 16 + 2 * t;
            int widx = hf * 40 + ks * 8 + t;
            int vrow = (wn * 8 + g) * VP;
            uint32_t bh2[2] = {vH[vrow + widx], vH[vrow + widx + 4]};
            uint32_t bl2[2] = {vL[vrow + widx], vL[vrow + widx + 4]};
            #pragma unroll
            for (int mi = 0; mi < 2; mi++) {
                int r0 = (mi * 16 + g) * PP, r1 = r0 + 8 * PP;
                uint32_t ah4[4] = {*(uint32_t*)&pH[r0 + kb], *(uint32_t*)&pH[r1 + kb],
                                   *(uint32_t*)&pH[r0 + kb + 8], *(uint32_t*)&pH[r1 + kb + 8]};
                uint32_t al4[4] = {*(uint32_t*)&pL[r0 + kb], *(uint32_t*)&pL[r1 + kb],
                                   *(uint32_t*)&pL[r0 + kb + 8], *(uint32_t*)&pL[r1 + kb + 8]};
                mma16816(oacc[mi], ah4, bh2);
                mma16816(oacc[mi], ah4, bl2);
                mma16816(oacc[mi], al4, bh2);
            }
        }
        __syncthreads();
    }

    // ---- reduce halves, normalize, write ctx ----
    #pragma unroll
    for (int mi = 0; mi < 2; mi++) {
        int q = mi * 16 + g;
        int dc = wn * 8 + 2 * t;
        stg[hf * 2048 + q * 64 + dc]           = oacc[mi][0];
        stg[hf * 2048 + q * 64 + dc + 1]       = oacc[mi][1];
        stg[hf * 2048 + (q + 8) * 64 + dc]     = oacc[mi][2];
        stg[hf * 2048 + (q + 8) * 64 + dc + 1] = oacc[mi][3];
    }
    __syncthreads();
    for (int i = tid; i < 2048; i += 512) {
        int q = i >> 6, dc = i & 63;
        ctx[((size_t)(b * SS) + q0 + q) * DD + h * DH + dc] =
            (stg[i] + stg[2048 + i]) * sInv[q];
    }
}

// ---------------- launch ----------------
extern "C" void kernel_launch(void* const* d_in, const int* in_sizes, int n_in,
                              void* d_out, int out_size)
{
    const float* query = (const float*)d_in[0];
    const float* key   = (const float*)d_in[1];
    const float* value = (const float*)d_in[2];
    const float* WQ_w  = (const float*)d_in[3];
    const float* WQ_b  = (const float*)d_in[4];
    const float* WK_w  = (const float*)d_in[5];
    const float* WK_b  = (const float*)d_in[6];
    const float* WV_w  = (const float*)d_in[7];
    const float* WV_b  = (const float*)d_in[8];
    const float* WO_w  = (const float*)d_in[9];
    const float* WO_b  = (const float*)d_in[10];
    const float* embK  = (const float*)d_in[11];
    const float* embV  = (const float*)d_in[12];

    float* out = (float*)d_out;                       // [B,S,D]
    float* attn = out + (size_t)BB * SS * DD;         // [B,H,S,S]

    static float *Qp = nullptr, *Kp, *Vp, *Ctx;
    static __nv_bfloat16 *qh, *ql, *kh, *kl, *vh, *vl, *ch, *cl;
    static __nv_bfloat16 *wqh, *wql, *wkh, *wkl, *wvh, *wvl, *woh, *wol;
    static uint32_t *vtH, *vtL;
    if (!Qp) {
        cudaGetSymbolAddress((void**)&Qp, g_Qp);
        cudaGetSymbolAddress((void**)&Kp, g_Kp);
        cudaGetSymbolAddress((void**)&Vp, g_Vp);
        cudaGetSymbolAddress((void**)&Ctx, g_Ctx);
        cudaGetSymbolAddress((void**)&qh, g_qh);   cudaGetSymbolAddress((void**)&ql, g_ql);
        cudaGetSymbolAddress((void**)&kh, g_kh);   cudaGetSymbolAddress((void**)&kl, g_kl);
        cudaGetSymbolAddress((void**)&vh, g_vh);   cudaGetSymbolAddress((void**)&vl, g_vl);
        cudaGetSymbolAddress((void**)&ch, g_ch);   cudaGetSymbolAddress((void**)&cl, g_cl);
        cudaGetSymbolAddress((void**)&wqh, g_wqh); cudaGetSymbolAddress((void**)&wql, g_wql);
        cudaGetSymbolAddress((void**)&wkh, g_wkh); cudaGetSymbolAddress((void**)&wkl, g_wkl);
        cudaGetSymbolAddress((void**)&wvh, g_wvh); cudaGetSymbolAddress((void**)&wvl, g_wvl);
        cudaGetSymbolAddress((void**)&woh, g_woh); cudaGetSymbolAddress((void**)&wol, g_wol);
        cudaGetSymbolAddress((void**)&vtH, g_vtH); cudaGetSymbolAddress((void**)&vtL, g_vtL);
        cudaFuncSetAttribute(attn_mma,
                             cudaFuncAttributeMaxDynamicSharedMemorySize, ASM_BYTES);
    }

    __nv_bfloat16* QsH = (__nv_bfloat16*)Qp;  __nv_bfloat16* QsL = QsH + (size_t)MTOT * DD;
    __nv_bfloat16* KsH = (__nv_bfloat16*)Kp;  __nv_bfloat16* KsL = KsH + (size_t)MTOT * DD;
    __nv_bfloat16* VsH = (__nv_bfloat16*)Vp;  __nv_bfloat16* VsL = VsH + (size_t)MTOT * DD;

    const int NIN = MTOT * DD;
    const int NW  = DD * DD;

    // launch 0
    split3_kernel<<<dim3(NIN / 4 / 256, 3), 256>>>(
        query, qh, ql, key, kh, kl, value, vh, vl, NIN);
    // launch 1
    split4_kernel<<<dim3(NW / 4 / 256, 4), 256>>>(
        WQ_w, wqh, wql, WK_w, wkh, wkl, WV_w, wvh, wvl, WO_w, woh, wol, NW);
    // launch 2
    gemm_qk<<<dim3(DD / 128, MTOT / 128, 2), 256>>>(
        qh, ql, wqh, wql, WQ_b, QsH, QsL,
        kh, kl, wkh, wkl, WK_b, KsH, KsL);
    // launch 3
    gemm_v<<<dim3(DD / 128, MTOT / 128), 256>>>(vh, vl, wvh, wvl, WV_b, VsH, VsL);
    // launch 4
    vtrans_kernel<<<BB * HH * 8, 256>>>(VsH, VsL, vtH, vtL);
    // launch 5  (ncu -s 5 profiles this)
    attn_mma<<<BB * HH * (SS / 32), 512, ASM_BYTES>>>(
        QsH, QsL, KsH, KsL, vtH, vtL, embK, embV, attn, Ctx);
    // launch 6
    split_kernel<<<NIN / 4 / 256, 256>>>(Ctx, ch, cl, NIN);
    // launch 7
    gemm_o<<<dim3(DD / 128, MTOT / 128), 256>>>(ch, cl, woh, wol, WO_b, out);
}

// round 8
// speedup vs baseline: 3.0306x; 1.3022x over previous
#include <cuda_runtime.h>
#include <cuda_bf16.h>
#include <cstdint>
#include <cstring>

// Problem constants
#define BB 4
#define SS 1024
#define DD 768
#define HH 12
#define DH 64
#define RR 129          // 2K+1, K=64
#define KWIN 64

#define MTOT (BB * SS)  // 4096

// ---------------- scratch (no allocation allowed) ----------------
__device__ float g_Qp[MTOT * DD];      // reinterpreted: bf16 QsH/QsL
__device__ float g_Kp[MTOT * DD];      // reinterpreted: bf16 KsH/KsL
__device__ float g_Vp[MTOT * DD];      // reinterpreted: bf16 VsH/VsL
__device__ float g_Ctx[MTOT * DD];

__device__ __nv_bfloat16 g_qh[MTOT * DD],  g_ql[MTOT * DD];
__device__ __nv_bfloat16 g_kh[MTOT * DD],  g_kl[MTOT * DD];
__device__ __nv_bfloat16 g_vh[MTOT * DD],  g_vl[MTOT * DD];
__device__ __nv_bfloat16 g_ch[MTOT * DD],  g_cl[MTOT * DD];
__device__ __nv_bfloat16 g_wqh[DD * DD], g_wql[DD * DD];
__device__ __nv_bfloat16 g_wkh[DD * DD], g_wkl[DD * DD];
__device__ __nv_bfloat16 g_wvh[DD * DD], g_wvl[DD * DD];
__device__ __nv_bfloat16 g_woh[DD * DD], g_wol[DD * DD];

// packed V^T: [b*HH+h][d(64)][pair(512)]
__device__ uint32_t g_vtH[BB * HH * DH * (SS / 2)];
__device__ uint32_t g_vtL[BB * HH * DH * (SS / 2)];

// ---------------- cp.async helpers ----------------
__device__ __forceinline__ uint32_t smem_u32(const void* p) {
    uint32_t a;
    asm("{ .reg .u64 t; cvta.to.shared.u64 t, %1; cvt.u32.u64 %0, t; }"
        : "=r"(a) : "l"(p));
    return a;
}
#define CP_ASYNC16(sa, ga) \
    asm volatile("cp.async.cg.shared.global [%0], [%1], 16;" :: "r"(sa), "l"(ga))
#define CP_COMMIT() asm volatile("cp.async.commit_group;" ::: "memory")
#define CP_WAIT1()  asm volatile("cp.async.wait_group 1;" ::: "memory")
#define CP_WAIT0()  asm volatile("cp.async.wait_group 0;" ::: "memory")

// ---------------- fp32 -> bf16 hi/lo split ----------------
__device__ __forceinline__ void split4(const float* __restrict__ x,
                                       __nv_bfloat16* __restrict__ hi,
                                       __nv_bfloat16* __restrict__ lo, int i)
{
    float4 v = *(const float4*)&x[i];
    float vv[4] = {v.x, v.y, v.z, v.w};
    uint16_t h[4], l[4];
    #pragma unroll
    for (int p = 0; p < 4; p++) {
        __nv_bfloat16 hb = __float2bfloat16(vv[p]);
        __nv_bfloat16 lb = __float2bfloat16(vv[p] - __bfloat162float(hb));
        h[p] = __bfloat16_as_ushort(hb);
        l[p] = __bfloat16_as_ushort(lb);
    }
    *(uint2*)&hi[i] = make_uint2(((uint32_t)h[1] << 16) | h[0], ((uint32_t)h[3] << 16) | h[2]);
    *(uint2*)&lo[i] = make_uint2(((uint32_t)l[1] << 16) | l[0], ((uint32_t)l[3] << 16) | l[2]);
}

__global__ __launch_bounds__(256) void split_kernel(
    const float* __restrict__ x, __nv_bfloat16* __restrict__ hi,
    __nv_bfloat16* __restrict__ lo, int n)
{
    int i = (blockIdx.x * 256 + threadIdx.x) * 4;
    if (i < n) split4(x, hi, lo, i);
}

__global__ __launch_bounds__(256) void split3_kernel(
    const float* __restrict__ a, __nv_bfloat16* ah, __nv_bfloat16* al,
    const float* __restrict__ b, __nv_bfloat16* bh, __nv_bfloat16* bl,
    const float* __restrict__ c, __nv_bfloat16* ch, __nv_bfloat16* cl, int n)
{
    int i = (blockIdx.x * 256 + threadIdx.x) * 4;
    if (i >= n) return;
    const float* x; __nv_bfloat16 *hi, *lo;
    if (blockIdx.y == 0)      { x = a; hi = ah; lo = al; }
    else if (blockIdx.y == 1) { x = b; hi = bh; lo = bl; }
    else                      { x = c; hi = ch; lo = cl; }
    split4(x, hi, lo, i);
}

__global__ __launch_bounds__(256) void split4_kernel(
    const float* __restrict__ a, __nv_bfloat16* ah, __nv_bfloat16* al,
    const float* __restrict__ b, __nv_bfloat16* bh, __nv_bfloat16* bl,
    const float* __restrict__ c, __nv_bfloat16* ch, __nv_bfloat16* cl,
    const float* __restrict__ d, __nv_bfloat16* dh, __nv_bfloat16* dl, int n)
{
    int i = (blockIdx.x * 256 + threadIdx.x) * 4;
    if (i >= n) return;
    const float* x; __nv_bfloat16 *hi, *lo;
    if (blockIdx.y == 0)      { x = a; hi = ah; lo = al; }
    else if (blockIdx.y == 1) { x = b; hi = bh; lo = bl; }
    else if (blockIdx.y == 2) { x = c; hi = ch; lo = cl; }
    else                      { x = d; hi = dh; lo = dl; }
    split4(x, hi, lo, i);
}

// ---------------- mma.sync helper ----------------
__device__ __forceinline__ void mma16816(float* d, const uint32_t* a, const uint32_t* b) {
    asm volatile("mma.sync.aligned.m16n8k16.row.col.f32.bf16.bf16.f32 "
        "{%0,%1,%2,%3}, {%4,%5,%6,%7}, {%8,%9}, {%0,%1,%2,%3};"
        : "+f"(d[0]), "+f"(d[1]), "+f"(d[2]), "+f"(d[3])
        : "r"(a[0]), "r"(a[1]), "r"(a[2]), "r"(a[3]), "r"(b[0]), "r"(b[1]));
}

// ---------------- bf16-split GEMM, cp.async double-buffered ----------------
#define SP 40
#define GARR 10240          // bytes per smem array (128*SP*2)
#define GBUF (4 * GARR)     // 40960 per stage
#define GSMB (2 * GBUF)     // 81920 total

__device__ __forceinline__ void gemm_issue(
    uint32_t sb, int buf, int tid, int bm, int bn, int k0, int Kd,
    const __nv_bfloat16* __restrict__ Ah, const __nv_bfloat16* __restrict__ Al,
    const __nv_bfloat16* __restrict__ Wh, const __nv_bfloat16* __restrict__ Wl)
{
    uint32_t bo = sb + buf * GBUF;
    #pragma unroll
    for (int it = 0; it < 2; it++) {
        int i = tid + it * 256;
        int row = i >> 2, cc = (i & 3) * 8;
        size_t ga = (size_t)(bm + row) * Kd + k0 + cc;
        size_t gw = (size_t)(bn + row) * Kd + k0 + cc;
        uint32_t so = (uint32_t)(row * SP + cc) * 2;
        CP_ASYNC16(bo + so,            Ah + ga);
        CP_ASYNC16(bo + GARR + so,     Al + ga);
        CP_ASYNC16(bo + 2 * GARR + so, Wh + gw);
        CP_ASYNC16(bo + 3 * GARR + so, Wl + gw);
    }
    CP_COMMIT();
}

__device__ __forceinline__ void gemm_body(
    const __nv_bfloat16* __restrict__ Ah, const __nv_bfloat16* __restrict__ Al,
    const __nv_bfloat16* __restrict__ Wh, const __nv_bfloat16* __restrict__ Wl,
    const float* __restrict__ bias, float* __restrict__ C,
    __nv_bfloat16* __restrict__ Ch, __nv_bfloat16* __restrict__ Cl,
    int M, int N, int Kd)
{
    extern __shared__ char gsm[];
    uint32_t sb = smem_u32(gsm);

    const int tid = threadIdx.x;
    const int bm = blockIdx.y * 128, bn = blockIdx.x * 128;
    const int warp = tid >> 5, lane = tid & 31;
    const int wm = warp & 1, wn = warp >> 1;
    const int g = lane >> 2, t = lane & 3;

    float d[4][4][4] = {};

    const int nch = Kd / 32;
    gemm_issue(sb, 0, tid, bm, bn, 0, Kd, Ah, Al, Wh, Wl);

    for (int c = 0; c < nch; c++) {
        if (c + 1 < nch) {
            gemm_issue(sb, (c + 1) & 1, tid, bm, bn, (c + 1) * 32, Kd, Ah, Al, Wh, Wl);
            CP_WAIT1();
        } else {
            CP_WAIT0();
        }
        __syncthreads();

        const __nv_bfloat16* sAh = (const __nv_bfloat16*)(gsm + (c & 1) * GBUF);
        const __nv_bfloat16* sAl = (const __nv_bfloat16*)(gsm + (c & 1) * GBUF + GARR);
        const __nv_bfloat16* sWh = (const __nv_bfloat16*)(gsm + (c & 1) * GBUF + 2 * GARR);
        const __nv_bfloat16* sWl = (const __nv_bfloat16*)(gsm + (c & 1) * GBUF + 3 * GARR);

        #pragma unroll
        for (int ks = 0; ks < 2; ks++) {
            const int kk = ks * 16 + 2 * t;
            uint32_t bh[4][2], bl[4][2];
            #pragma unroll
            for (int ni = 0; ni < 4; ni++) {
                int rb = (wn * 32 + ni * 8 + g) * SP;
                bh[ni][0] = *(const uint32_t*)&sWh[rb + kk];
                bh[ni][1] = *(const uint32_t*)&sWh[rb + kk + 8];
                bl[ni][0] = *(const uint32_t*)&sWl[rb + kk];
                bl[ni][1] = *(const uint32_t*)&sWl[rb + kk + 8];
            }
            #pragma unroll
            for (int mi = 0; mi < 4; mi++) {
                int r0 = (wm * 64 + mi * 16 + g) * SP;
                int r1 = (wm * 64 + mi * 16 + 8 + g) * SP;
                uint32_t ah[4], al[4];
                ah[0] = *(const uint32_t*)&sAh[r0 + kk];
                ah[1] = *(const uint32_t*)&sAh[r1 + kk];
                ah[2] = *(const uint32_t*)&sAh[r0 + kk + 8];
                ah[3] = *(const uint32_t*)&sAh[r1 + kk + 8];
                al[0] = *(const uint32_t*)&sAl[r0 + kk];
                al[1] = *(const uint32_t*)&sAl[r1 + kk];
                al[2] = *(const uint32_t*)&sAl[r0 + kk + 8];
                al[3] = *(const uint32_t*)&sAl[r1 + kk + 8];
                #pragma unroll
                for (int ni = 0; ni < 4; ni++) {
                    mma16816(d[mi][ni], ah, bh[ni]);
                    mma16816(d[mi][ni], ah, bl[ni]);
                    mma16816(d[mi][ni], al, bh[ni]);
                }
            }
        }
        __syncthreads();
    }

    #pragma unroll
    for (int mi = 0; mi < 4; mi++) {
        int r0 = bm + wm * 64 + mi * 16 + g;
        #pragma unroll
        for (int ni = 0; ni < 4; ni++) {
            int c0 = bn + wn * 32 + ni * 8 + 2 * t;
            float b0 = bias[c0], b1 = bias[c0 + 1];
            float v00 = d[mi][ni][0] + b0, v01 = d[mi][ni][1] + b1;
            float v10 = d[mi][ni][2] + b0, v11 = d[mi][ni][3] + b1;
            if (Ch) {
                uint32_t hp0, lp0, hp1, lp1;
                asm("cvt.rn.bf16x2.f32 %0, %1, %2;" : "=r"(hp0) : "f"(v01), "f"(v00));
                asm("cvt.rn.bf16x2.f32 %0, %1, %2;" : "=r"(hp1) : "f"(v11), "f"(v10));
                float h00 = __uint_as_float(hp0 << 16);
                float h01 = __uint_as_float(hp0 & 0xffff0000u);
                float h10 = __uint_as_float(hp1 << 16);
                float h11 = __uint_as_float(hp1 & 0xffff0000u);
                asm("cvt.rn.bf16x2.f32 %0, %1, %2;" : "=r"(lp0) : "f"(v01 - h01), "f"(v00 - h00));
                asm("cvt.rn.bf16x2.f32 %0, %1, %2;" : "=r"(lp1) : "f"(v11 - h11), "f"(v10 - h10));
                *(uint32_t*)&Ch[(size_t)r0 * N + c0]       = hp0;
                *(uint32_t*)&Cl[(size_t)r0 * N + c0]       = lp0;
                *(uint32_t*)&Ch[(size_t)(r0 + 8) * N + c0] = hp1;
                *(uint32_t*)&Cl[(size_t)(r0 + 8) * N + c0] = lp1;
            } else {
                C[(size_t)r0 * N + c0]           = v00;
                C[(size_t)r0 * N + c0 + 1]       = v01;
                C[(size_t)(r0 + 8) * N + c0]     = v10;
                C[(size_t)(r0 + 8) * N + c0 + 1] = v11;
            }
        }
    }
}

__global__ __launch_bounds__(256, 2) void gemm_qk(
    const __nv_bfloat16* qh, const __nv_bfloat16* ql,
    const __nv_bfloat16* wqh, const __nv_bfloat16* wql, const float* WQb,
    __nv_bfloat16* QsH, __nv_bfloat16* QsL,
    const __nv_bfloat16* kh, const __nv_bfloat16* kl,
    const __nv_bfloat16* wkh, const __nv_bfloat16* wkl, const float* WKb,
    __nv_bfloat16* KsH, __nv_bfloat16* KsL)
{
    if (blockIdx.z == 0)
        gemm_body(qh, ql, wqh, wql, WQb, nullptr, QsH, QsL, MTOT, DD, DD);
    else
        gemm_body(kh, kl, wkh, wkl, WKb, nullptr, KsH, KsL, MTOT, DD, DD);
}

__global__ __launch_bounds__(256, 2) void gemm_v(
    const __nv_bfloat16* vh, const __nv_bfloat16* vl,
    const __nv_bfloat16* wvh, const __nv_bfloat16* wvl, const float* WVb,
    __nv_bfloat16* VsH, __nv_bfloat16* VsL)
{
    gemm_body(vh, vl, wvh, wvl, WVb, nullptr, VsH, VsL, MTOT, DD, DD);
}

__global__ __launch_bounds__(256, 2) void gemm_o(
    const __nv_bfloat16* ch, const __nv_bfloat16* cl,
    const __nv_bfloat16* woh, const __nv_bfloat16* wol, const float* WOb,
    float* out)
{
    gemm_body(ch, cl, woh, wol, WOb, out, nullptr, nullptr, MTOT, DD, DD);
}

// ---------------- V transpose+pack ----------------
__global__ __launch_bounds__(256) void vtrans_kernel(
    const __nv_bfloat16* __restrict__ VsH, const __nv_bfloat16* __restrict__ VsL,
    uint32_t* __restrict__ vtH, uint32_t* __restrict__ vtL)
{
    const int vt = blockIdx.x & 7;
    const int h  = (blockIdx.x >> 3) % HH;
    const int b  = blockIdx.x / (8 * HH);
    const int tid = threadIdx.x;
    const size_t obase = ((size_t)(b * HH + h)) * DH * (SS / 2) + vt * 64;

    for (int i = tid; i < 1024; i += 256) {
        int s = i >> 9, r = i & 511;
        int p = r >> 3, dg = r & 7;
        const __nv_bfloat16* src = s ? VsL : VsH;
        uint32_t* dst = s ? vtL : vtH;
        size_t base = ((size_t)(b * SS) + vt * 128 + 2 * p) * DD + h * DH + dg * 8;
        uint4 w0 = *(const uint4*)&src[base];
        uint4 w1 = *(const uint4*)&src[base + DD];
        uint16_t a0[8], a1[8];
        memcpy(a0, &w0, 16);
        memcpy(a1, &w1, 16);
        #pragma unroll
        for (int j = 0; j < 8; j++)
            dst[obase + (size_t)(dg * 8 + j) * (SS / 2) + p] =
                (uint32_t)a0[j] | ((uint32_t)a1[j] << 16);
    }
}

// ---------------- fused relative attention with mma.sync ----------------
#define KP 72
#define PP 168
#define VP 84
#define WP 160
#define SSTR 1040
#define OFF_A  0
#define ASTRIDE 21504
#define OFF_Q  43008
#define QSTRIDE 4608
#define OFF_P  52224
#define PSTRIDE 10752
#define OFF_W  73728
#define OFF_S  94208
#define OFF_I  227328
#define ASM_BYTES 227456

__global__ __launch_bounds__(512) void attn_mma(
    const __nv_bfloat16* __restrict__ QsH, const __nv_bfloat16* __restrict__ QsL,
    const __nv_bfloat16* __restrict__ KsH, const __nv_bfloat16* __restrict__ KsL,
    const uint32_t* __restrict__ vtH, const uint32_t* __restrict__ vtL,
    const float* __restrict__ embK, const float* __restrict__ embV,
    float* __restrict__ attn_out, float* __restrict__ ctx)
{
    extern __shared__ char smc[];
    __nv_bfloat16* aH = (__nv_bfloat16*)(smc + OFF_A);
    __nv_bfloat16* aL = (__nv_bfloat16*)(smc + OFF_A + ASTRIDE);
    uint32_t* vH = (uint32_t*)(smc + OFF_A);
    uint32_t* vL = (uint32_t*)(smc + OFF_A + ASTRIDE);
    __nv_bfloat16* qH = (__nv_bfloat16*)(smc + OFF_Q);
    __nv_bfloat16* qL = (__nv_bfloat16*)(smc + OFF_Q + QSTRIDE);
    __nv_bfloat16* pH = (__nv_bfloat16*)(smc + OFF_P);
    __nv_bfloat16* pL = (__nv_bfloat16*)(smc + OFF_P + PSTRIDE);
    float* stg  = (float*)(smc + OFF_P);
    float* sW   = (float*)(smc + OFF_W);
    float* sS   = (float*)(smc + OFF_S);
    float* sInv = (float*)(smc + OFF_I);

    const int tid = threadIdx.x;
    const int warp = tid >> 5, lane = tid & 31;
    const int g = lane >> 2, t = lane & 3;
    const int nq = SS / 32;
    const int qt = blockIdx.x % nq;
    const int h  = (blockIdx.x / nq) % HH;
    const int b  = blockIdx.x / (nq * HH);
    const int q0 = qt * 32;
    const int bh = b * HH + h;

    // ---- load Q tile ----
    {
        int i = tid;
        if (i < 512) {
            int s = i >> 8, idx = i & 255;
            int row = idx >> 3, c = (idx & 7) * 8;
            const __nv_bfloat16* src = s ? QsL : QsH;
            __nv_bfloat16* dst = s ? qL : qH;
            *(uint4*)&dst[row * KP + c] =
                *(const uint4*)&src[((size_t)(b * SS) + q0 + row) * DD + h * DH + c];
        }
    }
    // ---- load embK ----
    for (int i = tid; i < 1088; i += 512) {
        int r = i >> 3, c = (i & 7) * 8;
        float v[8] = {};
        if (r < RR) {
            float4 x = *(const float4*)&embK[(size_t)r * DD + h * DH + c];
            float4 y = *(const float4*)&embK[(size_t)r * DD + h * DH + c + 4];
            v[0]=x.x; v[1]=x.y; v[2]=x.z; v[3]=x.w; v[4]=y.x; v[5]=y.y; v[6]=y.z; v[7]=y.w;
        }
        #pragma unroll
        for (int j = 0; j < 8; j++) {
            __nv_bfloat16 hb = __float2bfloat16(v[j]);
            aH[r * KP + c + j] = hb;
            aL[r * KP + c + j] = __float2bfloat16(v[j] - __bfloat162float(hb));
        }
    }
    __syncthreads();

    // prefetch K chunk 0 into regs (overlaps rel-table MMAs)
    uint4 kreg[4];
    #pragma unroll
    for (int it = 0; it < 4; it++) {
        int i = tid + it * 512;
        int s = i >> 10, idx = i & 1023;
        int row = idx >> 3, c = (idx & 7) * 8;
        const __nv_bfloat16* src = s ? KsL : KsH;
        kreg[it] = *(const uint4*)&src[((size_t)(b * SS) + row) * DD + h * DH + c];
    }

    // ---- rel table: sW[q][r] = Q . embK_r ----
    for (int nt = warp; nt < 17; nt += 16) {
        float dr[2][4] = {};
        #pragma unroll
        for (int ks = 0; ks < 4; ks++) {
            int kk = ks * 16 + 2 * t;
            int rb = (nt * 8 + g) * KP;
            uint32_t bh2[2] = {*(uint32_t*)&aH[rb + kk], *(uint32_t*)&aH[rb + kk + 8]};
            uint32_t bl2[2] = {*(uint32_t*)&aL[rb + kk], *(uint32_t*)&aL[rb + kk + 8]};
            #pragma unroll
            for (int mi = 0; mi < 2; mi++) {
                int r0 = (mi * 16 + g) * KP, r1 = r0 + 8 * KP;
                uint32_t ah4[4] = {*(uint32_t*)&qH[r0 + kk], *(uint32_t*)&qH[r1 + kk],
                                   *(uint32_t*)&qH[r0 + kk + 8], *(uint32_t*)&qH[r1 + kk + 8]};
                uint32_t al4[4] = {*(uint32_t*)&qL[r0 + kk], *(uint32_t*)&qL[r1 + kk],
                                   *(uint32_t*)&qL[r0 + kk + 8], *(uint32_t*)&qL[r1 + kk + 8]};
                mma16816(dr[mi], ah4, bh2);
                mma16816(dr[mi], ah4, bl2);
                mma16816(dr[mi], al4, bh2);
            }
        }
        #pragma unroll
        for (int mi = 0; mi < 2; mi++) {
            int q = mi * 16 + g;
            int r = nt * 8 + 2 * t;
            if (r < RR)     sW[q * WP + r]           = dr[mi][0];
            if (r + 1 < RR) sW[q * WP + r + 1]       = dr[mi][1];
            if (r < RR)     sW[(q + 8) * WP + r]     = dr[mi][2];
            if (r + 1 < RR) sW[(q + 8) * WP + r + 1] = dr[mi][3];
        }
    }
    __syncthreads();

    // ---- scores: 8 chunks, reg-prefetch pipelined ----
    const float scale = 0.125f;
    for (int kt = 0; kt < 8; kt++) {
        // store prefetched chunk
        #pragma unroll
        for (int it = 0; it < 4; it++) {
            int i = tid + it * 512;
            int s = i >> 10, idx = i & 1023;
            int row = idx >> 3, c = (idx & 7) * 8;
            __nv_bfloat16* dst = s ? aL : aH;
            *(uint4*)&dst[row * KP + c] = kreg[it];
        }
        __syncthreads();
        // prefetch next chunk (overlaps MMAs below)
        if (kt < 7) {
            #pragma unroll
            for (int it = 0; it < 4; it++) {
                int i = tid + it * 512;
                int s = i >> 10, idx = i & 1023;
                int row = idx >> 3, c = (idx & 7) * 8;
                const __nv_bfloat16* src = s ? KsL : KsH;
                kreg[it] = *(const uint4*)&src[((size_t)(b * SS) + (kt + 1) * 128 + row) * DD + h * DH + c];
            }
        }

        float dacc[2][4] = {};
        #pragma unroll
        for (int ks = 0; ks < 4; ks++) {
            int kk = ks * 16 + 2 * t;
            int rb = (warp * 8 + g) * KP;
            uint32_t bh2[2] = {*(uint32_t*)&aH[rb + kk], *(uint32_t*)&aH[rb + kk + 8]};
            uint32_t bl2[2] = {*(uint32_t*)&aL[rb + kk], *(uint32_t*)&aL[rb + kk + 8]};
            #pragma unroll
            for (int mi = 0; mi < 2; mi++) {
                int r0 = (mi * 16 + g) * KP, r1 = r0 + 8 * KP;
                uint32_t ah4[4] = {*(uint32_t*)&qH[r0 + kk], *(uint32_t*)&qH[r1 + kk],
                                   *(uint32_t*)&qH[r0 + kk + 8], *(uint32_t*)&qH[r1 + kk + 8]};
                uint32_t al4[4] = {*(uint32_t*)&qL[r0 + kk], *(uint32_t*)&qL[r1 + kk],
                                   *(uint32_t*)&qL[r0 + kk + 8], *(uint32_t*)&qL[r1 + kk + 8]};
                mma16816(dacc[mi], ah4, bh2);
                mma16816(dacc[mi], ah4, bl2);
                mma16816(dacc[mi], al4, bh2);
            }
        }
        #pragma unroll
        for (int mi = 0; mi < 2; mi++) {
            int q = mi * 16 + g;
            int gk = kt * 128 + warp * 8 + 2 * t;
            #pragma unroll
            for (int rr = 0; rr < 2; rr++) {
                int qq = q + rr * 8;
                int qg = q0 + qq;
                int rel0 = min(max(gk - qg,     -KWIN), KWIN) + KWIN;
                int rel1 = min(max(gk + 1 - qg, -KWIN), KWIN) + KWIN;
                sS[qq * SSTR + gk]     = (dacc[mi][rr * 2]     + sW[qq * WP + rel0]) * scale;
                sS[qq * SSTR + gk + 1] = (dacc[mi][rr * 2 + 1] + sW[qq * WP + rel1]) * scale;
            }
        }
        __syncthreads();
    }

    // prefetch V chunk 0 (overlaps softmax)
    uint4 vreg[4];
    #pragma unroll
    for (int it = 0; it < 4; it++) {
        int i = tid + it * 512;
        int s = i >> 10, idx = i & 1023;
        int d = idx >> 4, g4 = (idx & 15) * 4;
        const uint32_t* src = s ? vtL : vtH;
        vreg[it] = *(const uint4*)&src[((size_t)bh * DH + d) * (SS / 2) + g4];
    }

    // ---- softmax (no max pass): exp + rowsum, vectorized ----
    const int qrow = tid >> 4;
    const int s16  = tid & 15;
    {
        float* row = sS + qrow * SSTR;
        float sum = 0.f;
        for (int k4 = s16 * 4; k4 < SS; k4 += 64) {
            float4 e = *(float4*)&row[k4];
            e.x = __expf(e.x); e.y = __expf(e.y);
            e.z = __expf(e.z); e.w = __expf(e.w);
            *(float4*)&row[k4] = e;
            sum += e.x + e.y + e.z + e.w;
        }
        #pragma unroll
        for (int off = 1; off < 16; off <<= 1)
            sum += __shfl_xor_sync(0xffffffffu, sum, off, 16);
        if (s16 == 0) sInv[qrow] = 1.f / sum;
    }
    __syncthreads();

    // ---- write attn (normalized, float4) ----
    {
        float* aout = attn_out + ((size_t)bh * SS + q0) * SS;
        for (int i = tid; i < 8192; i += 512) {
            int qq = i >> 8, k4 = (i & 255) * 4;
            float4 v = *(float4*)&sS[qq * SSTR + k4];
            float s = sInv[qq];
            v.x *= s; v.y *= s; v.z *= s; v.w *= s;
            *(float4*)&aout[(size_t)qq * SS + k4] = v;
        }
    }

    // ---- w buckets (unnormalized) ----
    {
        const int qg = q0 + qrow;
        for (int r = 1 + s16; r <= 127; r += 16) {
            int k = qg - KWIN + r;
            sW[qrow * WP + r] = (k >= 0 && k < SS) ? sS[qrow * SSTR + k] : 0.f;
        }
        float s0 = 0.f, s1 = 0.f;
        for (int k = s16; k < SS; k += 16) {
            float v = sS[qrow * SSTR + k];
            if (k <= qg - KWIN) s0 += v;
            else if (k >= qg + KWIN) s1 += v;
        }
        #pragma unroll
        for (int off = 1; off < 16; off <<= 1) {
            s0 += __shfl_xor_sync(0xffffffffu, s0, off, 16);
            s1 += __shfl_xor_sync(0xffffffffu, s1, off, 16);
        }
        if (s16 == 0) {
            sW[qrow * WP + 0]   = s0;
            sW[qrow * WP + 128] = s1;
        }
        for (int i = tid; i < 32 * 31; i += 512) {
            int q = i / 31, r = 129 + (i % 31);
            sW[q * WP + r] = 0.f;
        }
    }
    __syncthreads();

    // ---- PV: 8 chunks, reg-prefetch pipelined ----
    const int wn = warp >> 1, hf = warp & 1;
    float oacc[2][4] = {};
    for (int vt = 0; vt < 8; vt++) {
        // store prefetched V chunk
        #pragma unroll
        for (int it = 0; it < 4; it++) {
            int i = tid + it * 512;
            int s = i >> 10, idx = i & 1023;
            int d = idx >> 4, g4 = (idx & 15) * 4;
            uint32_t* dst = s ? vL : vH;
            *(uint4*)&dst[d * VP + g4] = vreg[it];
        }
        // convert P chunk (pairs)
        for (int i = tid; i < 2048; i += 512) {
            int q = i >> 6, c2 = (i & 63) * 2;
            float2 v = *(float2*)&sS[q * SSTR + vt * 128 + c2];
            uint32_t hpk, lpk;
            asm("cvt.rn.bf16x2.f32 %0, %1, %2;" : "=r"(hpk) : "f"(v.y), "f"(v.x));
            float h0 = __uint_as_float(hpk << 16);
            float h1 = __uint_as_float(hpk & 0xffff0000u);
            asm("cvt.rn.bf16x2.f32 %0, %1, %2;" : "=r"(lpk) : "f"(v.y - h1), "f"(v.x - h0));
            *(uint32_t*)&pH[q * PP + c2] = hpk;
            *(uint32_t*)&pL[q * PP + c2] = lpk;
        }
        __syncthreads();
        // prefetch next V chunk (overlaps MMAs)
        if (vt < 7) {
            #pragma unroll
            for (int it = 0; it < 4; it++) {
                int i = tid + it * 512;
                int s = i >> 10, idx = i & 1023;
                int d = idx >> 4, g4 = (idx & 15) * 4;
                const uint32_t* src = s ? vtL : vtH;
                vreg[it] = *(const uint4*)&src[((size_t)bh * DH + d) * (SS / 2) + (vt + 1) * 64 + g4];
            }
        }

        #pragma unroll
        for (int ks = 0; ks < 4; ks++) {
            int kb = hf * 64 + ks * 16 + 2 * t;
            int widx = hf * 32 + ks * 8 + t;
            int vrow = (wn * 8 + g) * VP;
            uint32_t bh2[2] = {vH[vrow + widx], vH[vrow + widx + 4]};
            uint32_t bl2[2] = {vL[vrow + widx], vL[vrow + widx + 4]};
            #pragma unroll
            for (int mi = 0; mi < 2; mi++) {
                int r0 = (mi * 16 + g) * PP, r1 = r0 + 8 * PP;
                uint32_t ah4[4] = {*(uint32_t*)&pH[r0 + kb], *(uint32_t*)&pH[r1 + kb],
                                   *(uint32_t*)&pH[r0 + kb + 8], *(uint32_t*)&pH[r1 + kb + 8]};
                uint32_t al4[4] = {*(uint32_t*)&pL[r0 + kb], *(uint32_t*)&pL[r1 + kb],
                                   *(uint32_t*)&pL[r0 + kb + 8], *(uint32_t*)&pL[r1 + kb + 8]};
                mma16816(oacc[mi], ah4, bh2);
                mma16816(oacc[mi], ah4, bl2);
                mma16816(oacc[mi], al4, bh2);
            }
        }
        __syncthreads();
    }

    // ---- extra chunk: w @ embV_h ----
    {
        for (int i = tid; i < 640; i += 512) {
            int p = i >> 3, dg = i & 7;
            int r0 = 2 * p, r1 = 2 * p + 1;
            float v0[8] = {}, v1[8] = {};
            if (r0 < RR) {
                float4 x = *(const float4*)&embV[(size_t)r0 * DD + h * DH + dg * 8];
                float4 y = *(const float4*)&embV[(size_t)r0 * DD + h * DH + dg * 8 + 4];
                v0[0]=x.x; v0[1]=x.y; v0[2]=x.z; v0[3]=x.w; v0[4]=y.x; v0[5]=y.y; v0[6]=y.z; v0[7]=y.w;
            }
            if (r1 < RR) {
                float4 x = *(const float4*)&embV[(size_t)r1 * DD + h * DH + dg * 8];
                float4 y = *(const float4*)&embV[(size_t)r1 * DD + h * DH + dg * 8 + 4];
                v1[0]=x.x; v1[1]=x.y; v1[2]=x.z; v1[3]=x.w; v1[4]=y.x; v1[5]=y.y; v1[6]=y.z; v1[7]=y.w;
            }
            #pragma unroll
            for (int j = 0; j < 8; j++) {
                __nv_bfloat16 h0 = __float2bfloat16(v0[j]);
                __nv_bfloat16 h1 = __float2bfloat16(v1[j]);
                __nv_bfloat16 l0 = __float2bfloat16(v0[j] - __bfloat162float(h0));
                __nv_bfloat16 l1 = __float2bfloat16(v1[j] - __bfloat162float(h1));
                vH[(dg * 8 + j) * VP + p] =
                    (uint32_t)__bfloat16_as_ushort(h0) | ((uint32_t)__bfloat16_as_ushort(h1) << 16);
                vL[(dg * 8 + j) * VP + p] =
                    (uint32_t)__bfloat16_as_ushort(l0) | ((uint32_t)__bfloat16_as_ushort(l1) << 16);
            }
        }
        for (int i = tid; i < 2560; i += 512) {
            int q = i / 80, c2 = (i % 80) * 2;
            float2 v = *(float2*)&sW[q * WP + c2];
            uint32_t hpk, lpk;
            asm("cvt.rn.bf16x2.f32 %0, %1, %2;" : "=r"(hpk) : "f"(v.y), "f"(v.x));
            float h0 = __uint_as_float(hpk << 16);
            float h1 = __uint_as_float(hpk & 0xffff0000u);
            asm("cvt.rn.bf16x2.f32 %0, %1, %2;" : "=r"(lpk) : "f"(v.y - h1), "f"(v.x - h0));
            *(uint32_t*)&pH[q * PP + c2] = hpk;
            *(uint32_t*)&pL[q * PP + c2] = lpk;
        }
        __syncthreads();

        #pragma unroll
        for (int ks = 0; ks < 5; ks++) {
            int kb = hf * 80 + ks * 16 + 2 * t;
            int widx = hf * 40 + ks * 8 + t;
            int vrow = (wn * 8 + g) * VP;
            uint32_t bh2[2] = {vH[vrow + widx], vH[vrow + widx + 4]};
            uint32_t bl2[2] = {vL[vrow + widx], vL[vrow + widx + 4]};
            #pragma unroll
            for (int mi = 0; mi < 2; mi++) {
                int r0 = (mi * 16 + g) * PP, r1 = r0 + 8 * PP;
                uint32_t ah4[4] = {*(uint32_t*)&pH[r0 + kb], *(uint32_t*)&pH[r1 + kb],
                                   *(uint32_t*)&pH[r0 + kb + 8], *(uint32_t*)&pH[r1 + kb + 8]};
                uint32_t al4[4] = {*(uint32_t*)&pL[r0 + kb], *(uint32_t*)&pL[r1 + kb],
                                   *(uint32_t*)&pL[r0 + kb + 8], *(uint32_t*)&pL[r1 + kb + 8]};
                mma16816(oacc[mi], ah4, bh2);
                mma16816(oacc[mi], ah4, bl2);
                mma16816(oacc[mi], al4, bh2);
            }
        }
        __syncthreads();
    }

    // ---- reduce halves, normalize, write ctx ----
    #pragma unroll
    for (int mi = 0; mi < 2; mi++) {
        int q = mi * 16 + g;
        int dc = wn * 8 + 2 * t;
        stg[hf * 2048 + q * 64 + dc]           = oacc[mi][0];
        stg[hf * 2048 + q * 64 + dc + 1]       = oacc[mi][1];
        stg[hf * 2048 + (q + 8) * 64 + dc]     = oacc[mi][2];
        stg[hf * 2048 + (q + 8) * 64 + dc + 1] = oacc[mi][3];
    }
    __syncthreads();
    for (int i = tid; i < 2048; i += 512) {
        int q = i >> 6, dc = i & 63;
        ctx[((size_t)(b * SS) + q0 + q) * DD + h * DH + dc] =
            (stg[i] + stg[2048 + i]) * sInv[q];
    }
}

// ---------------- launch ----------------
extern "C" void kernel_launch(void* const* d_in, const int* in_sizes, int n_in,
                              void* d_out, int out_size)
{
    const float* query = (const float*)d_in[0];
    const float* key   = (const float*)d_in[1];
    const float* value = (const float*)d_in[2];
    const float* WQ_w  = (const float*)d_in[3];
    const float* WQ_b  = (const float*)d_in[4];
    const float* WK_w  = (const float*)d_in[5];
    const float* WK_b  = (const float*)d_in[6];
    const float* WV_w  = (const float*)d_in[7];
    const float* WV_b  = (const float*)d_in[8];
    const float* WO_w  = (const float*)d_in[9];
    const float* WO_b  = (const float*)d_in[10];
    const float* embK  = (const float*)d_in[11];
    const float* embV  = (const float*)d_in[12];

    float* out = (float*)d_out;                       // [B,S,D]
    float* attn = out + (size_t)BB * SS * DD;         // [B,H,S,S]

    static float *Qp = nullptr, *Kp, *Vp, *Ctx;
    static __nv_bfloat16 *qh, *ql, *kh, *kl, *vh, *vl, *ch, *cl;
    static __nv_bfloat16 *wqh, *wql, *wkh, *wkl, *wvh, *wvl, *woh, *wol;
    static uint32_t *vtH, *vtL;
    if (!Qp) {
        cudaGetSymbolAddress((void**)&Qp, g_Qp);
        cudaGetSymbolAddress((void**)&Kp, g_Kp);
        cudaGetSymbolAddress((void**)&Vp, g_Vp);
        cudaGetSymbolAddress((void**)&Ctx, g_Ctx);
        cudaGetSymbolAddress((void**)&qh, g_qh);   cudaGetSymbolAddress((void**)&ql, g_ql);
        cudaGetSymbolAddress((void**)&kh, g_kh);   cudaGetSymbolAddress((void**)&kl, g_kl);
        cudaGetSymbolAddress((void**)&vh, g_vh);   cudaGetSymbolAddress((void**)&vl, g_vl);
        cudaGetSymbolAddress((void**)&ch, g_ch);   cudaGetSymbolAddress((void**)&cl, g_cl);
        cudaGetSymbolAddress((void**)&wqh, g_wqh); cudaGetSymbolAddress((void**)&wql, g_wql);
        cudaGetSymbolAddress((void**)&wkh, g_wkh); cudaGetSymbolAddress((void**)&wkl, g_wkl);
        cudaGetSymbolAddress((void**)&wvh, g_wvh); cudaGetSymbolAddress((void**)&wvl, g_wvl);
        cudaGetSymbolAddress((void**)&woh, g_woh); cudaGetSymbolAddress((void**)&wol, g_wol);
        cudaGetSymbolAddress((void**)&vtH, g_vtH); cudaGetSymbolAddress((void**)&vtL, g_vtL);
        cudaFuncSetAttribute(attn_mma,
                             cudaFuncAttributeMaxDynamicSharedMemorySize, ASM_BYTES);
        cudaFuncSetAttribute(gemm_qk,
                             cudaFuncAttributeMaxDynamicSharedMemorySize, GSMB);
        cudaFuncSetAttribute(gemm_v,
                             cudaFuncAttributeMaxDynamicSharedMemorySize, GSMB);
        cudaFuncSetAttribute(gemm_o,
                             cudaFuncAttributeMaxDynamicSharedMemorySize, GSMB);
    }

    __nv_bfloat16* QsH = (__nv_bfloat16*)Qp;  __nv_bfloat16* QsL = QsH + (size_t)MTOT * DD;
    __nv_bfloat16* KsH = (__nv_bfloat16*)Kp;  __nv_bfloat16* KsL = KsH + (size_t)MTOT * DD;
    __nv_bfloat16* VsH = (__nv_bfloat16*)Vp;  __nv_bfloat16* VsL = VsH + (size_t)MTOT * DD;

    const int NIN = MTOT * DD;
    const int NW  = DD * DD;

    split3_kernel<<<dim3(NIN / 4 / 256, 3), 256>>>(
        query, qh, ql, key, kh, kl, value, vh, vl, NIN);
    split4_kernel<<<dim3(NW / 4 / 256, 4), 256>>>(
        WQ_w, wqh, wql, WK_w, wkh, wkl, WV_w, wvh, wvl, WO_w, woh, wol, NW);
    gemm_qk<<<dim3(DD / 128, MTOT / 128, 2), 256, GSMB>>>(
        qh, ql, wqh, wql, WQ_b, QsH, QsL,
        kh, kl, wkh, wkl, WK_b, KsH, KsL);
    gemm_v<<<dim3(DD / 128, MTOT / 128), 256, GSMB>>>(vh, vl, wvh, wvl, WV_b, VsH, VsL);
    vtrans_kernel<<<BB * HH * 8, 256>>>(VsH, VsL, vtH, vtL);
    attn_mma<<<BB * HH * (SS / 32), 512, ASM_BYTES>>>(
        QsH, QsL, KsH, KsL, vtH, vtL, embK, embV, attn, Ctx);
    split_kernel<<<NIN / 4 / 256, 256>>>(Ctx, ch, cl, NIN);
    gemm_o<<<dim3(DD / 128, MTOT / 128), 256, GSMB>>>(ch, cl, woh, wol, WO_b, out);
}

// round 10
// speedup vs baseline: 3.1361x; 1.0348x over previous
#include <cuda_runtime.h>
#include <cuda_bf16.h>
#include <cstdint>
#include <cstring>

// Problem constants
#define BB 4
#define SS 1024
#define DD 768
#define HH 12
#define DH 64
#define RR 129          // 2K+1, K=64
#define KWIN 64

#define MTOT (BB * SS)  // 4096

// ---------------- scratch (no allocation allowed) ----------------
__device__ float g_Qp[MTOT * DD];      // reinterpreted: bf16 QsH/QsL
__device__ float g_Kp[MTOT * DD];      // reinterpreted: bf16 KsH/KsL
__device__ float g_Vp[MTOT * DD];      // reinterpreted: bf16 VsH/VsL

__device__ __nv_bfloat16 g_qh[MTOT * DD],  g_ql[MTOT * DD];
__device__ __nv_bfloat16 g_kh[MTOT * DD],  g_kl[MTOT * DD];
__device__ __nv_bfloat16 g_vh[MTOT * DD],  g_vl[MTOT * DD];
__device__ __nv_bfloat16 g_ch[MTOT * DD],  g_cl[MTOT * DD];
__device__ __nv_bfloat16 g_wqh[DD * DD], g_wql[DD * DD];
__device__ __nv_bfloat16 g_wkh[DD * DD], g_wkl[DD * DD];
__device__ __nv_bfloat16 g_wvh[DD * DD], g_wvl[DD * DD];
__device__ __nv_bfloat16 g_woh[DD * DD], g_wol[DD * DD];

// packed V^T: [b*HH+h][d(64)][pair(512)]
__device__ uint32_t g_vtH[BB * HH * DH * (SS / 2)];
__device__ uint32_t g_vtL[BB * HH * DH * (SS / 2)];

// ---------------- cp.async helpers ----------------
__device__ __forceinline__ uint32_t smem_u32(const void* p) {
    uint32_t a;
    asm("{ .reg .u64 t; cvta.to.shared.u64 t, %1; cvt.u32.u64 %0, t; }"
        : "=r"(a) : "l"(p));
    return a;
}
#define CP_ASYNC16(sa, ga) \
    asm volatile("cp.async.cg.shared.global [%0], [%1], 16;" :: "r"(sa), "l"(ga))
#define CP_COMMIT() asm volatile("cp.async.commit_group;" ::: "memory")
#define CP_WAIT1()  asm volatile("cp.async.wait_group 1;" ::: "memory")
#define CP_WAIT0()  asm volatile("cp.async.wait_group 0;" ::: "memory")

// ---------------- fp32 -> bf16 hi/lo split ----------------
__device__ __forceinline__ void split4(const float* __restrict__ x,
                                       __nv_bfloat16* __restrict__ hi,
                                       __nv_bfloat16* __restrict__ lo, int i)
{
    float4 v = *(const float4*)&x[i];
    float vv[4] = {v.x, v.y, v.z, v.w};
    uint16_t h[4], l[4];
    #pragma unroll
    for (int p = 0; p < 4; p++) {
        __nv_bfloat16 hb = __float2bfloat16(vv[p]);
        __nv_bfloat16 lb = __float2bfloat16(vv[p] - __bfloat162float(hb));
        h[p] = __bfloat16_as_ushort(hb);
        l[p] = __bfloat16_as_ushort(lb);
    }
    *(uint2*)&hi[i] = make_uint2(((uint32_t)h[1] << 16) | h[0], ((uint32_t)h[3] << 16) | h[2]);
    *(uint2*)&lo[i] = make_uint2(((uint32_t)l[1] << 16) | l[0], ((uint32_t)l[3] << 16) | l[2]);
}

__global__ __launch_bounds__(256) void split3_kernel(
    const float* __restrict__ a, __nv_bfloat16* ah, __nv_bfloat16* al,
    const float* __restrict__ b, __nv_bfloat16* bh, __nv_bfloat16* bl,
    const float* __restrict__ c, __nv_bfloat16* ch, __nv_bfloat16* cl, int n)
{
    int i = (blockIdx.x * 256 + threadIdx.x) * 4;
    if (i >= n) return;
    const float* x; __nv_bfloat16 *hi, *lo;
    if (blockIdx.y == 0)      { x = a; hi = ah; lo = al; }
    else if (blockIdx.y == 1) { x = b; hi = bh; lo = bl; }
    else                      { x = c; hi = ch; lo = cl; }
    split4(x, hi, lo, i);
}

__global__ __launch_bounds__(256) void split4_kernel(
    const float* __restrict__ a, __nv_bfloat16* ah, __nv_bfloat16* al,
    const float* __restrict__ b, __nv_bfloat16* bh, __nv_bfloat16* bl,
    const float* __restrict__ c, __nv_bfloat16* ch, __nv_bfloat16* cl,
    const float* __restrict__ d, __nv_bfloat16* dh, __nv_bfloat16* dl, int n)
{
    int i = (blockIdx.x * 256 + threadIdx.x) * 4;
    if (i >= n) return;
    const float* x; __nv_bfloat16 *hi, *lo;
    if (blockIdx.y == 0)      { x = a; hi = ah; lo = al; }
    else if (blockIdx.y == 1) { x = b; hi = bh; lo = bl; }
    else if (blockIdx.y == 2) { x = c; hi = ch; lo = cl; }
    else                      { x = d; hi = dh; lo = dl; }
    split4(x, hi, lo, i);
}

// ---------------- mma.sync helper ----------------
__device__ __forceinline__ void mma16816(float* d, const uint32_t* a, const uint32_t* b) {
    asm volatile("mma.sync.aligned.m16n8k16.row.col.f32.bf16.bf16.f32 "
        "{%0,%1,%2,%3}, {%4,%5,%6,%7}, {%8,%9}, {%0,%1,%2,%3};"
        : "+f"(d[0]), "+f"(d[1]), "+f"(d[2]), "+f"(d[3])
        : "r"(a[0]), "r"(a[1]), "r"(a[2]), "r"(a[3]), "r"(b[0]), "r"(b[1]));
}

// ---------------- bf16-split GEMM, 64x128 tile, cp.async 2-stage ----------------
#define SP 40
#define AARR 5120           // 64*SP*2 bytes
#define WARR 10240          // 128*SP*2 bytes
#define GBUF 30720          // per stage: Ah+Al+Wh+Wl
#define GSMB (2 * GBUF)     // 61440

__device__ __forceinline__ void gemm_issue64(
    uint32_t sb, int buf, int tid, int bm, int bn, int k0, int Kd,
    const __nv_bfloat16* __restrict__ Ah, const __nv_bfloat16* __restrict__ Al,
    const __nv_bfloat16* __restrict__ Wh, const __nv_bfloat16* __restrict__ Wl)
{
    uint32_t bo = sb + buf * GBUF;
    {
        int rowA = tid >> 2, cc = (tid & 3) * 8;
        size_t ga = (size_t)(bm + rowA) * Kd + k0 + cc;
        uint32_t so = (uint32_t)(rowA * SP + cc) * 2;
        CP_ASYNC16(bo + so,        Ah + ga);
        CP_ASYNC16(bo + AARR + so, Al + ga);
    }
    #pragma unroll
    for (int it = 0; it < 2; it++) {
        int i = tid + it * 256;
        int rowW = i >> 2, cc = (i & 3) * 8;
        size_t gw = (size_t)(bn + rowW) * Kd + k0 + cc;
        uint32_t so = (uint32_t)(rowW * SP + cc) * 2;
        CP_ASYNC16(bo + 2 * AARR + so,        Wh + gw);
        CP_ASYNC16(bo + 2 * AARR + WARR + so, Wl + gw);
    }
    CP_COMMIT();
}

__device__ __forceinline__ void gemm_body64(
    const __nv_bfloat16* __restrict__ Ah, const __nv_bfloat16* __restrict__ Al,
    const __nv_bfloat16* __restrict__ Wh, const __nv_bfloat16* __restrict__ Wl,
    const float* __restrict__ bias, float* __restrict__ C,
    __nv_bfloat16* __restrict__ Ch, __nv_bfloat16* __restrict__ Cl,
    int M, int N, int Kd)
{
    extern __shared__ char gsm[];
    uint32_t sb = smem_u32(gsm);

    const int tid = threadIdx.x;
    const int bm = blockIdx.y * 64, bn = blockIdx.x * 128;
    const int warp = tid >> 5, lane = tid & 31;
    const int wm = warp & 1, wn = warp >> 1;
    const int g = lane >> 2, t = lane & 3;

    float d[2][4][4] = {};

    const int nch = Kd / 32;
    gemm_issue64(sb, 0, tid, bm, bn, 0, Kd, Ah, Al, Wh, Wl);

    for (int c = 0; c < nch; c++) {
        if (c + 1 < nch) {
            gemm_issue64(sb, (c + 1) & 1, tid, bm, bn, (c + 1) * 32, Kd, Ah, Al, Wh, Wl);
            CP_WAIT1();
        } else {
            CP_WAIT0();
        }
        __syncthreads();

        const char* st = gsm + (c & 1) * GBUF;
        const __nv_bfloat16* sAh = (const __nv_bfloat16*)st;
        const __nv_bfloat16* sAl = (const __nv_bfloat16*)(st + AARR);
        const __nv_bfloat16* sWh = (const __nv_bfloat16*)(st + 2 * AARR);
        const __nv_bfloat16* sWl = (const __nv_bfloat16*)(st + 2 * AARR + WARR);

        #pragma unroll
        for (int ks = 0; ks < 2; ks++) {
            const int kk = ks * 16 + 2 * t;
            uint32_t bh[4][2], bl[4][2];
            #pragma unroll
            for (int ni = 0; ni < 4; ni++) {
                int rb = (wn * 32 + ni * 8 + g) * SP;
                bh[ni][0] = *(const uint32_t*)&sWh[rb + kk];
                bh[ni][1] = *(const uint32_t*)&sWh[rb + kk + 8];
                bl[ni][0] = *(const uint32_t*)&sWl[rb + kk];
                bl[ni][1] = *(const uint32_t*)&sWl[rb + kk + 8];
            }
            #pragma unroll
            for (int mi = 0; mi < 2; mi++) {
                int r0 = (wm * 32 + mi * 16 + g) * SP;
                int r1 = r0 + 8 * SP;
                uint32_t ah[4], al[4];
                ah[0] = *(const uint32_t*)&sAh[r0 + kk];
                ah[1] = *(const uint32_t*)&sAh[r1 + kk];
                ah[2] = *(const uint32_t*)&sAh[r0 + kk + 8];
                ah[3] = *(const uint32_t*)&sAh[r1 + kk + 8];
                al[0] = *(const uint32_t*)&sAl[r0 + kk];
                al[1] = *(const uint32_t*)&sAl[r1 + kk];
                al[2] = *(const uint32_t*)&sAl[r0 + kk + 8];
                al[3] = *(const uint32_t*)&sAl[r1 + kk + 8];
                #pragma unroll
                for (int ni = 0; ni < 4; ni++) {
                    mma16816(d[mi][ni], ah, bh[ni]);
                    mma16816(d[mi][ni], ah, bl[ni]);
                    mma16816(d[mi][ni], al, bh[ni]);
                }
            }
        }
        __syncthreads();
    }

    #pragma unroll
    for (int mi = 0; mi < 2; mi++) {
        int r0 = bm + wm * 32 + mi * 16 + g;
        #pragma unroll
        for (int ni = 0; ni < 4; ni++) {
            int c0 = bn + wn * 32 + ni * 8 + 2 * t;
            float b0 = bias[c0], b1 = bias[c0 + 1];
            float v00 = d[mi][ni][0] + b0, v01 = d[mi][ni][1] + b1;
            float v10 = d[mi][ni][2] + b0, v11 = d[mi][ni][3] + b1;
            if (Ch) {
                uint32_t hp0, lp0, hp1, lp1;
                asm("cvt.rn.bf16x2.f32 %0, %1, %2;" : "=r"(hp0) : "f"(v01), "f"(v00));
                asm("cvt.rn.bf16x2.f32 %0, %1, %2;" : "=r"(hp1) : "f"(v11), "f"(v10));
                float h00 = __uint_as_float(hp0 << 16);
                float h01 = __uint_as_float(hp0 & 0xffff0000u);
                float h10 = __uint_as_float(hp1 << 16);
                float h11 = __uint_as_float(hp1 & 0xffff0000u);
                asm("cvt.rn.bf16x2.f32 %0, %1, %2;" : "=r"(lp0) : "f"(v01 - h01), "f"(v00 - h00));
                asm("cvt.rn.bf16x2.f32 %0, %1, %2;" : "=r"(lp1) : "f"(v11 - h11), "f"(v10 - h10));
                *(uint32_t*)&Ch[(size_t)r0 * N + c0]       = hp0;
                *(uint32_t*)&Cl[(size_t)r0 * N + c0]       = lp0;
                *(uint32_t*)&Ch[(size_t)(r0 + 8) * N + c0] = hp1;
                *(uint32_t*)&Cl[(size_t)(r0 + 8) * N + c0] = lp1;
            } else {
                C[(size_t)r0 * N + c0]           = v00;
                C[(size_t)r0 * N + c0 + 1]       = v01;
                C[(size_t)(r0 + 8) * N + c0]     = v10;
                C[(size_t)(r0 + 8) * N + c0 + 1] = v11;
            }
        }
    }
}

__global__ __launch_bounds__(256, 2) void gemm_qkv(
    const __nv_bfloat16* qh, const __nv_bfloat16* ql,
    const __nv_bfloat16* wqh, const __nv_bfloat16* wql, const float* WQb,
    __nv_bfloat16* QsH, __nv_bfloat16* QsL,
    const __nv_bfloat16* kh, const __nv_bfloat16* kl,
    const __nv_bfloat16* wkh, const __nv_bfloat16* wkl, const float* WKb,
    __nv_bfloat16* KsH, __nv_bfloat16* KsL,
    const __nv_bfloat16* vh, const __nv_bfloat16* vl,
    const __nv_bfloat16* wvh, const __nv_bfloat16* wvl, const float* WVb,
    __nv_bfloat16* VsH, __nv_bfloat16* VsL)
{
    if (blockIdx.z == 0)
        gemm_body64(qh, ql, wqh, wql, WQb, nullptr, QsH, QsL, MTOT, DD, DD);
    else if (blockIdx.z == 1)
        gemm_body64(kh, kl, wkh, wkl, WKb, nullptr, KsH, KsL, MTOT, DD, DD);
    else
        gemm_body64(vh, vl, wvh, wvl, WVb, nullptr, VsH, VsL, MTOT, DD, DD);
}

__global__ __launch_bounds__(256, 2) void gemm_o(
    const __nv_bfloat16* ch, const __nv_bfloat16* cl,
    const __nv_bfloat16* woh, const __nv_bfloat16* wol, const float* WOb,
    float* out)
{
    gemm_body64(ch, cl, woh, wol, WOb, out, nullptr, nullptr, MTOT, DD, DD);
}

// ---------------- V transpose+pack ----------------
__global__ __launch_bounds__(256) void vtrans_kernel(
    const __nv_bfloat16* __restrict__ VsH, const __nv_bfloat16* __restrict__ VsL,
    uint32_t* __restrict__ vtH, uint32_t* __restrict__ vtL)
{
    const int vt = blockIdx.x & 7;
    const int h  = (blockIdx.x >> 3) % HH;
    const int b  = blockIdx.x / (8 * HH);
    const int tid = threadIdx.x;
    const size_t obase = ((size_t)(b * HH + h)) * DH * (SS / 2) + vt * 64;

    for (int i = tid; i < 1024; i += 256) {
        int s = i >> 9, r = i & 511;
        int p = r >> 3, dg = r & 7;
        const __nv_bfloat16* src = s ? VsL : VsH;
        uint32_t* dst = s ? vtL : vtH;
        size_t base = ((size_t)(b * SS) + vt * 128 + 2 * p) * DD + h * DH + dg * 8;
        uint4 w0 = *(const uint4*)&src[base];
        uint4 w1 = *(const uint4*)&src[base + DD];
        uint16_t a0[8], a1[8];
        memcpy(a0, &w0, 16);
        memcpy(a1, &w1, 16);
        #pragma unroll
        for (int j = 0; j < 8; j++)
            dst[obase + (size_t)(dg * 8 + j) * (SS / 2) + p] =
                (uint32_t)a0[j] | ((uint32_t)a1[j] << 16);
    }
}

// ---------------- fused relative attention with mma.sync ----------------
#define KP 72
#define PP 168
#define VP 84
#define WP 160
#define SSTR 1040
#define OFF_A  0
#define ASTRIDE 21504
#define OFF_Q  43008
#define QSTRIDE 4608
#define OFF_P  52224
#define PSTRIDE 10752
#define OFF_W  73728
#define OFF_S  94208
#define OFF_I  227328
#define ASM_BYTES 227456

__global__ __launch_bounds__(512) void attn_mma(
    const __nv_bfloat16* __restrict__ QsH, const __nv_bfloat16* __restrict__ QsL,
    const __nv_bfloat16* __restrict__ KsH, const __nv_bfloat16* __restrict__ KsL,
    const uint32_t* __restrict__ vtH, const uint32_t* __restrict__ vtL,
    const float* __restrict__ embK, const float* __restrict__ embV,
    float* __restrict__ attn_out,
    __nv_bfloat16* __restrict__ ctxH, __nv_bfloat16* __restrict__ ctxL)
{
    extern __shared__ char smc[];
    __nv_bfloat16* aH = (__nv_bfloat16*)(smc + OFF_A);
    __nv_bfloat16* aL = (__nv_bfloat16*)(smc + OFF_A + ASTRIDE);
    uint32_t* vH = (uint32_t*)(smc + OFF_A);
    uint32_t* vL = (uint32_t*)(smc + OFF_A + ASTRIDE);
    __nv_bfloat16* qH = (__nv_bfloat16*)(smc + OFF_Q);
    __nv_bfloat16* qL = (__nv_bfloat16*)(smc + OFF_Q + QSTRIDE);
    __nv_bfloat16* pH = (__nv_bfloat16*)(smc + OFF_P);
    __nv_bfloat16* pL = (__nv_bfloat16*)(smc + OFF_P + PSTRIDE);
    float* stg  = (float*)(smc + OFF_P);
    float* sW   = (float*)(smc + OFF_W);
    float* sS   = (float*)(smc + OFF_S);
    float* sInv = (float*)(smc + OFF_I);

    const int tid = threadIdx.x;
    const int warp = tid >> 5, lane = tid & 31;
    const int g = lane >> 2, t = lane & 3;
    const int nq = SS / 32;
    const int qt = blockIdx.x % nq;
    const int h  = (blockIdx.x / nq) % HH;
    const int b  = blockIdx.x / (nq * HH);
    const int q0 = qt * 32;
    const int bh = b * HH + h;

    // ---- load Q tile ----
    {
        int i = tid;
        if (i < 512) {
            int s = i >> 8, idx = i & 255;
            int row = idx >> 3, c = (idx & 7) * 8;
            const __nv_bfloat16* src = s ? QsL : QsH;
            __nv_bfloat16* dst = s ? qL : qH;
            *(uint4*)&dst[row * KP + c] =
                *(const uint4*)&src[((size_t)(b * SS) + q0 + row) * DD + h * DH + c];
        }
    }
    // ---- load embK ----
    for (int i = tid; i < 1088; i += 512) {
        int r = i >> 3, c = (i & 7) * 8;
        float v[8] = {};
        if (r < RR) {
            float4 x = *(const float4*)&embK[(size_t)r * DD + h * DH + c];
            float4 y = *(const float4*)&embK[(size_t)r * DD + h * DH + c + 4];
            v[0]=x.x; v[1]=x.y; v[2]=x.z; v[3]=x.w; v[4]=y.x; v[5]=y.y; v[6]=y.z; v[7]=y.w;
        }
        #pragma unroll
        for (int j = 0; j < 8; j++) {
            __nv_bfloat16 hb = __float2bfloat16(v[j]);
            aH[r * KP + c + j] = hb;
            aL[r * KP + c + j] = __float2bfloat16(v[j] - __bfloat162float(hb));
        }
    }
    __syncthreads();

    // prefetch K chunk 0
    uint4 kreg[4];
    #pragma unroll
    for (int it = 0; it < 4; it++) {
        int i = tid + it * 512;
        int s = i >> 10, idx = i & 1023;
        int row = idx >> 3, c = (idx & 7) * 8;
        const __nv_bfloat16* src = s ? KsL : KsH;
        kreg[it] = *(const uint4*)&src[((size_t)(b * SS) + row) * DD + h * DH + c];
    }

    // ---- rel table ----
    for (int nt = warp; nt < 17; nt += 16) {
        float dr[2][4] = {};
        #pragma unroll
        for (int ks = 0; ks < 4; ks++) {
            int kk = ks * 16 + 2 * t;
            int rb = (nt * 8 + g) * KP;
            uint32_t bh2[2] = {*(uint32_t*)&aH[rb + kk], *(uint32_t*)&aH[rb + kk + 8]};
            uint32_t bl2[2] = {*(uint32_t*)&aL[rb + kk], *(uint32_t*)&aL[rb + kk + 8]};
            #pragma unroll
            for (int mi = 0; mi < 2; mi++) {
                int r0 = (mi * 16 + g) * KP, r1 = r0 + 8 * KP;
                uint32_t ah4[4] = {*(uint32_t*)&qH[r0 + kk], *(uint32_t*)&qH[r1 + kk],
                                   *(uint32_t*)&qH[r0 + kk + 8], *(uint32_t*)&qH[r1 + kk + 8]};
                uint32_t al4[4] = {*(uint32_t*)&qL[r0 + kk], *(uint32_t*)&qL[r1 + kk],
                                   *(uint32_t*)&qL[r0 + kk + 8], *(uint32_t*)&qL[r1 + kk + 8]};
                mma16816(dr[mi], ah4, bh2);
                mma16816(dr[mi], ah4, bl2);
                mma16816(dr[mi], al4, bh2);
            }
        }
        #pragma unroll
        for (int mi = 0; mi < 2; mi++) {
            int q = mi * 16 + g;
            int r = nt * 8 + 2 * t;
            if (r < RR)     sW[q * WP + r]           = dr[mi][0];
            if (r + 1 < RR) sW[q * WP + r + 1]       = dr[mi][1];
            if (r < RR)     sW[(q + 8) * WP + r]     = dr[mi][2];
            if (r + 1 < RR) sW[(q + 8) * WP + r + 1] = dr[mi][3];
        }
    }
    __syncthreads();

    // ---- scores: 8 chunks, reg-prefetch pipelined ----
    const float scale = 0.125f;
    for (int kt = 0; kt < 8; kt++) {
        #pragma unroll
        for (int it = 0; it < 4; it++) {
            int i = tid + it * 512;
            int s = i >> 10, idx = i & 1023;
            int row = idx >> 3, c = (idx & 7) * 8;
            __nv_bfloat16* dst = s ? aL : aH;
            *(uint4*)&dst[row * KP + c] = kreg[it];
        }
        __syncthreads();
        if (kt < 7) {
            #pragma unroll
            for (int it = 0; it < 4; it++) {
                int i = tid + it * 512;
                int s = i >> 10, idx = i & 1023;
                int row = idx >> 3, c = (idx & 7) * 8;
                const __nv_bfloat16* src = s ? KsL : KsH;
                kreg[it] = *(const uint4*)&src[((size_t)(b * SS) + (kt + 1) * 128 + row) * DD + h * DH + c];
            }
        }

        float dacc[2][4] = {};
        #pragma unroll
        for (int ks = 0; ks < 4; ks++) {
            int kk = ks * 16 + 2 * t;
            int rb = (warp * 8 + g) * KP;
            uint32_t bh2[2] = {*(uint32_t*)&aH[rb + kk], *(uint32_t*)&aH[rb + kk + 8]};
            uint32_t bl2[2] = {*(uint32_t*)&aL[rb + kk], *(uint32_t*)&aL[rb + kk + 8]};
            #pragma unroll
            for (int mi = 0; mi < 2; mi++) {
                int r0 = (mi * 16 + g) * KP, r1 = r0 + 8 * KP;
                uint32_t ah4[4] = {*(uint32_t*)&qH[r0 + kk], *(uint32_t*)&qH[r1 + kk],
                                   *(uint32_t*)&qH[r0 + kk + 8], *(uint32_t*)&qH[r1 + kk + 8]};
                uint32_t al4[4] = {*(uint32_t*)&qL[r0 + kk], *(uint32_t*)&qL[r1 + kk],
                                   *(uint32_t*)&qL[r0 + kk + 8], *(uint32_t*)&qL[r1 + kk + 8]};
                mma16816(dacc[mi], ah4, bh2);
                mma16816(dacc[mi], ah4, bl2);
                mma16816(dacc[mi], al4, bh2);
            }
        }
        #pragma unroll
        for (int mi = 0; mi < 2; mi++) {
            int q = mi * 16 + g;
            int gk = kt * 128 + warp * 8 + 2 * t;
            #pragma unroll
            for (int rr = 0; rr < 2; rr++) {
                int qq = q + rr * 8;
                int qg = q0 + qq;
                int rel0 = min(max(gk - qg,     -KWIN), KWIN) + KWIN;
                int rel1 = min(max(gk + 1 - qg, -KWIN), KWIN) + KWIN;
                sS[qq * SSTR + gk]     = (dacc[mi][rr * 2]     + sW[qq * WP + rel0]) * scale;
                sS[qq * SSTR + gk + 1] = (dacc[mi][rr * 2 + 1] + sW[qq * WP + rel1]) * scale;
            }
        }
        __syncthreads();
    }

    // prefetch V chunk 0
    uint4 vreg[4];
    #pragma unroll
    for (int it = 0; it < 4; it++) {
        int i = tid + it * 512;
        int s = i >> 10, idx = i & 1023;
        int d = idx >> 4, g4 = (idx & 15) * 4;
        const uint32_t* src = s ? vtL : vtH;
        vreg[it] = *(const uint4*)&src[((size_t)bh * DH + d) * (SS / 2) + g4];
    }

    // ---- softmax (no max pass) ----
    const int qrow = tid >> 4;
    const int s16  = tid & 15;
    {
        float* row = sS + qrow * SSTR;
        float sum = 0.f;
        for (int k4 = s16 * 4; k4 < SS; k4 += 64) {
            float4 e = *(float4*)&row[k4];
            e.x = __expf(e.x); e.y = __expf(e.y);
            e.z = __expf(e.z); e.w = __expf(e.w);
            *(float4*)&row[k4] = e;
            sum += e.x + e.y + e.z + e.w;
        }
        #pragma unroll
        for (int off = 1; off < 16; off <<= 1)
            sum += __shfl_xor_sync(0xffffffffu, sum, off, 16);
        if (s16 == 0) sInv[qrow] = 1.f / sum;
    }
    __syncthreads();

    // ---- write attn (normalized, float4) ----
    {
        float* aout = attn_out + ((size_t)bh * SS + q0) * SS;
        for (int i = tid; i < 8192; i += 512) {
            int qq = i >> 8, k4 = (i & 255) * 4;
            float4 v = *(float4*)&sS[qq * SSTR + k4];
            float s = sInv[qq];
            v.x *= s; v.y *= s; v.z *= s; v.w *= s;
            *(float4*)&aout[(size_t)qq * SS + k4] = v;
        }
    }

    // ---- w buckets ----
    {
        const int qg = q0 + qrow;
        for (int r = 1 + s16; r <= 127; r += 16) {
            int k = qg - KWIN + r;
            sW[qrow * WP + r] = (k >= 0 && k < SS) ? sS[qrow * SSTR + k] : 0.f;
        }
        float s0 = 0.f, s1 = 0.f;
        for (int k = s16; k < SS; k += 16) {
            float v = sS[qrow * SSTR + k];
            if (k <= qg - KWIN) s0 += v;
            else if (k >= qg + KWIN) s1 += v;
        }
        #pragma unroll
        for (int off = 1; off < 16; off <<= 1) {
            s0 += __shfl_xor_sync(0xffffffffu, s0, off, 16);
            s1 += __shfl_xor_sync(0xffffffffu, s1, off, 16);
        }
        if (s16 == 0) {
            sW[qrow * WP + 0]   = s0;
            sW[qrow * WP + 128] = s1;
        }
        for (int i = tid; i < 32 * 31; i += 512) {
            int q = i / 31, r = 129 + (i % 31);
            sW[q * WP + r] = 0.f;
        }
    }
    __syncthreads();

    // ---- PV: 8 chunks, reg-prefetch pipelined ----
    const int wn = warp >> 1, hf = warp & 1;
    float oacc[2][4] = {};
    for (int vt = 0; vt < 8; vt++) {
        #pragma unroll
        for (int it = 0; it < 4; it++) {
            int i = tid + it * 512;
            int s = i >> 10, idx = i & 1023;
            int d = idx >> 4, g4 = (idx & 15) * 4;
            uint32_t* dst = s ? vL : vH;
            *(uint4*)&dst[d * VP + g4] = vreg[it];
        }
        for (int i = tid; i < 2048; i += 512) {
            int q = i >> 6, c2 = (i & 63) * 2;
            float2 v = *(float2*)&sS[q * SSTR + vt * 128 + c2];
            uint32_t hpk, lpk;
            asm("cvt.rn.bf16x2.f32 %0, %1, %2;" : "=r"(hpk) : "f"(v.y), "f"(v.x));
            float h0 = __uint_as_float(hpk << 16);
            float h1 = __uint_as_float(hpk & 0xffff0000u);
            asm("cvt.rn.bf16x2.f32 %0, %1, %2;" : "=r"(lpk) : "f"(v.y - h1), "f"(v.x - h0));
            *(uint32_t*)&pH[q * PP + c2] = hpk;
            *(uint32_t*)&pL[q * PP + c2] = lpk;
        }
        __syncthreads();
        if (vt < 7) {
            #pragma unroll
            for (int it = 0; it < 4; it++) {
                int i = tid + it * 512;
                int s = i >> 10, idx = i & 1023;
                int d = idx >> 4, g4 = (idx & 15) * 4;
                const uint32_t* src = s ? vtL : vtH;
                vreg[it] = *(const uint4*)&src[((size_t)bh * DH + d) * (SS / 2) + (vt + 1) * 64 + g4];
            }
        }

        #pragma unroll
        for (int ks = 0; ks < 4; ks++) {
            int kb = hf * 64 + ks * 16 + 2 * t;
            int widx = hf * 32 + ks * 8 + t;
            int vrow = (wn * 8 + g) * VP;
            uint32_t bh2[2] = {vH[vrow + widx], vH[vrow + widx + 4]};
            uint32_t bl2[2] = {vL[vrow + widx], vL[vrow + widx + 4]};
            #pragma unroll
            for (int mi = 0; mi < 2; mi++) {
                int r0 = (mi * 16 + g) * PP, r1 = r0 + 8 * PP;
                uint32_t ah4[4] = {*(uint32_t*)&pH[r0 + kb], *(uint32_t*)&pH[r1 + kb],
                                   *(uint32_t*)&pH[r0 + kb + 8], *(uint32_t*)&pH[r1 + kb + 8]};
                uint32_t al4[4] = {*(uint32_t*)&pL[r0 + kb], *(uint32_t*)&pL[r1 + kb],
                                   *(uint32_t*)&pL[r0 + kb + 8], *(uint32_t*)&pL[r1 + kb + 8]};
                mma16816(oacc[mi], ah4, bh2);
                mma16816(oacc[mi], ah4, bl2);
                mma16816(oacc[mi], al4, bh2);
            }
        }
        __syncthreads();
    }

    // ---- extra chunk: w @ embV_h ----
    {
        for (int i = tid; i < 640; i += 512) {
            int p = i >> 3, dg = i & 7;
            int r0 = 2 * p, r1 = 2 * p + 1;
            float v0[8] = {}, v1[8] = {};
            if (r0 < RR) {
                float4 x = *(const float4*)&embV[(size_t)r0 * DD + h * DH + dg * 8];
                float4 y = *(const float4*)&embV[(size_t)r0 * DD + h * DH + dg * 8 + 4];
                v0[0]=x.x; v0[1]=x.y; v0[2]=x.z; v0[3]=x.w; v0[4]=y.x; v0[5]=y.y; v0[6]=y.z; v0[7]=y.w;
            }
            if (r1 < RR) {
                float4 x = *(const float4*)&embV[(size_t)r1 * DD + h * DH + dg * 8];
                float4 y = *(const float4*)&embV[(size_t)r1 * DD + h * DH + dg * 8 + 4];
                v1[0]=x.x; v1[1]=x.y; v1[2]=x.z; v1[3]=x.w; v1[4]=y.x; v1[5]=y.y; v1[6]=y.z; v1[7]=y.w;
            }
            #pragma unroll
            for (int j = 0; j < 8; j++) {
                __nv_bfloat16 h0 = __float2bfloat16(v0[j]);
                __nv_bfloat16 h1 = __float2bfloat16(v1[j]);
                __nv_bfloat16 l0 = __float2bfloat16(v0[j] - __bfloat162float(h0));
                __nv_bfloat16 l1 = __float2bfloat16(v1[j] - __bfloat162float(h1));
                vH[(dg * 8 + j) * VP + p] =
                    (uint32_t)__bfloat16_as_ushort(h0) | ((uint32_t)__bfloat16_as_ushort(h1) << 16);
                vL[(dg * 8 + j) * VP + p] =
                    (uint32_t)__bfloat16_as_ushort(l0) | ((uint32_t)__bfloat16_as_ushort(l1) << 16);
            }
        }
        for (int i = tid; i < 2560; i += 512) {
            int q = i / 80, c2 = (i % 80) * 2;
            float2 v = *(float2*)&sW[q * WP + c2];
            uint32_t hpk, lpk;
            asm("cvt.rn.bf16x2.f32 %0, %1, %2;" : "=r"(hpk) : "f"(v.y), "f"(v.x));
            float h0 = __uint_as_float(hpk << 16);
            float h1 = __uint_as_float(hpk & 0xffff0000u);
            asm("cvt.rn.bf16x2.f32 %0, %1, %2;" : "=r"(lpk) : "f"(v.y - h1), "f"(v.x - h0));
            *(uint32_t*)&pH[q * PP + c2] = hpk;
            *(uint32_t*)&pL[q * PP + c2] = lpk;
        }
        __syncthreads();

        #pragma unroll
        for (int ks = 0; ks < 5; ks++) {
            int kb = hf * 80 + ks * 16 + 2 * t;
            int widx = hf * 40 + ks * 8 + t;
            int vrow = (wn * 8 + g) * VP;
            uint32_t bh2[2] = {vH[vrow + widx], vH[vrow + widx + 4]};
            uint32_t bl2[2] = {vL[vrow + widx], vL[vrow + widx + 4]};
            #pragma unroll
            for (int mi = 0; mi < 2; mi++) {
                int r0 = (mi * 16 + g) * PP, r1 = r0 + 8 * PP;
                uint32_t ah4[4] = {*(uint32_t*)&pH[r0 + kb], *(uint32_t*)&pH[r1 + kb],
                                   *(uint32_t*)&pH[r0 + kb + 8], *(uint32_t*)&pH[r1 + kb + 8]};
                uint32_t al4[4] = {*(uint32_t*)&pL[r0 + kb], *(uint32_t*)&pL[r1 + kb],
                                   *(uint32_t*)&pL[r0 + kb + 8], *(uint32_t*)&pL[r1 + kb + 8]};
                mma16816(oacc[mi], ah4, bh2);
                mma16816(oacc[mi], ah4, bl2);
                mma16816(oacc[mi], al4, bh2);
            }
        }
        __syncthreads();
    }

    // ---- reduce halves, normalize, write ctx as bf16 hi/lo split ----
    #pragma unroll
    for (int mi = 0; mi < 2; mi++) {
        int q = mi * 16 + g;
        int dc = wn * 8 + 2 * t;
        stg[hf * 2048 + q * 64 + dc]           = oacc[mi][0];
        stg[hf * 2048 + q * 64 + dc + 1]       = oacc[mi][1];
        stg[hf * 2048 + (q + 8) * 64 + dc]     = oacc[mi][2];
        stg[hf * 2048 + (q + 8) * 64 + dc + 1] = oacc[mi][3];
    }
    __syncthreads();
    for (int i = tid; i < 1024; i += 512) {
        int q = i >> 5, dc2 = (i & 31) * 2;
        float inv = sInv[q];
        float v0 = (stg[q * 64 + dc2]     + stg[2048 + q * 64 + dc2])     * inv;
        float v1 = (stg[q * 64 + dc2 + 1] + stg[2048 + q * 64 + dc2 + 1]) * inv;
        uint32_t hpk, lpk;
        asm("cvt.rn.bf16x2.f32 %0, %1, %2;" : "=r"(hpk) : "f"(v1), "f"(v0));
        float h0 = __uint_as_float(hpk << 16);
        float h1 = __uint_as_float(hpk & 0xffff0000u);
        asm("cvt.rn.bf16x2.f32 %0, %1, %2;" : "=r"(lpk) : "f"(v1 - h1), "f"(v0 - h0));
        size_t dst = ((size_t)(b * SS) + q0 + q) * DD + h * DH + dc2;
        *(uint32_t*)&ctxH[dst] = hpk;
        *(uint32_t*)&ctxL[dst] = lpk;
    }
}

// ---------------- launch ----------------
extern "C" void kernel_launch(void* const* d_in, const int* in_sizes, int n_in,
                              void* d_out, int out_size)
{
    const float* query = (const float*)d_in[0];
    const float* key   = (const float*)d_in[1];
    const float* value = (const float*)d_in[2];
    const float* WQ_w  = (const float*)d_in[3];
    const float* WQ_b  = (const float*)d_in[4];
    const float* WK_w  = (const float*)d_in[5];
    const float* WK_b  = (const float*)d_in[6];
    const float* WV_w  = (const float*)d_in[7];
    const float* WV_b  = (const float*)d_in[8];
    const float* WO_w  = (const float*)d_in[9];
    const float* WO_b  = (const float*)d_in[10];
    const float* embK  = (const float*)d_in[11];
    const float* embV  = (const float*)d_in[12];

    float* out = (float*)d_out;                       // [B,S,D]
    float* attn = out + (size_t)BB * SS * DD;         // [B,H,S,S]

    static float *Qp = nullptr, *Kp, *Vp;
    static __nv_bfloat16 *qh, *ql, *kh, *kl, *vh, *vl, *ch, *cl;
    static __nv_bfloat16 *wqh, *wql, *wkh, *wkl, *wvh, *wvl, *woh, *wol;
    static uint32_t *vtH, *vtL;
    if (!Qp) {
        cudaGetSymbolAddress((void**)&Qp, g_Qp);
        cudaGetSymbolAddress((void**)&Kp, g_Kp);
        cudaGetSymbolAddress((void**)&Vp, g_Vp);
        cudaGetSymbolAddress((void**)&qh, g_qh);   cudaGetSymbolAddress((void**)&ql, g_ql);
        cudaGetSymbolAddress((void**)&kh, g_kh);   cudaGetSymbolAddress((void**)&kl, g_kl);
        cudaGetSymbolAddress((void**)&vh, g_vh);   cudaGetSymbolAddress((void**)&vl, g_vl);
        cudaGetSymbolAddress((void**)&ch, g_ch);   cudaGetSymbolAddress((void**)&cl, g_cl);
        cudaGetSymbolAddress((void**)&wqh, g_wqh); cudaGetSymbolAddress((void**)&wql, g_wql);
        cudaGetSymbolAddress((void**)&wkh, g_wkh); cudaGetSymbolAddress((void**)&wkl, g_wkl);
        cudaGetSymbolAddress((void**)&wvh, g_wvh); cudaGetSymbolAddress((void**)&wvl, g_wvl);
        cudaGetSymbolAddress((void**)&woh, g_woh); cudaGetSymbolAddress((void**)&wol, g_wol);
        cudaGetSymbolAddress((void**)&vtH, g_vtH); cudaGetSymbolAddress((void**)&vtL, g_vtL);
        cudaFuncSetAttribute(attn_mma,
                             cudaFuncAttributeMaxDynamicSharedMemorySize, ASM_BYTES);
        cudaFuncSetAttribute(gemm_qkv,
                             cudaFuncAttributeMaxDynamicSharedMemorySize, GSMB);
        cudaFuncSetAttribute(gemm_o,
                             cudaFuncAttributeMaxDynamicSharedMemorySize, GSMB);
    }

    __nv_bfloat16* QsH = (__nv_bfloat16*)Qp;  __nv_bfloat16* QsL = QsH + (size_t)MTOT * DD;
    __nv_bfloat16* KsH = (__nv_bfloat16*)Kp;  __nv_bfloat16* KsL = KsH + (size_t)MTOT * DD;
    __nv_bfloat16* VsH = (__nv_bfloat16*)Vp;  __nv_bfloat16* VsL = VsH + (size_t)MTOT * DD;

    const int NIN = MTOT * DD;
    const int NW  = DD * DD;

    split3_kernel<<<dim3(NIN / 4 / 256, 3), 256>>>(
        query, qh, ql, key, kh, kl, value, vh, vl, NIN);
    split4_kernel<<<dim3(NW / 4 / 256, 4), 256>>>(
        WQ_w, wqh, wql, WK_w, wkh, wkl, WV_w, wvh, wvl, WO_w, woh, wol, NW);
    gemm_qkv<<<dim3(DD / 128, MTOT / 64, 3), 256, GSMB>>>(
        qh, ql, wqh, wql, WQ_b, QsH, QsL,
        kh, kl, wkh, wkl, WK_b, KsH, KsL,
        vh, vl, wvh, wvl, WV_b, VsH, VsL);
    vtrans_kernel<<<BB * HH * 8, 256>>>(VsH, VsL, vtH, vtL);
    attn_mma<<<BB * HH * (SS / 32), 512, ASM_BYTES>>>(
        QsH, QsL, KsH, KsL, vtH, vtL, embK, embV, attn, ch, cl);
    gemm_o<<<dim3(DD / 128, MTOT / 64), 256, GSMB>>>(ch, cl, woh, wol, WO_b, out);
}

// round 11
// speedup vs baseline: 3.1530x; 1.0054x over previous
#include <cuda_runtime.h>
#include <cuda_bf16.h>
#include <cstdint>
#include <cstring>

// Problem constants
#define BB 4
#define SS 1024
#define DD 768
#define HH 12
#define DH 64
#define RR 129          // 2K+1, K=64
#define KWIN 64

#define MTOT (BB * SS)  // 4096

// ---------------- scratch (no allocation allowed) ----------------
__device__ float g_Qp[MTOT * DD];      // reinterpreted: bf16 QsH/QsL
__device__ float g_Kp[MTOT * DD];      // reinterpreted: bf16 KsH/KsL
__device__ float g_Vp[MTOT * DD];      // reinterpreted: bf16 VsH/VsL

__device__ __nv_bfloat16 g_qh[MTOT * DD],  g_ql[MTOT * DD];
__device__ __nv_bfloat16 g_kh[MTOT * DD],  g_kl[MTOT * DD];
__device__ __nv_bfloat16 g_vh[MTOT * DD],  g_vl[MTOT * DD];
__device__ __nv_bfloat16 g_ch[MTOT * DD],  g_cl[MTOT * DD];
__device__ __nv_bfloat16 g_wqh[DD * DD], g_wql[DD * DD];
__device__ __nv_bfloat16 g_wkh[DD * DD], g_wkl[DD * DD];
__device__ __nv_bfloat16 g_wvh[DD * DD], g_wvl[DD * DD];
__device__ __nv_bfloat16 g_woh[DD * DD], g_wol[DD * DD];

// packed V^T: [b*HH+h][d(64)][pair(512)]
__device__ uint32_t g_vtH[BB * HH * DH * (SS / 2)];
__device__ uint32_t g_vtL[BB * HH * DH * (SS / 2)];

// ---------------- cp.async helpers ----------------
__device__ __forceinline__ uint32_t smem_u32(const void* p) {
    uint32_t a;
    asm("{ .reg .u64 t; cvta.to.shared.u64 t, %1; cvt.u32.u64 %0, t; }"
        : "=r"(a) : "l"(p));
    return a;
}
#define CP_ASYNC16(sa, ga) \
    asm volatile("cp.async.cg.shared.global [%0], [%1], 16;" :: "r"(sa), "l"(ga))
#define CP_COMMIT() asm volatile("cp.async.commit_group;" ::: "memory")
#define CP_WAIT1()  asm volatile("cp.async.wait_group 1;" ::: "memory")
#define CP_WAIT0()  asm volatile("cp.async.wait_group 0;" ::: "memory")

// ---------------- fp32 -> bf16 hi/lo split ----------------
__device__ __forceinline__ void split4(const float* __restrict__ x,
                                       __nv_bfloat16* __restrict__ hi,
                                       __nv_bfloat16* __restrict__ lo, int i)
{
    float4 v = *(const float4*)&x[i];
    float vv[4] = {v.x, v.y, v.z, v.w};
    uint16_t h[4], l[4];
    #pragma unroll
    for (int p = 0; p < 4; p++) {
        __nv_bfloat16 hb = __float2bfloat16(vv[p]);
        __nv_bfloat16 lb = __float2bfloat16(vv[p] - __bfloat162float(hb));
        h[p] = __bfloat16_as_ushort(hb);
        l[p] = __bfloat16_as_ushort(lb);
    }
    *(uint2*)&hi[i] = make_uint2(((uint32_t)h[1] << 16) | h[0], ((uint32_t)h[3] << 16) | h[2]);
    *(uint2*)&lo[i] = make_uint2(((uint32_t)l[1] << 16) | l[0], ((uint32_t)l[3] << 16) | l[2]);
}

// One launch: y = 0..2 inputs (n = nin), y = 3..6 weights (n = nw).
__global__ __launch_bounds__(256) void split_all_kernel(
    const float* __restrict__ i0, __nv_bfloat16* i0h, __nv_bfloat16* i0l,
    const float* __restrict__ i1, __nv_bfloat16* i1h, __nv_bfloat16* i1l,
    const float* __restrict__ i2, __nv_bfloat16* i2h, __nv_bfloat16* i2l,
    const float* __restrict__ w0, __nv_bfloat16* w0h, __nv_bfloat16* w0l,
    const float* __restrict__ w1, __nv_bfloat16* w1h, __nv_bfloat16* w1l,
    const float* __restrict__ w2, __nv_bfloat16* w2h, __nv_bfloat16* w2l,
    const float* __restrict__ w3, __nv_bfloat16* w3h, __nv_bfloat16* w3l,
    int nin, int nw)
{
    int i = (blockIdx.x * 256 + threadIdx.x) * 4;
    int y = blockIdx.y;
    int n = (y < 3) ? nin : nw;
    if (i >= n) return;
    const float* x; __nv_bfloat16 *hi, *lo;
    switch (y) {
        case 0: x = i0; hi = i0h; lo = i0l; break;
        case 1: x = i1; hi = i1h; lo = i1l; break;
        case 2: x = i2; hi = i2h; lo = i2l; break;
        case 3: x = w0; hi = w0h; lo = w0l; break;
        case 4: x = w1; hi = w1h; lo = w1l; break;
        case 5: x = w2; hi = w2h; lo = w2l; break;
        default: x = w3; hi = w3h; lo = w3l; break;
    }
    split4(x, hi, lo, i);
}

// ---------------- mma.sync helper ----------------
__device__ __forceinline__ void mma16816(float* d, const uint32_t* a, const uint32_t* b) {
    asm volatile("mma.sync.aligned.m16n8k16.row.col.f32.bf16.bf16.f32 "
        "{%0,%1,%2,%3}, {%4,%5,%6,%7}, {%8,%9}, {%0,%1,%2,%3};"
        : "+f"(d[0]), "+f"(d[1]), "+f"(d[2]), "+f"(d[3])
        : "r"(a[0]), "r"(a[1]), "r"(a[2]), "r"(a[3]), "r"(b[0]), "r"(b[1]));
}

// ---------------- bf16-split GEMM, 64x128 tile, cp.async 2-stage ----------------
#define SP 40
#define AARR 5120
#define WARR 10240
#define GBUF 30720
#define GSMB (2 * GBUF)

__device__ __forceinline__ void gemm_issue64(
    uint32_t sb, int buf, int tid, int bm, int bn, int k0, int Kd,
    const __nv_bfloat16* __restrict__ Ah, const __nv_bfloat16* __restrict__ Al,
    const __nv_bfloat16* __restrict__ Wh, const __nv_bfloat16* __restrict__ Wl)
{
    uint32_t bo = sb + buf * GBUF;
    {
        int rowA = tid >> 2, cc = (tid & 3) * 8;
        size_t ga = (size_t)(bm + rowA) * Kd + k0 + cc;
        uint32_t so = (uint32_t)(rowA * SP + cc) * 2;
        CP_ASYNC16(bo + so,        Ah + ga);
        CP_ASYNC16(bo + AARR + so, Al + ga);
    }
    #pragma unroll
    for (int it = 0; it < 2; it++) {
        int i = tid + it * 256;
        int rowW = i >> 2, cc = (i & 3) * 8;
        size_t gw = (size_t)(bn + rowW) * Kd + k0 + cc;
        uint32_t so = (uint32_t)(rowW * SP + cc) * 2;
        CP_ASYNC16(bo + 2 * AARR + so,        Wh + gw);
        CP_ASYNC16(bo + 2 * AARR + WARR + so, Wl + gw);
    }
    CP_COMMIT();
}

__device__ __forceinline__ void gemm_body64(
    const __nv_bfloat16* __restrict__ Ah, const __nv_bfloat16* __restrict__ Al,
    const __nv_bfloat16* __restrict__ Wh, const __nv_bfloat16* __restrict__ Wl,
    const float* __restrict__ bias, float* __restrict__ C,
    __nv_bfloat16* __restrict__ Ch, __nv_bfloat16* __restrict__ Cl,
    int M, int N, int Kd)
{
    extern __shared__ char gsm[];
    uint32_t sb = smem_u32(gsm);

    const int tid = threadIdx.x;
    const int bm = blockIdx.y * 64, bn = blockIdx.x * 128;
    const int warp = tid >> 5, lane = tid & 31;
    const int wm = warp & 1, wn = warp >> 1;
    const int g = lane >> 2, t = lane & 3;

    float d[2][4][4] = {};

    const int nch = Kd / 32;
    gemm_issue64(sb, 0, tid, bm, bn, 0, Kd, Ah, Al, Wh, Wl);

    for (int c = 0; c < nch; c++) {
        if (c + 1 < nch) {
            gemm_issue64(sb, (c + 1) & 1, tid, bm, bn, (c + 1) * 32, Kd, Ah, Al, Wh, Wl);
            CP_WAIT1();
        } else {
            CP_WAIT0();
        }
        __syncthreads();

        const char* st = gsm + (c & 1) * GBUF;
        const __nv_bfloat16* sAh = (const __nv_bfloat16*)st;
        const __nv_bfloat16* sAl = (const __nv_bfloat16*)(st + AARR);
        const __nv_bfloat16* sWh = (const __nv_bfloat16*)(st + 2 * AARR);
        const __nv_bfloat16* sWl = (const __nv_bfloat16*)(st + 2 * AARR + WARR);

        #pragma unroll
        for (int ks = 0; ks < 2; ks++) {
            const int kk = ks * 16 + 2 * t;
            uint32_t bh[4][2], bl[4][2];
            #pragma unroll
            for (int ni = 0; ni < 4; ni++) {
                int rb = (wn * 32 + ni * 8 + g) * SP;
                bh[ni][0] = *(const uint32_t*)&sWh[rb + kk];
                bh[ni][1] = *(const uint32_t*)&sWh[rb + kk + 8];
                bl[ni][0] = *(const uint32_t*)&sWl[rb + kk];
                bl[ni][1] = *(const uint32_t*)&sWl[rb + kk + 8];
            }
            #pragma unroll
            for (int mi = 0; mi < 2; mi++) {
                int r0 = (wm * 32 + mi * 16 + g) * SP;
                int r1 = r0 + 8 * SP;
                uint32_t ah[4], al[4];
                ah[0] = *(const uint32_t*)&sAh[r0 + kk];
                ah[1] = *(const uint32_t*)&sAh[r1 + kk];
                ah[2] = *(const uint32_t*)&sAh[r0 + kk + 8];
                ah[3] = *(const uint32_t*)&sAh[r1 + kk + 8];
                al[0] = *(const uint32_t*)&sAl[r0 + kk];
                al[1] = *(const uint32_t*)&sAl[r1 + kk];
                al[2] = *(const uint32_t*)&sAl[r0 + kk + 8];
                al[3] = *(const uint32_t*)&sAl[r1 + kk + 8];
                #pragma unroll
                for (int ni = 0; ni < 4; ni++) {
                    mma16816(d[mi][ni], ah, bh[ni]);
                    mma16816(d[mi][ni], ah, bl[ni]);
                    mma16816(d[mi][ni], al, bh[ni]);
                }
            }
        }
        __syncthreads();
    }

    #pragma unroll
    for (int mi = 0; mi < 2; mi++) {
        int r0 = bm + wm * 32 + mi * 16 + g;
        #pragma unroll
        for (int ni = 0; ni < 4; ni++) {
            int c0 = bn + wn * 32 + ni * 8 + 2 * t;
            float b0 = bias[c0], b1 = bias[c0 + 1];
            float v00 = d[mi][ni][0] + b0, v01 = d[mi][ni][1] + b1;
            float v10 = d[mi][ni][2] + b0, v11 = d[mi][ni][3] + b1;
            if (Ch) {
                uint32_t hp0, lp0, hp1, lp1;
                asm("cvt.rn.bf16x2.f32 %0, %1, %2;" : "=r"(hp0) : "f"(v01), "f"(v00));
                asm("cvt.rn.bf16x2.f32 %0, %1, %2;" : "=r"(hp1) : "f"(v11), "f"(v10));
                float h00 = __uint_as_float(hp0 << 16);
                float h01 = __uint_as_float(hp0 & 0xffff0000u);
                float h10 = __uint_as_float(hp1 << 16);
                float h11 = __uint_as_float(hp1 & 0xffff0000u);
                asm("cvt.rn.bf16x2.f32 %0, %1, %2;" : "=r"(lp0) : "f"(v01 - h01), "f"(v00 - h00));
                asm("cvt.rn.bf16x2.f32 %0, %1, %2;" : "=r"(lp1) : "f"(v11 - h11), "f"(v10 - h10));
                *(uint32_t*)&Ch[(size_t)r0 * N + c0]       = hp0;
                *(uint32_t*)&Cl[(size_t)r0 * N + c0]       = lp0;
                *(uint32_t*)&Ch[(size_t)(r0 + 8) * N + c0] = hp1;
                *(uint32_t*)&Cl[(size_t)(r0 + 8) * N + c0] = lp1;
            } else {
                C[(size_t)r0 * N + c0]           = v00;
                C[(size_t)r0 * N + c0 + 1]       = v01;
                C[(size_t)(r0 + 8) * N + c0]     = v10;
                C[(size_t)(r0 + 8) * N + c0 + 1] = v11;
            }
        }
    }
}

__global__ __launch_bounds__(256, 2) void gemm_qkv(
    const __nv_bfloat16* qh, const __nv_bfloat16* ql,
    const __nv_bfloat16* wqh, const __nv_bfloat16* wql, const float* WQb,
    __nv_bfloat16* QsH, __nv_bfloat16* QsL,
    const __nv_bfloat16* kh, const __nv_bfloat16* kl,
    const __nv_bfloat16* wkh, const __nv_bfloat16* wkl, const float* WKb,
    __nv_bfloat16* KsH, __nv_bfloat16* KsL,
    const __nv_bfloat16* vh, const __nv_bfloat16* vl,
    const __nv_bfloat16* wvh, const __nv_bfloat16* wvl, const float* WVb,
    __nv_bfloat16* VsH, __nv_bfloat16* VsL)
{
    if (blockIdx.z == 0)
        gemm_body64(qh, ql, wqh, wql, WQb, nullptr, QsH, QsL, MTOT, DD, DD);
    else if (blockIdx.z == 1)
        gemm_body64(kh, kl, wkh, wkl, WKb, nullptr, KsH, KsL, MTOT, DD, DD);
    else
        gemm_body64(vh, vl, wvh, wvl, WVb, nullptr, VsH, VsL, MTOT, DD, DD);
}

__global__ __launch_bounds__(256, 2) void gemm_o(
    const __nv_bfloat16* ch, const __nv_bfloat16* cl,
    const __nv_bfloat16* woh, const __nv_bfloat16* wol, const float* WOb,
    float* out)
{
    gemm_body64(ch, cl, woh, wol, WOb, out, nullptr, nullptr, MTOT, DD, DD);
}

// ---------------- V transpose+pack ----------------
__global__ __launch_bounds__(256) void vtrans_kernel(
    const __nv_bfloat16* __restrict__ VsH, const __nv_bfloat16* __restrict__ VsL,
    uint32_t* __restrict__ vtH, uint32_t* __restrict__ vtL)
{
    const int vt = blockIdx.x & 7;
    const int h  = (blockIdx.x >> 3) % HH;
    const int b  = blockIdx.x / (8 * HH);
    const int tid = threadIdx.x;
    const size_t obase = ((size_t)(b * HH + h)) * DH * (SS / 2) + vt * 64;

    for (int i = tid; i < 1024; i += 256) {
        int s = i >> 9, r = i & 511;
        int p = r >> 3, dg = r & 7;
        const __nv_bfloat16* src = s ? VsL : VsH;
        uint32_t* dst = s ? vtL : vtH;
        size_t base = ((size_t)(b * SS) + vt * 128 + 2 * p) * DD + h * DH + dg * 8;
        uint4 w0 = *(const uint4*)&src[base];
        uint4 w1 = *(const uint4*)&src[base + DD];
        uint16_t a0[8], a1[8];
        memcpy(a0, &w0, 16);
        memcpy(a1, &w1, 16);
        #pragma unroll
        for (int j = 0; j < 8; j++)
            dst[obase + (size_t)(dg * 8 + j) * (SS / 2) + p] =
                (uint32_t)a0[j] | ((uint32_t)a1[j] << 16);
    }
}

// ---------------- fused relative attention with mma.sync ----------------
#define KP 72
#define PP 168
#define VP 84
#define WP 160
#define SSTR 1040
#define OFF_A  0
#define ASTRIDE 21504
#define OFF_Q  43008
#define QSTRIDE 4608
#define OFF_P  52224
#define PSTRIDE 10752
#define OFF_W  73728
#define OFF_S  94208
#define OFF_I  227328
#define OFF_SU 227456
#define ASM_BYTES 227584

__global__ __launch_bounds__(512) void attn_mma(
    const __nv_bfloat16* __restrict__ QsH, const __nv_bfloat16* __restrict__ QsL,
    const __nv_bfloat16* __restrict__ KsH, const __nv_bfloat16* __restrict__ KsL,
    const uint32_t* __restrict__ vtH, const uint32_t* __restrict__ vtL,
    const float* __restrict__ embK, const float* __restrict__ embV,
    float* __restrict__ attn_out,
    __nv_bfloat16* __restrict__ ctxH, __nv_bfloat16* __restrict__ ctxL)
{
    extern __shared__ char smc[];
    __nv_bfloat16* aH = (__nv_bfloat16*)(smc + OFF_A);
    __nv_bfloat16* aL = (__nv_bfloat16*)(smc + OFF_A + ASTRIDE);
    uint32_t* vH = (uint32_t*)(smc + OFF_A);
    uint32_t* vL = (uint32_t*)(smc + OFF_A + ASTRIDE);
    __nv_bfloat16* qH = (__nv_bfloat16*)(smc + OFF_Q);
    __nv_bfloat16* qL = (__nv_bfloat16*)(smc + OFF_Q + QSTRIDE);
    __nv_bfloat16* pH = (__nv_bfloat16*)(smc + OFF_P);
    __nv_bfloat16* pL = (__nv_bfloat16*)(smc + OFF_P + PSTRIDE);
    float* stg  = (float*)(smc + OFF_P);
    float* sW   = (float*)(smc + OFF_W);
    float* sS   = (float*)(smc + OFF_S);
    float* sInv = (float*)(smc + OFF_I);
    float* sSum = (float*)(smc + OFF_SU);

    const int tid = threadIdx.x;
    const int warp = tid >> 5, lane = tid & 31;
    const int g = lane >> 2, t = lane & 3;
    const int nq = SS / 32;
    const int qt = blockIdx.x % nq;
    const int h  = (blockIdx.x / nq) % HH;
    const int b  = blockIdx.x / (nq * HH);
    const int q0 = qt * 32;
    const int bh = b * HH + h;

    // ---- load Q tile ----
    {
        int i = tid;
        if (i < 512) {
            int s = i >> 8, idx = i & 255;
            int row = idx >> 3, c = (idx & 7) * 8;
            const __nv_bfloat16* src = s ? QsL : QsH;
            __nv_bfloat16* dst = s ? qL : qH;
            *(uint4*)&dst[row * KP + c] =
                *(const uint4*)&src[((size_t)(b * SS) + q0 + row) * DD + h * DH + c];
        }
    }
    // ---- load embK ----
    for (int i = tid; i < 1088; i += 512) {
        int r = i >> 3, c = (i & 7) * 8;
        float v[8] = {};
        if (r < RR) {
            float4 x = *(const float4*)&embK[(size_t)r * DD + h * DH + c];
            float4 y = *(const float4*)&embK[(size_t)r * DD + h * DH + c + 4];
            v[0]=x.x; v[1]=x.y; v[2]=x.z; v[3]=x.w; v[4]=y.x; v[5]=y.y; v[6]=y.z; v[7]=y.w;
        }
        #pragma unroll
        for (int j = 0; j < 8; j++) {
            __nv_bfloat16 hb = __float2bfloat16(v[j]);
            aH[r * KP + c + j] = hb;
            aL[r * KP + c + j] = __float2bfloat16(v[j] - __bfloat162float(hb));
        }
    }
    __syncthreads();

    // prefetch K chunk 0
    uint4 kreg[4];
    #pragma unroll
    for (int it = 0; it < 4; it++) {
        int i = tid + it * 512;
        int s = i >> 10, idx = i & 1023;
        int row = idx >> 3, c = (idx & 7) * 8;
        const __nv_bfloat16* src = s ? KsL : KsH;
        kreg[it] = *(const uint4*)&src[((size_t)(b * SS) + row) * DD + h * DH + c];
    }

    // ---- rel table ----
    for (int nt = warp; nt < 17; nt += 16) {
        float dr[2][4] = {};
        #pragma unroll
        for (int ks = 0; ks < 4; ks++) {
            int kk = ks * 16 + 2 * t;
            int rb = (nt * 8 + g) * KP;
            uint32_t bh2[2] = {*(uint32_t*)&aH[rb + kk], *(uint32_t*)&aH[rb + kk + 8]};
            uint32_t bl2[2] = {*(uint32_t*)&aL[rb + kk], *(uint32_t*)&aL[rb + kk + 8]};
            #pragma unroll
            for (int mi = 0; mi < 2; mi++) {
                int r0 = (mi * 16 + g) * KP, r1 = r0 + 8 * KP;
                uint32_t ah4[4] = {*(uint32_t*)&qH[r0 + kk], *(uint32_t*)&qH[r1 + kk],
                                   *(uint32_t*)&qH[r0 + kk + 8], *(uint32_t*)&qH[r1 + kk + 8]};
                uint32_t al4[4] = {*(uint32_t*)&qL[r0 + kk], *(uint32_t*)&qL[r1 + kk],
                                   *(uint32_t*)&qL[r0 + kk + 8], *(uint32_t*)&qL[r1 + kk + 8]};
                mma16816(dr[mi], ah4, bh2);
                mma16816(dr[mi], ah4, bl2);
                mma16816(dr[mi], al4, bh2);
            }
        }
        #pragma unroll
        for (int mi = 0; mi < 2; mi++) {
            int q = mi * 16 + g;
            int r = nt * 8 + 2 * t;
            if (r < RR)     sW[q * WP + r]           = dr[mi][0];
            if (r + 1 < RR) sW[q * WP + r + 1]       = dr[mi][1];
            if (r < RR)     sW[(q + 8) * WP + r]     = dr[mi][2];
            if (r + 1 < RR) sW[(q + 8) * WP + r + 1] = dr[mi][3];
        }
    }
    __syncthreads();

    // ---- scores: 8 chunks, reg-prefetch pipelined ----
    const float scale = 0.125f;
    for (int kt = 0; kt < 8; kt++) {
        #pragma unroll
        for (int it = 0; it < 4; it++) {
            int i = tid + it * 512;
            int s = i >> 10, idx = i & 1023;
            int row = idx >> 3, c = (idx & 7) * 8;
            __nv_bfloat16* dst = s ? aL : aH;
            *(uint4*)&dst[row * KP + c] = kreg[it];
        }
        __syncthreads();
        if (kt < 7) {
            #pragma unroll
            for (int it = 0; it < 4; it++) {
                int i = tid + it * 512;
                int s = i >> 10, idx = i & 1023;
                int row = idx >> 3, c = (idx & 7) * 8;
                const __nv_bfloat16* src = s ? KsL : KsH;
                kreg[it] = *(const uint4*)&src[((size_t)(b * SS) + (kt + 1) * 128 + row) * DD + h * DH + c];
            }
        }

        float dacc[2][4] = {};
        #pragma unroll
        for (int ks = 0; ks < 4; ks++) {
            int kk = ks * 16 + 2 * t;
            int rb = (warp * 8 + g) * KP;
            uint32_t bh2[2] = {*(uint32_t*)&aH[rb + kk], *(uint32_t*)&aH[rb + kk + 8]};
            uint32_t bl2[2] = {*(uint32_t*)&aL[rb + kk], *(uint32_t*)&aL[rb + kk + 8]};
            #pragma unroll
            for (int mi = 0; mi < 2; mi++) {
                int r0 = (mi * 16 + g) * KP, r1 = r0 + 8 * KP;
                uint32_t ah4[4] = {*(uint32_t*)&qH[r0 + kk], *(uint32_t*)&qH[r1 + kk],
                                   *(uint32_t*)&qH[r0 + kk + 8], *(uint32_t*)&qH[r1 + kk + 8]};
                uint32_t al4[4] = {*(uint32_t*)&qL[r0 + kk], *(uint32_t*)&qL[r1 + kk],
                                   *(uint32_t*)&qL[r0 + kk + 8], *(uint32_t*)&qL[r1 + kk + 8]};
                mma16816(dacc[mi], ah4, bh2);
                mma16816(dacc[mi], ah4, bl2);
                mma16816(dacc[mi], al4, bh2);
            }
        }
        #pragma unroll
        for (int mi = 0; mi < 2; mi++) {
            int q = mi * 16 + g;
            int gk = kt * 128 + warp * 8 + 2 * t;
            #pragma unroll
            for (int rr = 0; rr < 2; rr++) {
                int qq = q + rr * 8;
                int qg = q0 + qq;
                int rel0 = min(max(gk - qg,     -KWIN), KWIN) + KWIN;
                int rel1 = min(max(gk + 1 - qg, -KWIN), KWIN) + KWIN;
                sS[qq * SSTR + gk]     = (dacc[mi][rr * 2]     + sW[qq * WP + rel0]) * scale;
                sS[qq * SSTR + gk + 1] = (dacc[mi][rr * 2 + 1] + sW[qq * WP + rel1]) * scale;
            }
        }
        __syncthreads();
    }

    // prefetch V chunk 0
    uint4 vreg[4];
    #pragma unroll
    for (int it = 0; it < 4; it++) {
        int i = tid + it * 512;
        int s = i >> 10, idx = i & 1023;
        int d = idx >> 4, g4 = (idx & 15) * 4;
        const uint32_t* src = s ? vtL : vtH;
        vreg[it] = *(const uint4*)&src[((size_t)bh * DH + d) * (SS / 2) + g4];
    }

    // ---- softmax (no max pass) ----
    const int qrow = tid >> 4;
    const int s16  = tid & 15;
    {
        float* row = sS + qrow * SSTR;
        float sum = 0.f;
        for (int k4 = s16 * 4; k4 < SS; k4 += 64) {
            float4 e = *(float4*)&row[k4];
            e.x = __expf(e.x); e.y = __expf(e.y);
            e.z = __expf(e.z); e.w = __expf(e.w);
            *(float4*)&row[k4] = e;
            sum += e.x + e.y + e.z + e.w;
        }
        #pragma unroll
        for (int off = 1; off < 16; off <<= 1)
            sum += __shfl_xor_sync(0xffffffffu, sum, off, 16);
        if (s16 == 0) {
            sSum[qrow] = sum;
            sInv[qrow] = 1.f / sum;
        }
    }
    __syncthreads();

    // ---- write attn (normalized, float4) ----
    {
        float* aout = attn_out + ((size_t)bh * SS + q0) * SS;
        for (int i = tid; i < 8192; i += 512) {
            int qq = i >> 8, k4 = (i & 255) * 4;
            float4 v = *(float4*)&sS[qq * SSTR + k4];
            float s = sInv[qq];
            v.x *= s; v.y *= s; v.z *= s; v.w *= s;
            *(float4*)&aout[(size_t)qq * SS + k4] = v;
        }
    }

    // ---- w buckets (prefix-only scan; s1 derived from rowsum) ----
    {
        const int qg = q0 + qrow;
        float mid = 0.f;
        for (int r = 1 + s16; r <= 127; r += 16) {
            int k = qg - KWIN + r;
            float v = (k >= 0 && k < SS) ? sS[qrow * SSTR + k] : 0.f;
            sW[qrow * WP + r] = v;
            mid += v;
        }
        float s0 = 0.f;
        const int kmax = qg - KWIN;   // inclusive upper bound for left tail
        for (int k = s16; k <= kmax; k += 16)
            s0 += sS[qrow * SSTR + k];
        #pragma unroll
        for (int off = 1; off < 16; off <<= 1) {
            s0  += __shfl_xor_sync(0xffffffffu, s0,  off, 16);
            mid += __shfl_xor_sync(0xffffffffu, mid, off, 16);
        }
        if (s16 == 0) {
            sW[qrow * WP + 0]   = s0;
            sW[qrow * WP + 128] = sSum[qrow] - s0 - mid;
        }
        for (int i = tid; i < 32 * 31; i += 512) {
            int q = i / 31, r = 129 + (i % 31);
            sW[q * WP + r] = 0.f;
        }
    }
    __syncthreads();

    // ---- PV: 8 chunks, reg-prefetch pipelined ----
    const int wn = warp >> 1, hf = warp & 1;
    float oacc[2][4] = {};
    for (int vt = 0; vt < 8; vt++) {
        #pragma unroll
        for (int it = 0; it < 4; it++) {
            int i = tid + it * 512;
            int s = i >> 10, idx = i & 1023;
            int d = idx >> 4, g4 = (idx & 15) * 4;
            uint32_t* dst = s ? vL : vH;
            *(uint4*)&dst[d * VP + g4] = vreg[it];
        }
        for (int i = tid; i < 2048; i += 512) {
            int q = i >> 6, c2 = (i & 63) * 2;
            float2 v = *(float2*)&sS[q * SSTR + vt * 128 + c2];
            uint32_t hpk, lpk;
            asm("cvt.rn.bf16x2.f32 %0, %1, %2;" : "=r"(hpk) : "f"(v.y), "f"(v.x));
            float h0 = __uint_as_float(hpk << 16);
            float h1 = __uint_as_float(hpk & 0xffff0000u);
            asm("cvt.rn.bf16x2.f32 %0, %1, %2;" : "=r"(lpk) : "f"(v.y - h1), "f"(v.x - h0));
            *(uint32_t*)&pH[q * PP + c2] = hpk;
            *(uint32_t*)&pL[q * PP + c2] = lpk;
        }
        __syncthreads();
        if (vt < 7) {
            #pragma unroll
            for (int it = 0; it < 4; it++) {
                int i = tid + it * 512;
                int s = i >> 10, idx = i & 1023;
                int d = idx >> 4, g4 = (idx & 15) * 4;
                const uint32_t* src = s ? vtL : vtH;
                vreg[it] = *(const uint4*)&src[((size_t)bh * DH + d) * (SS / 2) + (vt + 1) * 64 + g4];
            }
        }

        #pragma unroll
        for (int ks = 0; ks < 4; ks++) {
            int kb = hf * 64 + ks * 16 + 2 * t;
            int widx = hf * 32 + ks * 8 + t;
            int vrow = (wn * 8 + g) * VP;
            uint32_t bh2[2] = {vH[vrow + widx], vH[vrow + widx + 4]};
            uint32_t bl2[2] = {vL[vrow + widx], vL[vrow + widx + 4]};
            #pragma unroll
            for (int mi = 0; mi < 2; mi++) {
                int r0 = (mi * 16 + g) * PP, r1 = r0 + 8 * PP;
                uint32_t ah4[4] = {*(uint32_t*)&pH[r0 + kb], *(uint32_t*)&pH[r1 + kb],
                                   *(uint32_t*)&pH[r0 + kb + 8], *(uint32_t*)&pH[r1 + kb + 8]};
                uint32_t al4[4] = {*(uint32_t*)&pL[r0 + kb], *(uint32_t*)&pL[r1 + kb],
                                   *(uint32_t*)&pL[r0 + kb + 8], *(uint32_t*)&pL[r1 + kb + 8]};
                mma16816(oacc[mi], ah4, bh2);
                mma16816(oacc[mi], ah4, bl2);
                mma16816(oacc[mi], al4, bh2);
            }
        }
        __syncthreads();
    }

    // ---- extra chunk: w @ embV_h ----
    {
        for (int i = tid; i < 640; i += 512) {
            int p = i >> 3, dg = i & 7;
            int r0 = 2 * p, r1 = 2 * p + 1;
            float v0[8] = {}, v1[8] = {};
            if (r0 < RR) {
                float4 x = *(const float4*)&embV[(size_t)r0 * DD + h * DH + dg * 8];
                float4 y = *(const float4*)&embV[(size_t)r0 * DD + h * DH + dg * 8 + 4];
                v0[0]=x.x; v0[1]=x.y; v0[2]=x.z; v0[3]=x.w; v0[4]=y.x; v0[5]=y.y; v0[6]=y.z; v0[7]=y.w;
            }
            if (r1 < RR) {
                float4 x = *(const float4*)&embV[(size_t)r1 * DD + h * DH + dg * 8];
                float4 y = *(const float4*)&embV[(size_t)r1 * DD + h * DH + dg * 8 + 4];
                v1[0]=x.x; v1[1]=x.y; v1[2]=x.z; v1[3]=x.w; v1[4]=y.x; v1[5]=y.y; v1[6]=y.z; v1[7]=y.w;
            }
            #pragma unroll
            for (int j = 0; j < 8; j++) {
                __nv_bfloat16 h0 = __float2bfloat16(v0[j]);
                __nv_bfloat16 h1 = __float2bfloat16(v1[j]);
                __nv_bfloat16 l0 = __float2bfloat16(v0[j] - __bfloat162float(h0));
                __nv_bfloat16 l1 = __float2bfloat16(v1[j] - __bfloat162float(h1));
                vH[(dg * 8 + j) * VP + p] =
                    (uint32_t)__bfloat16_as_ushort(h0) | ((uint32_t)__bfloat16_as_ushort(h1) << 16);
                vL[(dg * 8 + j) * VP + p] =
                    (uint32_t)__bfloat16_as_ushort(l0) | ((uint32_t)__bfloat16_as_ushort(l1) << 16);
            }
        }
        for (int i = tid; i < 2560; i += 512) {
            int q = i / 80, c2 = (i % 80) * 2;
            float2 v = *(float2*)&sW[q * WP + c2];
            uint32_t hpk, lpk;
            asm("cvt.rn.bf16x2.f32 %0, %1, %2;" : "=r"(hpk) : "f"(v.y), "f"(v.x));
            float h0 = __uint_as_float(hpk << 16);
            float h1 = __uint_as_float(hpk & 0xffff0000u);
            asm("cvt.rn.bf16x2.f32 %0, %1, %2;" : "=r"(lpk) : "f"(v.y - h1), "f"(v.x - h0));
            *(uint32_t*)&pH[q * PP + c2] = hpk;
            *(uint32_t*)&pL[q * PP + c2] = lpk;
        }
        __syncthreads();

        #pragma unroll
        for (int ks = 0; ks < 5; ks++) {
            int kb = hf * 80 + ks * 16 + 2 * t;
            int widx = hf * 40 + ks * 8 + t;
            int vrow = (wn * 8 + g) * VP;
            uint32_t bh2[2] = {vH[vrow + widx], vH[vrow + widx + 4]};
            uint32_t bl2[2] = {vL[vrow + widx], vL[vrow + widx + 4]};
            #pragma unroll
            for (int mi = 0; mi < 2; mi++) {
                int r0 = (mi * 16 + g) * PP, r1 = r0 + 8 * PP;
                uint32_t ah4[4] = {*(uint32_t*)&pH[r0 + kb], *(uint32_t*)&pH[r1 + kb],
                                   *(uint32_t*)&pH[r0 + kb + 8], *(uint32_t*)&pH[r1 + kb + 8]};
                uint32_t al4[4] = {*(uint32_t*)&pL[r0 + kb], *(uint32_t*)&pL[r1 + kb],
                                   *(uint32_t*)&pL[r0 + kb + 8], *(uint32_t*)&pL[r1 + kb + 8]};
                mma16816(oacc[mi], ah4, bh2);
                mma16816(oacc[mi], ah4, bl2);
                mma16816(oacc[mi], al4, bh2);
            }
        }
        __syncthreads();
    }

    // ---- reduce halves, normalize, write ctx as bf16 hi/lo split ----
    #pragma unroll
    for (int mi = 0; mi < 2; mi++) {
        int q = mi * 16 + g;
        int dc = wn * 8 + 2 * t;
        stg[hf * 2048 + q * 64 + dc]           = oacc[mi][0];
        stg[hf * 2048 + q * 64 + dc + 1]       = oacc[mi][1];
        stg[hf * 2048 + (q + 8) * 64 + dc]     = oacc[mi][2];
        stg[hf * 2048 + (q + 8) * 64 + dc + 1] = oacc[mi][3];
    }
    __syncthreads();
    for (int i = tid; i < 1024; i += 512) {
        int q = i >> 5, dc2 = (i & 31) * 2;
        float inv = sInv[q];
        float v0 = (stg[q * 64 + dc2]     + stg[2048 + q * 64 + dc2])     * inv;
        float v1 = (stg[q * 64 + dc2 + 1] + stg[2048 + q * 64 + dc2 + 1]) * inv;
        uint32_t hpk, lpk;
        asm("cvt.rn.bf16x2.f32 %0, %1, %2;" : "=r"(hpk) : "f"(v1), "f"(v0));
        float h0 = __uint_as_float(hpk << 16);
        float h1 = __uint_as_float(hpk & 0xffff0000u);
        asm("cvt.rn.bf16x2.f32 %0, %1, %2;" : "=r"(lpk) : "f"(v1 - h1), "f"(v0 - h0));
        size_t dst = ((size_t)(b * SS) + q0 + q) * DD + h * DH + dc2;
        *(uint32_t*)&ctxH[dst] = hpk;
        *(uint32_t*)&ctxL[dst] = lpk;
    }
}

// ---------------- launch ----------------
extern "C" void kernel_launch(void* const* d_in, const int* in_sizes, int n_in,
                              void* d_out, int out_size)
{
    const float* query = (const float*)d_in[0];
    const float* key   = (const float*)d_in[1];
    const float* value = (const float*)d_in[2];
    const float* WQ_w  = (const float*)d_in[3];
    const float* WQ_b  = (const float*)d_in[4];
    const float* WK_w  = (const float*)d_in[5];
    const float* WK_b  = (const float*)d_in[6];
    const float* WV_w  = (const float*)d_in[7];
    const float* WV_b  = (const float*)d_in[8];
    const float* WO_w  = (const float*)d_in[9];
    const float* WO_b  = (const float*)d_in[10];
    const float* embK  = (const float*)d_in[11];
    const float* embV  = (const float*)d_in[12];

    float* out = (float*)d_out;                       // [B,S,D]
    float* attn = out + (size_t)BB * SS * DD;         // [B,H,S,S]

    static float *Qp = nullptr, *Kp, *Vp;
    static __nv_bfloat16 *qh, *ql, *kh, *kl, *vh, *vl, *ch, *cl;
    static __nv_bfloat16 *wqh, *wql, *wkh, *wkl, *wvh, *wvl, *woh, *wol;
    static uint32_t *vtH, *vtL;
    if (!Qp) {
        cudaGetSymbolAddress((void**)&Qp, g_Qp);
        cudaGetSymbolAddress((void**)&Kp, g_Kp);
        cudaGetSymbolAddress((void**)&Vp, g_Vp);
        cudaGetSymbolAddress((void**)&qh, g_qh);   cudaGetSymbolAddress((void**)&ql, g_ql);
        cudaGetSymbolAddress((void**)&kh, g_kh);   cudaGetSymbolAddress((void**)&kl, g_kl);
        cudaGetSymbolAddress((void**)&vh, g_vh);   cudaGetSymbolAddress((void**)&vl, g_vl);
        cudaGetSymbolAddress((void**)&ch, g_ch);   cudaGetSymbolAddress((void**)&cl, g_cl);
        cudaGetSymbolAddress((void**)&wqh, g_wqh); cudaGetSymbolAddress((void**)&wql, g_wql);
        cudaGetSymbolAddress((void**)&wkh, g_wkh); cudaGetSymbolAddress((void**)&wkl, g_wkl);
        cudaGetSymbolAddress((void**)&wvh, g_wvh); cudaGetSymbolAddress((void**)&wvl, g_wvl);
        cudaGetSymbolAddress((void**)&woh, g_woh); cudaGetSymbolAddress((void**)&wol, g_wol);
        cudaGetSymbolAddress((void**)&vtH, g_vtH); cudaGetSymbolAddress((void**)&vtL, g_vtL);
        cudaFuncSetAttribute(attn_mma,
                             cudaFuncAttributeMaxDynamicSharedMemorySize, ASM_BYTES);
        cudaFuncSetAttribute(gemm_qkv,
                             cudaFuncAttributeMaxDynamicSharedMemorySize, GSMB);
        cudaFuncSetAttribute(gemm_o,
                             cudaFuncAttributeMaxDynamicSharedMemorySize, GSMB);
    }

    __nv_bfloat16* QsH = (__nv_bfloat16*)Qp;  __nv_bfloat16* QsL = QsH + (size_t)MTOT * DD;
    __nv_bfloat16* KsH = (__nv_bfloat16*)Kp;  __nv_bfloat16* KsL = KsH + (size_t)MTOT * DD;
    __nv_bfloat16* VsH = (__nv_bfloat16*)Vp;  __nv_bfloat16* VsL = VsH + (size_t)MTOT * DD;

    const int NIN = MTOT * DD;
    const int NW  = DD * DD;

    // launch 0: all splits in one kernel (y 0..2 inputs, 3..6 weights)
    split_all_kernel<<<dim3(NIN / 4 / 256, 7), 256>>>(
        query, qh, ql, key, kh, kl, value, vh, vl,
        WQ_w, wqh, wql, WK_w, wkh, wkl, WV_w, wvh, wvl, WO_w, woh, wol,
        NIN, NW);
    // launch 1
    gemm_qkv<<<dim3(DD / 128, MTOT / 64, 3), 256, GSMB>>>(
        qh, ql, wqh, wql, WQ_b, QsH, QsL,
        kh, kl, wkh, wkl, WK_b, KsH, KsL,
        vh, vl, wvh, wvl, WV_b, VsH, VsL);
    // launch 2
    vtrans_kernel<<<BB * HH * 8, 256>>>(VsH, VsL, vtH, vtL);
    // launch 3  (profiled by ncu next round)
    attn_mma<<<BB * HH * (SS / 32), 512, ASM_BYTES>>>(
        QsH, QsL, KsH, KsL, vtH, vtL, embK, embV, attn, ch, cl);
    // launch 4
    gemm_o<<<dim3(DD / 128, MTOT / 64), 256, GSMB>>>(ch, cl, woh, wol, WO_b, out);
}

// round 13
// speedup vs baseline: 3.2741x; 1.0384x over previous
#include <cuda_runtime.h>
#include <cuda_bf16.h>
#include <cstdint>
#include <cstring>

// Problem constants
#define BB 4
#define SS 1024
#define DD 768
#define HH 12
#define DH 64
#define RR 129          // 2K+1, K=64
#define KWIN 64

#define MTOT (BB * SS)  // 4096

// ---------------- scratch (no allocation allowed) ----------------
__device__ float g_Qp[MTOT * DD];      // reinterpreted: bf16 QsH/QsL
__device__ float g_Kp[MTOT * DD];      // reinterpreted: bf16 KsH/KsL
__device__ float g_Vp[MTOT * DD];      // reinterpreted: bf16 VsH/VsL

__device__ __nv_bfloat16 g_qh[MTOT * DD],  g_ql[MTOT * DD];
__device__ __nv_bfloat16 g_kh[MTOT * DD],  g_kl[MTOT * DD];
__device__ __nv_bfloat16 g_vh[MTOT * DD],  g_vl[MTOT * DD];
__device__ __nv_bfloat16 g_ch[MTOT * DD],  g_cl[MTOT * DD];
__device__ __nv_bfloat16 g_wqh[DD * DD], g_wql[DD * DD];
__device__ __nv_bfloat16 g_wkh[DD * DD], g_wkl[DD * DD];
__device__ __nv_bfloat16 g_wvh[DD * DD], g_wvl[DD * DD];
__device__ __nv_bfloat16 g_woh[DD * DD], g_wol[DD * DD];

// packed V^T: [b*HH+h][d(64)][pair(512)]
__device__ uint32_t g_vtH[BB * HH * DH * (SS / 2)];
__device__ uint32_t g_vtL[BB * HH * DH * (SS / 2)];

// ---------------- cp.async helpers ----------------
__device__ __forceinline__ uint32_t smem_u32(const void* p) {
    uint32_t a;
    asm("{ .reg .u64 t; cvta.to.shared.u64 t, %1; cvt.u32.u64 %0, t; }"
        : "=r"(a) : "l"(p));
    return a;
}
#define CP_ASYNC16(sa, ga) \
    asm volatile("cp.async.cg.shared.global [%0], [%1], 16;" :: "r"(sa), "l"(ga))
#define CP_COMMIT() asm volatile("cp.async.commit_group;" ::: "memory")
#define CP_WAIT1()  asm volatile("cp.async.wait_group 1;" ::: "memory")
#define CP_WAIT0()  asm volatile("cp.async.wait_group 0;" ::: "memory")

// ---------------- fp32 -> bf16 hi/lo split ----------------
__device__ __forceinline__ void split4(const float* __restrict__ x,
                                       __nv_bfloat16* __restrict__ hi,
                                       __nv_bfloat16* __restrict__ lo, int i)
{
    float4 v = *(const float4*)&x[i];
    float vv[4] = {v.x, v.y, v.z, v.w};
    uint16_t h[4], l[4];
    #pragma unroll
    for (int p = 0; p < 4; p++) {
        __nv_bfloat16 hb = __float2bfloat16(vv[p]);
        __nv_bfloat16 lb = __float2bfloat16(vv[p] - __bfloat162float(hb));
        h[p] = __bfloat16_as_ushort(hb);
        l[p] = __bfloat16_as_ushort(lb);
    }
    *(uint2*)&hi[i] = make_uint2(((uint32_t)h[1] << 16) | h[0], ((uint32_t)h[3] << 16) | h[2]);
    *(uint2*)&lo[i] = make_uint2(((uint32_t)l[1] << 16) | l[0], ((uint32_t)l[3] << 16) | l[2]);
}

__global__ __launch_bounds__(256) void split_all_kernel(
    const float* __restrict__ i0, __nv_bfloat16* i0h, __nv_bfloat16* i0l,
    const float* __restrict__ i1, __nv_bfloat16* i1h, __nv_bfloat16* i1l,
    const float* __restrict__ i2, __nv_bfloat16* i2h, __nv_bfloat16* i2l,
    const float* __restrict__ w0, __nv_bfloat16* w0h, __nv_bfloat16* w0l,
    const float* __restrict__ w1, __nv_bfloat16* w1h, __nv_bfloat16* w1l,
    const float* __restrict__ w2, __nv_bfloat16* w2h, __nv_bfloat16* w2l,
    const float* __restrict__ w3, __nv_bfloat16* w3h, __nv_bfloat16* w3l,
    int nin, int nw)
{
    int i = (blockIdx.x * 256 + threadIdx.x) * 4;
    int y = blockIdx.y;
    int n = (y < 3) ? nin : nw;
    if (i >= n) return;
    const float* x; __nv_bfloat16 *hi, *lo;
    switch (y) {
        case 0: x = i0; hi = i0h; lo = i0l; break;
        case 1: x = i1; hi = i1h; lo = i1l; break;
        case 2: x = i2; hi = i2h; lo = i2l; break;
        case 3: x = w0; hi = w0h; lo = w0l; break;
        case 4: x = w1; hi = w1h; lo = w1l; break;
        case 5: x = w2; hi = w2h; lo = w2l; break;
        default: x = w3; hi = w3h; lo = w3l; break;
    }
    split4(x, hi, lo, i);
}

// ---------------- mma.sync helper ----------------
__device__ __forceinline__ void mma16816(float* d, const uint32_t* a, const uint32_t* b) {
    asm volatile("mma.sync.aligned.m16n8k16.row.col.f32.bf16.bf16.f32 "
        "{%0,%1,%2,%3}, {%4,%5,%6,%7}, {%8,%9}, {%0,%1,%2,%3};"
        : "+f"(d[0]), "+f"(d[1]), "+f"(d[2]), "+f"(d[3])
        : "r"(a[0]), "r"(a[1]), "r"(a[2]), "r"(a[3]), "r"(b[0]), "r"(b[1]));
}

// ---------------- bf16-split GEMM, 64x128 tile, cp.async 2-stage ----------------
#define SP 40
#define AARR 5120
#define WARR 10240
#define GBUF 30720
#define GSMB (2 * GBUF)

__device__ __forceinline__ void gemm_issue64(
    uint32_t sb, int buf, int tid, int bm, int bn, int k0, int Kd,
    const __nv_bfloat16* __restrict__ Ah, const __nv_bfloat16* __restrict__ Al,
    const __nv_bfloat16* __restrict__ Wh, const __nv_bfloat16* __restrict__ Wl)
{
    uint32_t bo = sb + buf * GBUF;
    {
        int rowA = tid >> 2, cc = (tid & 3) * 8;
        size_t ga = (size_t)(bm + rowA) * Kd + k0 + cc;
        uint32_t so = (uint32_t)(rowA * SP + cc) * 2;
        CP_ASYNC16(bo + so,        Ah + ga);
        CP_ASYNC16(bo + AARR + so, Al + ga);
    }
    #pragma unroll
    for (int it = 0; it < 2; it++) {
        int i = tid + it * 256;
        int rowW = i >> 2, cc = (i & 3) * 8;
        size_t gw = (size_t)(bn + rowW) * Kd + k0 + cc;
        uint32_t so = (uint32_t)(rowW * SP + cc) * 2;
        CP_ASYNC16(bo + 2 * AARR + so,        Wh + gw);
        CP_ASYNC16(bo + 2 * AARR + WARR + so, Wl + gw);
    }
    CP_COMMIT();
}

__device__ __forceinline__ void gemm_body64(
    const __nv_bfloat16* __restrict__ Ah, const __nv_bfloat16* __restrict__ Al,
    const __nv_bfloat16* __restrict__ Wh, const __nv_bfloat16* __restrict__ Wl,
    const float* __restrict__ bias, float* __restrict__ C,
    __nv_bfloat16* __restrict__ Ch, __nv_bfloat16* __restrict__ Cl,
    int M, int N, int Kd)
{
    extern __shared__ char gsm[];
    uint32_t sb = smem_u32(gsm);

    const int tid = threadIdx.x;
    const int bm = blockIdx.y * 64, bn = blockIdx.x * 128;
    const int warp = tid >> 5, lane = tid & 31;
    const int wm = warp & 1, wn = warp >> 1;
    const int g = lane >> 2, t = lane & 3;

    float d[2][4][4] = {};

    const int nch = Kd / 32;
    gemm_issue64(sb, 0, tid, bm, bn, 0, Kd, Ah, Al, Wh, Wl);

    for (int c = 0; c < nch; c++) {
        if (c + 1 < nch) {
            gemm_issue64(sb, (c + 1) & 1, tid, bm, bn, (c + 1) * 32, Kd, Ah, Al, Wh, Wl);
            CP_WAIT1();
        } else {
            CP_WAIT0();
        }
        __syncthreads();

        const char* st = gsm + (c & 1) * GBUF;
        const __nv_bfloat16* sAh = (const __nv_bfloat16*)st;
        const __nv_bfloat16* sAl = (const __nv_bfloat16*)(st + AARR);
        const __nv_bfloat16* sWh = (const __nv_bfloat16*)(st + 2 * AARR);
        const __nv_bfloat16* sWl = (const __nv_bfloat16*)(st + 2 * AARR + WARR);

        #pragma unroll
        for (int ks = 0; ks < 2; ks++) {
            const int kk = ks * 16 + 2 * t;
            uint32_t bh[4][2], bl[4][2];
            #pragma unroll
            for (int ni = 0; ni < 4; ni++) {
                int rb = (wn * 32 + ni * 8 + g) * SP;
                bh[ni][0] = *(const uint32_t*)&sWh[rb + kk];
                bh[ni][1] = *(const uint32_t*)&sWh[rb + kk + 8];
                bl[ni][0] = *(const uint32_t*)&sWl[rb + kk];
                bl[ni][1] = *(const uint32_t*)&sWl[rb + kk + 8];
            }
            #pragma unroll
            for (int mi = 0; mi < 2; mi++) {
                int r0 = (wm * 32 + mi * 16 + g) * SP;
                int r1 = r0 + 8 * SP;
                uint32_t ah[4], al[4];
                ah[0] = *(const uint32_t*)&sAh[r0 + kk];
                ah[1] = *(const uint32_t*)&sAh[r1 + kk];
                ah[2] = *(const uint32_t*)&sAh[r0 + kk + 8];
                ah[3] = *(const uint32_t*)&sAh[r1 + kk + 8];
                al[0] = *(const uint32_t*)&sAl[r0 + kk];
                al[1] = *(const uint32_t*)&sAl[r1 + kk];
                al[2] = *(const uint32_t*)&sAl[r0 + kk + 8];
                al[3] = *(const uint32_t*)&sAl[r1 + kk + 8];
                #pragma unroll
                for (int ni = 0; ni < 4; ni++) {
                    mma16816(d[mi][ni], ah, bh[ni]);
                    mma16816(d[mi][ni], ah, bl[ni]);
                    mma16816(d[mi][ni], al, bh[ni]);
                }
            }
        }
        __syncthreads();
    }

    #pragma unroll
    for (int mi = 0; mi < 2; mi++) {
        int r0 = bm + wm * 32 + mi * 16 + g;
        #pragma unroll
        for (int ni = 0; ni < 4; ni++) {
            int c0 = bn + wn * 32 + ni * 8 + 2 * t;
            float b0 = bias[c0], b1 = bias[c0 + 1];
            float v00 = d[mi][ni][0] + b0, v01 = d[mi][ni][1] + b1;
            float v10 = d[mi][ni][2] + b0, v11 = d[mi][ni][3] + b1;
            if (Ch) {
                uint32_t hp0, lp0, hp1, lp1;
                asm("cvt.rn.bf16x2.f32 %0, %1, %2;" : "=r"(hp0) : "f"(v01), "f"(v00));
                asm("cvt.rn.bf16x2.f32 %0, %1, %2;" : "=r"(hp1) : "f"(v11), "f"(v10));
                float h00 = __uint_as_float(hp0 << 16);
                float h01 = __uint_as_float(hp0 & 0xffff0000u);
                float h10 = __uint_as_float(hp1 << 16);
                float h11 = __uint_as_float(hp1 & 0xffff0000u);
                asm("cvt.rn.bf16x2.f32 %0, %1, %2;" : "=r"(lp0) : "f"(v01 - h01), "f"(v00 - h00));
                asm("cvt.rn.bf16x2.f32 %0, %1, %2;" : "=r"(lp1) : "f"(v11 - h11), "f"(v10 - h10));
                *(uint32_t*)&Ch[(size_t)r0 * N + c0]       = hp0;
                *(uint32_t*)&Cl[(size_t)r0 * N + c0]       = lp0;
                *(uint32_t*)&Ch[(size_t)(r0 + 8) * N + c0] = hp1;
                *(uint32_t*)&Cl[(size_t)(r0 + 8) * N + c0] = lp1;
            } else {
                C[(size_t)r0 * N + c0]           = v00;
                C[(size_t)r0 * N + c0 + 1]       = v01;
                C[(size_t)(r0 + 8) * N + c0]     = v10;
                C[(size_t)(r0 + 8) * N + c0 + 1] = v11;
            }
        }
    }
}

__global__ __launch_bounds__(256, 2) void gemm_qkv(
    const __nv_bfloat16* qh, const __nv_bfloat16* ql,
    const __nv_bfloat16* wqh, const __nv_bfloat16* wql, const float* WQb,
    __nv_bfloat16* QsH, __nv_bfloat16* QsL,
    const __nv_bfloat16* kh, const __nv_bfloat16* kl,
    const __nv_bfloat16* wkh, const __nv_bfloat16* wkl, const float* WKb,
    __nv_bfloat16* KsH, __nv_bfloat16* KsL,
    const __nv_bfloat16* vh, const __nv_bfloat16* vl,
    const __nv_bfloat16* wvh, const __nv_bfloat16* wvl, const float* WVb,
    __nv_bfloat16* VsH, __nv_bfloat16* VsL)
{
    if (blockIdx.z == 0)
        gemm_body64(qh, ql, wqh, wql, WQb, nullptr, QsH, QsL, MTOT, DD, DD);
    else if (blockIdx.z == 1)
        gemm_body64(kh, kl, wkh, wkl, WKb, nullptr, KsH, KsL, MTOT, DD, DD);
    else
        gemm_body64(vh, vl, wvh, wvl, WVb, nullptr, VsH, VsL, MTOT, DD, DD);
}

__global__ __launch_bounds__(256, 2) void gemm_o(
    const __nv_bfloat16* ch, const __nv_bfloat16* cl,
    const __nv_bfloat16* woh, const __nv_bfloat16* wol, const float* WOb,
    float* out)
{
    gemm_body64(ch, cl, woh, wol, WOb, out, nullptr, nullptr, MTOT, DD, DD);
}

// ---------------- V transpose+pack ----------------
__global__ __launch_bounds__(256) void vtrans_kernel(
    const __nv_bfloat16* __restrict__ VsH, const __nv_bfloat16* __restrict__ VsL,
    uint32_t* __restrict__ vtH, uint32_t* __restrict__ vtL)
{
    const int vt = blockIdx.x & 7;
    const int h  = (blockIdx.x >> 3) % HH;
    const int b  = blockIdx.x / (8 * HH);
    const int tid = threadIdx.x;
    const size_t obase = ((size_t)(b * HH + h)) * DH * (SS / 2) + vt * 64;

    for (int i = tid; i < 1024; i += 256) {
        int s = i >> 9, r = i & 511;
        int p = r >> 3, dg = r & 7;
        const __nv_bfloat16* src = s ? VsL : VsH;
        uint32_t* dst = s ? vtL : vtH;
        size_t base = ((size_t)(b * SS) + vt * 128 + 2 * p) * DD + h * DH + dg * 8;
        uint4 w0 = *(const uint4*)&src[base];
        uint4 w1 = *(const uint4*)&src[base + DD];
        uint16_t a0[8], a1[8];
        memcpy(a0, &w0, 16);
        memcpy(a1, &w1, 16);
        #pragma unroll
        for (int j = 0; j < 8; j++)
            dst[obase + (size_t)(dg * 8 + j) * (SS / 2) + p] =
                (uint32_t)a0[j] | ((uint32_t)a1[j] << 16);
    }
}

// ---------------- fused relative attention with mma.sync ----------------
#define KP 72
#define PP 168
#define VP 84
#define WP 160
#define SSTR 1040
#define OFF_A  0
#define ASTRIDE 21504
#define OFF_Q  43008
#define QSTRIDE 4608
#define OFF_P  52224
#define PSTRIDE 10752
#define OFF_W  73728
#define OFF_S  94208
#define OFF_I  227328
#define OFF_SU 227456
#define ASM_BYTES 227584

__global__ __launch_bounds__(512) void attn_mma(
    const __nv_bfloat16* __restrict__ QsH, const __nv_bfloat16* __restrict__ QsL,
    const __nv_bfloat16* __restrict__ KsH, const __nv_bfloat16* __restrict__ KsL,
    const uint32_t* __restrict__ vtH, const uint32_t* __restrict__ vtL,
    const float* __restrict__ embK, const float* __restrict__ embV,
    float* __restrict__ attn_out,
    __nv_bfloat16* __restrict__ ctxH, __nv_bfloat16* __restrict__ ctxL)
{
    extern __shared__ char smc[];
    __nv_bfloat16* aH = (__nv_bfloat16*)(smc + OFF_A);
    __nv_bfloat16* aL = (__nv_bfloat16*)(smc + OFF_A + ASTRIDE);
    uint32_t* vH = (uint32_t*)(smc + OFF_A);
    uint32_t* vL = (uint32_t*)(smc + OFF_A + ASTRIDE);
    __nv_bfloat16* qH = (__nv_bfloat16*)(smc + OFF_Q);
    __nv_bfloat16* qL = (__nv_bfloat16*)(smc + OFF_Q + QSTRIDE);
    __nv_bfloat16* pH = (__nv_bfloat16*)(smc + OFF_P);
    __nv_bfloat16* pL = (__nv_bfloat16*)(smc + OFF_P + PSTRIDE);
    float* stg  = (float*)(smc + OFF_P);
    float* sW   = (float*)(smc + OFF_W);
    float* sS   = (float*)(smc + OFF_S);
    float* sInv = (float*)(smc + OFF_I);
    float* sSum = (float*)(smc + OFF_SU);

    const int tid = threadIdx.x;
    const int warp = tid >> 5, lane = tid & 31;
    const int g = lane >> 2, t = lane & 3;
    const int nq = SS / 32;
    const int qt = blockIdx.x % nq;
    const int h  = (blockIdx.x / nq) % HH;
    const int b  = blockIdx.x / (nq * HH);
    const int q0 = qt * 32;
    const int bh = b * HH + h;

    // ---- load Q tile ----
    {
        int i = tid;
        if (i < 512) {
            int s = i >> 8, idx = i & 255;
            int row = idx >> 3, c = (idx & 7) * 8;
            const __nv_bfloat16* src = s ? QsL : QsH;
            __nv_bfloat16* dst = s ? qL : qH;
            *(uint4*)&dst[row * KP + c] =
                *(const uint4*)&src[((size_t)(b * SS) + q0 + row) * DD + h * DH + c];
        }
    }
    // ---- load embK ----
    for (int i = tid; i < 1088; i += 512) {
        int r = i >> 3, c = (i & 7) * 8;
        float v[8] = {};
        if (r < RR) {
            float4 x = *(const float4*)&embK[(size_t)r * DD + h * DH + c];
            float4 y = *(const float4*)&embK[(size_t)r * DD + h * DH + c + 4];
            v[0]=x.x; v[1]=x.y; v[2]=x.z; v[3]=x.w; v[4]=y.x; v[5]=y.y; v[6]=y.z; v[7]=y.w;
        }
        #pragma unroll
        for (int j = 0; j < 8; j++) {
            __nv_bfloat16 hb = __float2bfloat16(v[j]);
            aH[r * KP + c + j] = hb;
            aL[r * KP + c + j] = __float2bfloat16(v[j] - __bfloat162float(hb));
        }
    }
    __syncthreads();

    // ---- hoist Q-hi fragments to registers (reused by rel table + all chunks) ----
    uint32_t qfh[4][2][4];
    #pragma unroll
    for (int ks = 0; ks < 4; ks++) {
        int kk = ks * 16 + 2 * t;
        #pragma unroll
        for (int mi = 0; mi < 2; mi++) {
            int r0 = (mi * 16 + g) * KP, r1 = r0 + 8 * KP;
            qfh[ks][mi][0] = *(uint32_t*)&qH[r0 + kk];
            qfh[ks][mi][1] = *(uint32_t*)&qH[r1 + kk];
            qfh[ks][mi][2] = *(uint32_t*)&qH[r0 + kk + 8];
            qfh[ks][mi][3] = *(uint32_t*)&qH[r1 + kk + 8];
        }
    }

    // prefetch K chunk 0
    uint4 kreg[4];
    #pragma unroll
    for (int it = 0; it < 4; it++) {
        int i = tid + it * 512;
        int s = i >> 10, idx = i & 1023;
        int row = idx >> 3, c = (idx & 7) * 8;
        const __nv_bfloat16* src = s ? KsL : KsH;
        kreg[it] = *(const uint4*)&src[((size_t)(b * SS) + row) * DD + h * DH + c];
    }

    // ---- rel table ----
    for (int nt = warp; nt < 17; nt += 16) {
        float dr[2][4] = {};
        #pragma unroll
        for (int ks = 0; ks < 4; ks++) {
            int kk = ks * 16 + 2 * t;
            int rb = (nt * 8 + g) * KP;
            uint32_t bh2[2] = {*(uint32_t*)&aH[rb + kk], *(uint32_t*)&aH[rb + kk + 8]};
            uint32_t bl2[2] = {*(uint32_t*)&aL[rb + kk], *(uint32_t*)&aL[rb + kk + 8]};
            #pragma unroll
            for (int mi = 0; mi < 2; mi++) {
                int r0 = (mi * 16 + g) * KP, r1 = r0 + 8 * KP;
                uint32_t al4[4] = {*(uint32_t*)&qL[r0 + kk], *(uint32_t*)&qL[r1 + kk],
                                   *(uint32_t*)&qL[r0 + kk + 8], *(uint32_t*)&qL[r1 + kk + 8]};
                mma16816(dr[mi], qfh[ks][mi], bh2);
                mma16816(dr[mi], qfh[ks][mi], bl2);
                mma16816(dr[mi], al4, bh2);
            }
        }
        #pragma unroll
        for (int mi = 0; mi < 2; mi++) {
            int q = mi * 16 + g;
            int r = nt * 8 + 2 * t;
            if (r < RR)     sW[q * WP + r]           = dr[mi][0];
            if (r + 1 < RR) sW[q * WP + r + 1]       = dr[mi][1];
            if (r < RR)     sW[(q + 8) * WP + r]     = dr[mi][2];
            if (r + 1 < RR) sW[(q + 8) * WP + r + 1] = dr[mi][3];
        }
    }
    __syncthreads();

    // ---- scores: 8 chunks, reg-prefetch pipelined ----
    const float scale = 0.125f;
    for (int kt = 0; kt < 8; kt++) {
        #pragma unroll
        for (int it = 0; it < 4; it++) {
            int i = tid + it * 512;
            int s = i >> 10, idx = i & 1023;
            int row = idx >> 3, c = (idx & 7) * 8;
            __nv_bfloat16* dst = s ? aL : aH;
            *(uint4*)&dst[row * KP + c] = kreg[it];
        }
        __syncthreads();
        if (kt < 7) {
            #pragma unroll
            for (int it = 0; it < 4; it++) {
                int i = tid + it * 512;
                int s = i >> 10, idx = i & 1023;
                int row = idx >> 3, c = (idx & 7) * 8;
                const __nv_bfloat16* src = s ? KsL : KsH;
                kreg[it] = *(const uint4*)&src[((size_t)(b * SS) + (kt + 1) * 128 + row) * DD + h * DH + c];
            }
        }

        float dacc[2][4] = {};
        #pragma unroll
        for (int ks = 0; ks < 4; ks++) {
            int kk = ks * 16 + 2 * t;
            int rb = (warp * 8 + g) * KP;
            uint32_t bh2[2] = {*(uint32_t*)&aH[rb + kk], *(uint32_t*)&aH[rb + kk + 8]};
            uint32_t bl2[2] = {*(uint32_t*)&aL[rb + kk], *(uint32_t*)&aL[rb + kk + 8]};
            #pragma unroll
            for (int mi = 0; mi < 2; mi++) {
                int r0 = (mi * 16 + g) * KP, r1 = r0 + 8 * KP;
                uint32_t al4[4] = {*(uint32_t*)&qL[r0 + kk], *(uint32_t*)&qL[r1 + kk],
                                   *(uint32_t*)&qL[r0 + kk + 8], *(uint32_t*)&qL[r1 + kk + 8]};
                mma16816(dacc[mi], qfh[ks][mi], bh2);
                mma16816(dacc[mi], qfh[ks][mi], bl2);
                mma16816(dacc[mi], al4, bh2);
            }
        }
        #pragma unroll
        for (int mi = 0; mi < 2; mi++) {
            int q = mi * 16 + g;
            int gk = kt * 128 + warp * 8 + 2 * t;
            #pragma unroll
            for (int rr = 0; rr < 2; rr++) {
                int qq = q + rr * 8;
                int qg = q0 + qq;
                int rel0 = min(max(gk - qg,     -KWIN), KWIN) + KWIN;
                int rel1 = min(max(gk + 1 - qg, -KWIN), KWIN) + KWIN;
                sS[qq * SSTR + gk]     = (dacc[mi][rr * 2]     + sW[qq * WP + rel0]) * scale;
                sS[qq * SSTR + gk + 1] = (dacc[mi][rr * 2 + 1] + sW[qq * WP + rel1]) * scale;
            }
        }
        __syncthreads();
    }

    // prefetch V chunk 0
    uint4 vreg[4];
    #pragma unroll
    for (int it = 0; it < 4; it++) {
        int i = tid + it * 512;
        int s = i >> 10, idx = i & 1023;
        int d = idx >> 4, g4 = (idx & 15) * 4;
        const uint32_t* src = s ? vtL : vtH;
        vreg[it] = *(const uint4*)&src[((size_t)bh * DH + d) * (SS / 2) + g4];
    }

    // ---- softmax (no max pass) ----
    const int qrow = tid >> 4;
    const int s16  = tid & 15;
    {
        float* row = sS + qrow * SSTR;
        float sum = 0.f;
        for (int k4 = s16 * 4; k4 < SS; k4 += 64) {
            float4 e = *(float4*)&row[k4];
            e.x = __expf(e.x); e.y = __expf(e.y);
            e.z = __expf(e.z); e.w = __expf(e.w);
            *(float4*)&row[k4] = e;
            sum += e.x + e.y + e.z + e.w;
        }
        #pragma unroll
        for (int off = 1; off < 16; off <<= 1)
            sum += __shfl_xor_sync(0xffffffffu, sum, off, 16);
        if (s16 == 0) {
            sSum[qrow] = sum;
            sInv[qrow] = 1.f / sum;
        }
    }
    __syncthreads();

    // ---- write attn (normalized, float4) ----
    {
        float* aout = attn_out + ((size_t)bh * SS + q0) * SS;
        for (int i = tid; i < 8192; i += 512) {
            int qq = i >> 8, k4 = (i & 255) * 4;
            float4 v = *(float4*)&sS[qq * SSTR + k4];
            float s = sInv[qq];
            v.x *= s; v.y *= s; v.z *= s; v.w *= s;
            *(float4*)&aout[(size_t)qq * SS + k4] = v;
        }
    }

    // ---- w buckets (prefix-only scan; s1 derived from rowsum) ----
    {
        const int qg = q0 + qrow;
        float mid = 0.f;
        for (int r = 1 + s16; r <= 127; r += 16) {
            int k = qg - KWIN + r;
            float v = (k >= 0 && k < SS) ? sS[qrow * SSTR + k] : 0.f;
            sW[qrow * WP + r] = v;
            mid += v;
        }
        float s0 = 0.f;
        const int kmax = qg - KWIN;
        for (int k = s16; k <= kmax; k += 16)
            s0 += sS[qrow * SSTR + k];
        #pragma unroll
        for (int off = 1; off < 16; off <<= 1) {
            s0  += __shfl_xor_sync(0xffffffffu, s0,  off, 16);
            mid += __shfl_xor_sync(0xffffffffu, mid, off, 16);
        }
        if (s16 == 0) {
            sW[qrow * WP + 0]   = s0;
            sW[qrow * WP + 128] = sSum[qrow] - s0 - mid;
        }
        for (int i = tid; i < 32 * 31; i += 512) {
            int q = i / 31, r = 129 + (i % 31);
            sW[q * WP + r] = 0.f;
        }
    }
    __syncthreads();

    // ---- PV: 8 chunks; warp = (wn 0..3: 16 d-cols, hf 0..3: k-quarter) ----
    const int wn = warp >> 2, hf = warp & 3;
    float oacc[2][2][4] = {};
    for (int vt = 0; vt < 8; vt++) {
        #pragma unroll
        for (int it = 0; it < 4; it++) {
            int i = tid + it * 512;
            int s = i >> 10, idx = i & 1023;
            int d = idx >> 4, g4 = (idx & 15) * 4;
            uint32_t* dst = s ? vL : vH;
            *(uint4*)&dst[d * VP + g4] = vreg[it];
        }
        for (int i = tid; i < 2048; i += 512) {
            int q = i >> 6, c2 = (i & 63) * 2;
            float2 v = *(float2*)&sS[q * SSTR + vt * 128 + c2];
            uint32_t hpk, lpk;
            asm("cvt.rn.bf16x2.f32 %0, %1, %2;" : "=r"(hpk) : "f"(v.y), "f"(v.x));
            float h0 = __uint_as_float(hpk << 16);
            float h1 = __uint_as_float(hpk & 0xffff0000u);
            asm("cvt.rn.bf16x2.f32 %0, %1, %2;" : "=r"(lpk) : "f"(v.y - h1), "f"(v.x - h0));
            *(uint32_t*)&pH[q * PP + c2] = hpk;
            *(uint32_t*)&pL[q * PP + c2] = lpk;
        }
        __syncthreads();
        if (vt < 7) {
            #pragma unroll
            for (int it = 0; it < 4; it++) {
                int i = tid + it * 512;
                int s = i >> 10, idx = i & 1023;
                int d = idx >> 4, g4 = (idx & 15) * 4;
                const uint32_t* src = s ? vtL : vtH;
                vreg[it] = *(const uint4*)&src[((size_t)bh * DH + d) * (SS / 2) + (vt + 1) * 64 + g4];
            }
        }

        #pragma unroll
        for (int ks = 0; ks < 2; ks++) {
            int kb = hf * 32 + ks * 16 + 2 * t;
            int widx = hf * 16 + ks * 8 + t;
            uint32_t bh2[2][2], bl2[2][2];
            #pragma unroll
            for (int ni = 0; ni < 2; ni++) {
                int vrow = (wn * 16 + ni * 8 + g) * VP;
                bh2[ni][0] = vH[vrow + widx];  bh2[ni][1] = vH[vrow + widx + 4];
                bl2[ni][0] = vL[vrow + widx];  bl2[ni][1] = vL[vrow + widx + 4];
            }
            #pragma unroll
            for (int mi = 0; mi < 2; mi++) {
                int r0 = (mi * 16 + g) * PP, r1 = r0 + 8 * PP;
                uint32_t ah4[4] = {*(uint32_t*)&pH[r0 + kb], *(uint32_t*)&pH[r1 + kb],
                                   *(uint32_t*)&pH[r0 + kb + 8], *(uint32_t*)&pH[r1 + kb + 8]};
                uint32_t al4[4] = {*(uint32_t*)&pL[r0 + kb], *(uint32_t*)&pL[r1 + kb],
                                   *(uint32_t*)&pL[r0 + kb + 8], *(uint32_t*)&pL[r1 + kb + 8]};
                #pragma unroll
                for (int ni = 0; ni < 2; ni++) {
                    mma16816(oacc[mi][ni], ah4, bh2[ni]);
                    mma16816(oacc[mi][ni], ah4, bl2[ni]);
                    mma16816(oacc[mi][ni], al4, bh2[ni]);
                }
            }
        }
        __syncthreads();
    }

    // ---- extra chunk: w @ embV_h (hf 0,1 only; 2x80 cols) ----
    {
        for (int i = tid; i < 640; i += 512) {
            int p = i >> 3, dg = i & 7;
            int r0 = 2 * p, r1 = 2 * p + 1;
            float v0[8] = {}, v1[8] = {};
            if (r0 < RR) {
                float4 x = *(const float4*)&embV[(size_t)r0 * DD + h * DH + dg * 8];
                float4 y = *(const float4*)&embV[(size_t)r0 * DD + h * DH + dg * 8 + 4];
                v0[0]=x.x; v0[1]=x.y; v0[2]=x.z; v0[3]=x.w; v0[4]=y.x; v0[5]=y.y; v0[6]=y.z; v0[7]=y.w;
            }
            if (r1 < RR) {
                float4 x = *(const float4*)&embV[(size_t)r1 * DD + h * DH + dg * 8];
                float4 y = *(const float4*)&embV[(size_t)r1 * DD + h * DH + dg * 8 + 4];
                v1[0]=x.x; v1[1]=x.y; v1[2]=x.z; v1[3]=x.w; v1[4]=y.x; v1[5]=y.y; v1[6]=y.z; v1[7]=y.w;
            }
            #pragma unroll
            for (int j = 0; j < 8; j++) {
                __nv_bfloat16 h0 = __float2bfloat16(v0[j]);
                __nv_bfloat16 h1 = __float2bfloat16(v1[j]);
                __nv_bfloat16 l0 = __float2bfloat16(v0[j] - __bfloat162float(h0));
                __nv_bfloat16 l1 = __float2bfloat16(v1[j] - __bfloat162float(h1));
                vH[(dg * 8 + j) * VP + p] =
                    (uint32_t)__bfloat16_as_ushort(h0) | ((uint32_t)__bfloat16_as_ushort(h1) << 16);
                vL[(dg * 8 + j) * VP + p] =
                    (uint32_t)__bfloat16_as_ushort(l0) | ((uint32_t)__bfloat16_as_ushort(l1) << 16);
            }
        }
        for (int i = tid; i < 2560; i += 512) {
            int q = i / 80, c2 = (i % 80) * 2;
            float2 v = *(float2*)&sW[q * WP + c2];
            uint32_t hpk, lpk;
            asm("cvt.rn.bf16x2.f32 %0, %1, %2;" : "=r"(hpk) : "f"(v.y), "f"(v.x));
            float h0 = __uint_as_float(hpk << 16);
            float h1 = __uint_as_float(hpk & 0xffff0000u);
            asm("cvt.rn.bf16x2.f32 %0, %1, %2;" : "=r"(lpk) : "f"(v.y - h1), "f"(v.x - h0));
            *(uint32_t*)&pH[q * PP + c2] = hpk;
            *(uint32_t*)&pL[q * PP + c2] = lpk;
        }
        __syncthreads();

        if (hf < 2) {
            #pragma unroll
            for (int ks = 0; ks < 5; ks++) {
                int kb = hf * 80 + ks * 16 + 2 * t;
                int widx = hf * 40 + ks * 8 + t;
                uint32_t bh2[2][2], bl2[2][2];
                #pragma unroll
                for (int ni = 0; ni < 2; ni++) {
                    int vrow = (wn * 16 + ni * 8 + g) * VP;
                    bh2[ni][0] = vH[vrow + widx];  bh2[ni][1] = vH[vrow + widx + 4];
                    bl2[ni][0] = vL[vrow + widx];  bl2[ni][1] = vL[vrow + widx + 4];
                }
                #pragma unroll
                for (int mi = 0; mi < 2; mi++) {
                    int r0 = (mi * 16 + g) * PP, r1 = r0 + 8 * PP;
                    uint32_t ah4[4] = {*(uint32_t*)&pH[r0 + kb], *(uint32_t*)&pH[r1 + kb],
                                       *(uint32_t*)&pH[r0 + kb + 8], *(uint32_t*)&pH[r1 + kb + 8]};
                    uint32_t al4[4] = {*(uint32_t*)&pL[r0 + kb], *(uint32_t*)&pL[r1 + kb],
                                       *(uint32_t*)&pL[r0 + kb + 8], *(uint32_t*)&pL[r1 + kb + 8]};
                    #pragma unroll
                    for (int ni = 0; ni < 2; ni++) {
                        mma16816(oacc[mi][ni], ah4, bh2[ni]);
                        mma16816(oacc[mi][ni], ah4, bl2[ni]);
                        mma16816(oacc[mi][ni], al4, bh2[ni]);
                    }
                }
            }
        }
        __syncthreads();
    }

    // ---- reduce 4 hf partials (two 2-way rounds, 16KB staging) ----
    // element map: oacc[mi][ni][e]: q = mi*16+g (+8 for e>=2); dc = wn*16+ni*8+2t (+1 for odd e)
    {
        // round A: hf 1 -> slot 0, hf 3 -> slot 1
        if (hf & 1) {
            int slot = hf >> 1;
            #pragma unroll
            for (int mi = 0; mi < 2; mi++)
                #pragma unroll
                for (int ni = 0; ni < 2; ni++) {
                    int q = mi * 16 + g, dc = wn * 16 + ni * 8 + 2 * t;
                    stg[slot * 2048 + q * 64 + dc]           = oacc[mi][ni][0];
                    stg[slot * 2048 + q * 64 + dc + 1]       = oacc[mi][ni][1];
                    stg[slot * 2048 + (q + 8) * 64 + dc]     = oacc[mi][ni][2];
                    stg[slot * 2048 + (q + 8) * 64 + dc + 1] = oacc[mi][ni][3];
                }
        }
        __syncthreads();
        if (!(hf & 1)) {
            int slot = hf >> 1;
            #pragma unroll
            for (int mi = 0; mi < 2; mi++)
                #pragma unroll
                for (int ni = 0; ni < 2; ni++) {
                    int q = mi * 16 + g, dc = wn * 16 + ni * 8 + 2 * t;
                    oacc[mi][ni][0] += stg[slot * 2048 + q * 64 + dc];
                    oacc[mi][ni][1] += stg[slot * 2048 + q * 64 + dc + 1];
                    oacc[mi][ni][2] += stg[slot * 2048 + (q + 8) * 64 + dc];
                    oacc[mi][ni][3] += stg[slot * 2048 + (q + 8) * 64 + dc + 1];
                }
        }
        __syncthreads();
        // round B: hf 2 -> slot 0
        if (hf == 2) {
            #pragma unroll
            for (int mi = 0; mi < 2; mi++)
                #pragma unroll
                for (int ni = 0; ni < 2; ni++) {
                    int q = mi * 16 + g, dc = wn * 16 + ni * 8 + 2 * t;
                    stg[q * 64 + dc]           = oacc[mi][ni][0];
                    stg[q * 64 + dc + 1]       = oacc[mi][ni][1];
                    stg[(q + 8) * 64 + dc]     = oacc[mi][ni][2];
                    stg[(q + 8) * 64 + dc + 1] = oacc[mi][ni][3];
                }
        }
        __syncthreads();
        if (hf == 0) {
            #pragma unroll
            for (int mi = 0; mi < 2; mi++)
                #pragma unroll
                for (int ni = 0; ni < 2; ni++) {
                    int q = mi * 16 + g, dc = wn * 16 + ni * 8 + 2 * t;
                    float v00 = (oacc[mi][ni][0] + stg[q * 64 + dc])           * sInv[q];
                    float v01 = (oacc[mi][ni][1] + stg[q * 64 + dc + 1])       * sInv[q];
                    float v10 = (oacc[mi][ni][2] + stg[(q + 8) * 64 + dc])     * sInv[q + 8];
                    float v11 = (oacc[mi][ni][3] + stg[(q + 8) * 64 + dc + 1]) * sInv[q + 8];
                    uint32_t hp0, lp0, hp1, lp1;
                    asm("cvt.rn.bf16x2.f32 %0, %1, %2;" : "=r"(hp0) : "f"(v01), "f"(v00));
                    asm("cvt.rn.bf16x2.f32 %0, %1, %2;" : "=r"(hp1) : "f"(v11), "f"(v10));
                    float h00 = __uint_as_float(hp0 << 16);
                    float h01 = __uint_as_float(hp0 & 0xffff0000u);
                    float h10 = __uint_as_float(hp1 << 16);
                    float h11 = __uint_as_float(hp1 & 0xffff0000u);
                    asm("cvt.rn.bf16x2.f32 %0, %1, %2;" : "=r"(lp0) : "f"(v01 - h01), "f"(v00 - h00));
                    asm("cvt.rn.bf16x2.f32 %0, %1, %2;" : "=r"(lp1) : "f"(v11 - h11), "f"(v10 - h10));
                    size_t d0 = ((size_t)(b * SS) + q0 + q) * DD + h * DH + dc;
                    size_t d1 = ((size_t)(b * SS) + q0 + q + 8) * DD + h * DH + dc;
                    *(uint32_t*)&ctxH[d0] = hp0;
                    *(uint32_t*)&ctxL[d0] = lp0;
                    *(uint32_t*)&ctxH[d1] = hp1;
                    *(uint32_t*)&ctxL[d1] = lp1;
                }
        }
    }
}

// ---------------- launch ----------------
extern "C" void kernel_launch(void* const* d_in, const int* in_sizes, int n_in,
                              void* d_out, int out_size)
{
    const float* query = (const float*)d_in[0];
    const float* key   = (const float*)d_in[1];
    const float* value = (const float*)d_in[2];
    const float* WQ_w  = (const float*)d_in[3];
    const float* WQ_b  = (const float*)d_in[4];
    const float* WK_w  = (const float*)d_in[5];
    const float* WK_b  = (const float*)d_in[6];
    const float* WV_w  = (const float*)d_in[7];
    const float* WV_b  = (const float*)d_in[8];
    const float* WO_w  = (const float*)d_in[9];
    const float* WO_b  = (const float*)d_in[10];
    const float* embK  = (const float*)d_in[11];
    const float* embV  = (const float*)d_in[12];

    float* out = (float*)d_out;                       // [B,S,D]
    float* attn = out + (size_t)BB * SS * DD;         // [B,H,S,S]

    static float *Qp = nullptr, *Kp, *Vp;
    static __nv_bfloat16 *qh, *ql, *kh, *kl, *vh, *vl, *ch, *cl;
    static __nv_bfloat16 *wqh, *wql, *wkh, *wkl, *wvh, *wvl, *woh, *wol;
    static uint32_t *vtH, *vtL;
    if (!Qp) {
        cudaGetSymbolAddress((void**)&Qp, g_Qp);
        cudaGetSymbolAddress((void**)&Kp, g_Kp);
        cudaGetSymbolAddress((void**)&Vp, g_Vp);
        cudaGetSymbolAddress((void**)&qh, g_qh);   cudaGetSymbolAddress((void**)&ql, g_ql);
        cudaGetSymbolAddress((void**)&kh, g_kh);   cudaGetSymbolAddress((void**)&kl, g_kl);
        cudaGetSymbolAddress((void**)&vh, g_vh);   cudaGetSymbolAddress((void**)&vl, g_vl);
        cudaGetSymbolAddress((void**)&ch, g_ch);   cudaGetSymbolAddress((void**)&cl, g_cl);
        cudaGetSymbolAddress((void**)&wqh, g_wqh); cudaGetSymbolAddress((void**)&wql, g_wql);
        cudaGetSymbolAddress((void**)&wkh, g_wkh); cudaGetSymbolAddress((void**)&wkl, g_wkl);
        cudaGetSymbolAddress((void**)&wvh, g_wvh); cudaGetSymbolAddress((void**)&wvl, g_wvl);
        cudaGetSymbolAddress((void**)&woh, g_woh); cudaGetSymbolAddress((void**)&wol, g_wol);
        cudaGetSymbolAddress((void**)&vtH, g_vtH); cudaGetSymbolAddress((void**)&vtL, g_vtL);
        cudaFuncSetAttribute(attn_mma,
                             cudaFuncAttributeMaxDynamicSharedMemorySize, ASM_BYTES);
        cudaFuncSetAttribute(gemm_qkv,
                             cudaFuncAttributeMaxDynamicSharedMemorySize, GSMB);
        cudaFuncSetAttribute(gemm_o,
                             cudaFuncAttributeMaxDynamicSharedMemorySize, GSMB);
    }

    __nv_bfloat16* QsH = (__nv_bfloat16*)Qp;  __nv_bfloat16* QsL = QsH + (size_t)MTOT * DD;
    __nv_bfloat16* KsH = (__nv_bfloat16*)Kp;  __nv_bfloat16* KsL = KsH + (size_t)MTOT * DD;
    __nv_bfloat16* VsH = (__nv_bfloat16*)Vp;  __nv_bfloat16* VsL = VsH + (size_t)MTOT * DD;

    const int NIN = MTOT * DD;
    const int NW  = DD * DD;

    split_all_kernel<<<dim3(NIN / 4 / 256, 7), 256>>>(
        query, qh, ql, key, kh, kl, value, vh, vl,
        WQ_w, wqh, wql, WK_w, wkh, wkl, WV_w, wvh, wvl, WO_w, woh, wol,
        NIN, NW);
    gemm_qkv<<<dim3(DD / 128, MTOT / 64, 3), 256, GSMB>>>(
        qh, ql, wqh, wql, WQ_b, QsH, QsL,
        kh, kl, wkh, wkl, WK_b, KsH, KsL,
        vh, vl, wvh, wvl, WV_b, VsH, VsL);
    vtrans_kernel<<<BB * HH * 8, 256>>>(VsH, VsL, vtH, vtL);
    attn_mma<<<BB * HH * (SS / 32), 512, ASM_BYTES>>>(
        QsH, QsL, KsH, KsL, vtH, vtL, embK, embV, attn, ch, cl);
    gemm_o<<<dim3(DD / 128, MTOT / 64), 256, GSMB>>>(ch, cl, woh, wol, WO_b, out);
}